// round 3
// baseline (speedup 1.0000x reference)
#include <cuda_runtime.h>
#include <math.h>

#define MMIX 4
#define PIX 8

// ---------------- scratch (static __device__, no allocation) ----------------
__device__ float d_kpad0[3076096];
__device__ float d_vpad0[12304384];
__device__ float d_q0[3072000];
__device__ float d_att0[3072000];
__device__ float d_bn0[768000];

__device__ float d_kpad1[2310144];
__device__ float d_vpad1[9240576];
__device__ float d_q1[1536000];
__device__ float d_att1[1536000];
__device__ float d_bn1[384000];

__device__ float d_kpad2[48256];
__device__ float d_vpad2[193024];
__device__ float d_q2[24000];
__device__ float d_att2[24000];
__device__ float d_bn2[24000];

__device__ float d_emb[120]; // 3 stages x (M*K <= 40)

// ---------------- mixture embedding: emb[m,k] = softmax_m(la[m,i]+lb[m,j]) ----
__global__ void emb_kernel(const float* __restrict__ ea, const float* __restrict__ eb,
                           const float* __restrict__ em, float* __restrict__ emb_out,
                           int Co, int kh, int kw_)
{
    int K = kh * kw_;
    int t = threadIdx.x;
    if (t >= K) return;
    int i = t / kw_, j = t % kw_;
    float logits[MMIX];
    #pragma unroll
    for (int m = 0; m < MMIX; m++) {
        float la = 0.f, lb = 0.f;
        for (int c = 0; c < Co; c++) {
            float e = em[m * Co + c];
            la += e * ea[c * kh + i];
            lb += e * eb[c * kw_ + j];
        }
        logits[m] = la + lb;
    }
    float mx = logits[0];
    #pragma unroll
    for (int m = 1; m < MMIX; m++) mx = fmaxf(mx, logits[m]);
    float sum = 0.f;
    #pragma unroll
    for (int m = 0; m < MMIX; m++) { logits[m] = expf(logits[m] - mx); sum += logits[m]; }
    float inv = 1.f / sum;
    #pragma unroll
    for (int m = 0; m < MMIX; m++) emb_out[m * K + t] = logits[m] * inv;
}

// ---------------- projection: k (padded grid), v[0..3] (padded grid), q ------
// x is channel-last [B,H,W,Cin]. Outputs channel-last. Implicit zero padding.
__global__ void proj_kernel(const float* __restrict__ x,
    const float* __restrict__ qw, const float* __restrict__ kw_,
    const float* __restrict__ vw,
    float* __restrict__ kpad, float* __restrict__ vpad, float* __restrict__ qout,
    int B, int Cin, int H, int W, int Co,
    int Hp, int Wp, int Hout, int Wout, int pt, int pl)
{
    int co = threadIdx.x;
    int g0 = blockIdx.x * PIX;
    int totalPix = B * Hp * Wp;

    int xbase[PIX]; int hh[PIX], ww[PIX], bb[PIX];
    bool valid[PIX], inq[PIX];
    #pragma unroll
    for (int p = 0; p < PIX; p++) {
        int pix = g0 + p;
        valid[p] = false; inq[p] = false;
        xbase[p] = 0; hh[p] = 0; ww[p] = 0; bb[p] = 0;
        if (pix < totalPix) {
            int wp = pix % Wp; int t = pix / Wp;
            int hp = t % Hp;  int b = t / Hp;
            int h = hp - pt, w = wp - pl;
            if (h >= 0 && h < H && w >= 0 && w < W) {
                valid[p] = true;
                xbase[p] = ((b * H + h) * W + w) * Cin;
                inq[p] = (h < Hout) && (w < Wout);
                hh[p] = h; ww[p] = w; bb[p] = b;
            }
        }
    }

    if (co >= Co) return;

    float ak[PIX], aq[PIX], av0[PIX], av1[PIX], av2[PIX], av3[PIX];
    #pragma unroll
    for (int p = 0; p < PIX; p++) { ak[p]=0.f; aq[p]=0.f; av0[p]=0.f; av1[p]=0.f; av2[p]=0.f; av3[p]=0.f; }

    int CinCo = Cin * Co;
    for (int ci = 0; ci < Cin; ci++) {
        float wq  = qw [ci * Co + co];
        float wk  = kw_[ci * Co + co];
        float wv0 = vw [ci * Co + co];
        float wv1 = vw [CinCo     + ci * Co + co];
        float wv2 = vw [2 * CinCo + ci * Co + co];
        float wv3 = vw [3 * CinCo + ci * Co + co];
        #pragma unroll
        for (int p = 0; p < PIX; p++) {
            if (valid[p]) {
                float xv = x[xbase[p] + ci];
                aq[p]  = fmaf(xv, wq,  aq[p]);
                ak[p]  = fmaf(xv, wk,  ak[p]);
                av0[p] = fmaf(xv, wv0, av0[p]);
                av1[p] = fmaf(xv, wv1, av1[p]);
                av2[p] = fmaf(xv, wv2, av2[p]);
                av3[p] = fmaf(xv, wv3, av3[p]);
            }
        }
    }

    long vstride = (long)totalPix * Co;
    #pragma unroll
    for (int p = 0; p < PIX; p++) {
        int pix = g0 + p;
        if (pix < totalPix) {
            long off = (long)pix * Co + co;
            kpad[off] = ak[p];
            vpad[off] = av0[p];
            vpad[vstride + off] = av1[p];
            vpad[2 * vstride + off] = av2[p];
            vpad[3 * vstride + off] = av3[p];
            if (inq[p])
                qout[(((long)bb[p] * Hout + hh[p]) * Wout + ww[p]) * Co + co] = aq[p];
        }
    }
}

// ---------------- attention: one block per output pixel ----------------------
template<int KH, int KW>
__global__ void att_kernel(const float* __restrict__ q,
    const float* __restrict__ kpad, const float* __restrict__ vpad,
    const float* __restrict__ emb, float* __restrict__ out,
    int B, int Co, int Hp, int Wp, int Hout, int Wout, long vstride)
{
    constexpr int K = KH * KW;
    int pix = blockIdx.x;
    int wo = pix % Wout; int t = pix / Wout;
    int ho = t % Hout;  int b = t / Hout;
    int tid = threadIdx.x, T = blockDim.x;
    int lane = tid & 31, wid = tid >> 5, nwarp = T >> 5;

    long kvbase[K];
    #pragma unroll
    for (int k = 0; k < K; k++) {
        int i = k / KW, j = k % KW;
        kvbase[k] = ((long)(b * Hp + ho + i) * Wp + (wo + j)) * Co;
    }

    float partial[K];
    #pragma unroll
    for (int k = 0; k < K; k++) partial[k] = 0.f;

    long qbase = (long)pix * Co;
    for (int co = tid; co < Co; co += T) {
        float qv = q[qbase + co];
        #pragma unroll
        for (int k = 0; k < K; k++)
            partial[k] = fmaf(qv, kpad[kvbase[k] + co], partial[k]);
    }

    __shared__ float s_part[4][K];
    __shared__ float s_attn[K];
    __shared__ float s_emb[MMIX * K];
    // FIX (R2): strided load — blockDim may be smaller than MMIX*K (stage 2: 32 < 40),
    // the old single-shot guarded load left s_emb[32..39] uninitialized.
    for (int e = tid; e < MMIX * K; e += T) s_emb[e] = emb[e];

    #pragma unroll
    for (int k = 0; k < K; k++) {
        float v = partial[k];
        v += __shfl_down_sync(0xffffffffu, v, 16);
        v += __shfl_down_sync(0xffffffffu, v, 8);
        v += __shfl_down_sync(0xffffffffu, v, 4);
        v += __shfl_down_sync(0xffffffffu, v, 2);
        v += __shfl_down_sync(0xffffffffu, v, 1);
        if (lane == 0) s_part[wid][k] = v;
    }
    __syncthreads();
    if (tid == 0) {
        float sc[K];
        float mx = -1e30f;
        #pragma unroll
        for (int k = 0; k < K; k++) {
            float s = 0.f;
            for (int w = 0; w < nwarp; w++) s += s_part[w][k];
            sc[k] = s; mx = fmaxf(mx, s);
        }
        float sum = 0.f;
        #pragma unroll
        for (int k = 0; k < K; k++) { sc[k] = expf(sc[k] - mx); sum += sc[k]; }
        float inv = 1.f / sum;
        #pragma unroll
        for (int k = 0; k < K; k++) s_attn[k] = sc[k] * inv;
    }
    __syncthreads();

    float aw[K];
    #pragma unroll
    for (int k = 0; k < K; k++) aw[k] = s_attn[k];

    for (int co = tid; co < Co; co += T) {
        float acc = 0.f;
        #pragma unroll
        for (int k = 0; k < K; k++) {
            long off = kvbase[k] + co;
            float vg = s_emb[k]         * vpad[off]
                     + s_emb[K + k]     * vpad[vstride + off]
                     + s_emb[2 * K + k] * vpad[2 * vstride + off]
                     + s_emb[3 * K + k] * vpad[3 * vstride + off];
            acc = fmaf(aw[k], vg, acc);
        }
        out[qbase + co] = acc;
    }
}

// ---------------- fused BN(train) + ReLU + stride subsample ------------------
__global__ void bn_kernel(const float* __restrict__ in,
    const float* __restrict__ gamma, const float* __restrict__ beta,
    float* __restrict__ out, int B, int H, int W, int Co, int sh, int sw)
{
    int c = blockIdx.x;
    int tid = threadIdx.x, T = blockDim.x;
    long N = (long)B * H * W;
    float s = 0.f, sq = 0.f;
    for (long i = tid; i < N; i += T) {
        float v = in[i * Co + c];
        s += v; sq += v * v;
    }
    __shared__ float sh_s[256], sh_q[256];
    sh_s[tid] = s; sh_q[tid] = sq;
    __syncthreads();
    for (int off = T / 2; off > 0; off >>= 1) {
        if (tid < off) { sh_s[tid] += sh_s[tid + off]; sh_q[tid] += sh_q[tid + off]; }
        __syncthreads();
    }
    __shared__ float s_scale, s_shift;
    if (tid == 0) {
        float mean = sh_s[0] / (float)N;
        float var  = sh_q[0] / (float)N - mean * mean;
        float sc = gamma[c] * rsqrtf(var + 1e-5f);
        s_scale = sc;
        s_shift = beta[c] - mean * sc;
    }
    __syncthreads();
    float sc = s_scale, sf = s_shift;
    int Hs = (H + sh - 1) / sh;
    int Ws = (W + sw - 1) / sw;
    long M_ = (long)B * Hs * Ws;
    for (long i = tid; i < M_; i += T) {
        int ws = (int)(i % Ws); long t = i / Ws; int hs = (int)(t % Hs); int bb = (int)(t / Hs);
        float v = in[(((long)bb * H + hs * sh) * W + ws * sw) * Co + c];
        float y = fmaf(v, sc, sf);
        out[i * Co + c] = y > 0.f ? y : 0.f;
    }
}

// ---------------- final AvgPool2d((1,56)) ------------------------------------
__global__ void avgpool_kernel(const float* __restrict__ in, float* __restrict__ out,
                               int B, int C, int W, int nW)
{
    int idx = blockIdx.x * blockDim.x + threadIdx.x;
    int total = B * C * nW;
    if (idx >= total) return;
    int nw = idx % nW; int t = idx / nW; int c = t % C; int b = t / C;
    float s = 0.f;
    for (int j = 0; j < 56; j++)
        s += in[((long)b * W + nw * 56 + j) * C + c];
    out[(b * C + c) * nW + nw] = s * (1.f / 56.f);
}

// ---------------- launch -----------------------------------------------------
extern "C" void kernel_launch(void* const* d_in, const int* in_sizes, int n_in,
                              void* d_out, int out_size)
{
    const float* x = (const float*)d_in[0];
    const float* p[24];
    for (int i = 0; i < 24; i++) p[i] = (const float*)d_in[1 + i];

    float *kpad0, *vpad0, *q0, *att0, *bn0;
    float *kpad1, *vpad1, *q1, *att1, *bn1;
    float *kpad2, *vpad2, *q2, *att2, *bn2;
    float *emb;
    cudaGetSymbolAddress((void**)&kpad0, d_kpad0);
    cudaGetSymbolAddress((void**)&vpad0, d_vpad0);
    cudaGetSymbolAddress((void**)&q0,    d_q0);
    cudaGetSymbolAddress((void**)&att0,  d_att0);
    cudaGetSymbolAddress((void**)&bn0,   d_bn0);
    cudaGetSymbolAddress((void**)&kpad1, d_kpad1);
    cudaGetSymbolAddress((void**)&vpad1, d_vpad1);
    cudaGetSymbolAddress((void**)&q1,    d_q1);
    cudaGetSymbolAddress((void**)&att1,  d_att1);
    cudaGetSymbolAddress((void**)&bn1,   d_bn1);
    cudaGetSymbolAddress((void**)&kpad2, d_kpad2);
    cudaGetSymbolAddress((void**)&vpad2, d_vpad2);
    cudaGetSymbolAddress((void**)&q2,    d_q2);
    cudaGetSymbolAddress((void**)&att2,  d_att2);
    cudaGetSymbolAddress((void**)&bn2,   d_bn2);
    cudaGetSymbolAddress((void**)&emb,   d_emb);

    // ---- stage 0: Cin=1 -> Co=64, kh=1 kw=5, pad (l,r,t,b)=(2,2,0,0)
    // H=8 W=3000, Hp=8 Wp=3004, Hout=8 Wout=3000
    emb_kernel<<<1, 32>>>(p[3], p[4], p[5], emb + 0, 64, 1, 5);
    {
        int tp = 2 * 8 * 3004;
        proj_kernel<<<(tp + PIX - 1) / PIX, 64>>>(x, p[0], p[1], p[2],
            kpad0, vpad0, q0, 2, 1, 8, 3000, 64, 8, 3004, 8, 3000, 0, 2);
        att_kernel<1, 5><<<2 * 8 * 3000, 64>>>(q0, kpad0, vpad0, emb + 0, att0,
            2, 64, 8, 3004, 8, 3000, (long)tp * 64);
        bn_kernel<<<64, 256>>>(att0, p[6], p[7], bn0, 2, 8, 3000, 64, 2, 2);
    }

    // ---- stage 1: Cin=64 -> Co=128, kh=2 kw=5, pad (2,2,1,1)
    // H=4 W=1500, Hp=6 Wp=1504, Hout=4 Wout=1500
    emb_kernel<<<1, 32>>>(p[11], p[12], p[13], emb + 40, 128, 2, 5);
    {
        int tp = 2 * 6 * 1504;
        proj_kernel<<<(tp + PIX - 1) / PIX, 128>>>(bn0, p[8], p[9], p[10],
            kpad1, vpad1, q1, 2, 64, 4, 1500, 128, 6, 1504, 4, 1500, 1, 2);
        att_kernel<2, 5><<<2 * 4 * 1500, 128>>>(q1, kpad1, vpad1, emb + 40, att1,
            2, 128, 6, 1504, 4, 1500, (long)tp * 128);
        bn_kernel<<<128, 256>>>(att1, p[14], p[15], bn1, 2, 4, 1500, 128, 2, 2);
    }

    // ---- stage 2: Cin=128 -> Co=16, kh=2 kw=5, pad (2,2,0,0)
    // H=2 W=750, Hp=2 Wp=754, Hout=1 Wout=750
    emb_kernel<<<1, 32>>>(p[19], p[20], p[21], emb + 80, 16, 2, 5);
    {
        int tp = 2 * 2 * 754;
        proj_kernel<<<(tp + PIX - 1) / PIX, 32>>>(bn1, p[16], p[17], p[18],
            kpad2, vpad2, q2, 2, 128, 2, 750, 16, 2, 754, 1, 750, 0, 2);
        att_kernel<2, 5><<<2 * 1 * 750, 32>>>(q2, kpad2, vpad2, emb + 80, att2,
            2, 16, 2, 754, 1, 750, (long)tp * 16);
        bn_kernel<<<16, 256>>>(att2, p[22], p[23], bn2, 2, 1, 750, 16, 1, 1);
    }

    // ---- AvgPool2d((1,56)): [2,16,1,750] -> [2,16,1,13]
    avgpool_kernel<<<(2 * 16 * 13 + 127) / 128, 128>>>(bn2, (float*)d_out, 2, 16, 750, 13);
}

// round 4
// speedup vs baseline: 1.3761x; 1.3761x over previous
#include <cuda_runtime.h>
#include <math.h>

#define MMIX 4
#define PIX 8
#define BN_BLOCKS 96

// ---------------- scratch (static __device__, no allocation) ----------------
__device__ float d_kpad0[3076096];
__device__ float d_vpad0[12304384];
__device__ float d_q0[3072000];
__device__ float d_att0[3072000];
__device__ float d_bn0[768000];

__device__ float d_kpad1[2310144];
__device__ float d_vpad1[9240576];
__device__ float d_q1[1536000];
__device__ float d_att1[1536000];
__device__ float d_bn1[384000];

__device__ float d_kpad2[48256];
__device__ float d_vpad2[193024];
__device__ float d_q2[24000];
__device__ float d_att2[24000];
__device__ float d_bn2[24000];

__device__ float d_emb[120];                 // 3 stages x (M*K <= 40)
__device__ float d_bnpart[BN_BLOCKS * 256];  // per-block partial sums (2*Co <= 256)
__device__ float d_bnss[256];                // per-channel scale/shift

// ---------------- mixture embedding: emb[m,k] = softmax_m(la[m,i]+lb[m,j]) ----
__global__ void emb_kernel(const float* __restrict__ ea, const float* __restrict__ eb,
                           const float* __restrict__ em, float* __restrict__ emb_out,
                           int Co, int kh, int kw_)
{
    int K = kh * kw_;
    int t = threadIdx.x;
    if (t >= K) return;
    int i = t / kw_, j = t % kw_;
    float logits[MMIX];
    #pragma unroll
    for (int m = 0; m < MMIX; m++) {
        float la = 0.f, lb = 0.f;
        for (int c = 0; c < Co; c++) {
            float e = em[m * Co + c];
            la += e * ea[c * kh + i];
            lb += e * eb[c * kw_ + j];
        }
        logits[m] = la + lb;
    }
    float mx = logits[0];
    #pragma unroll
    for (int m = 1; m < MMIX; m++) mx = fmaxf(mx, logits[m]);
    float sum = 0.f;
    #pragma unroll
    for (int m = 0; m < MMIX; m++) { logits[m] = expf(logits[m] - mx); sum += logits[m]; }
    float inv = 1.f / sum;
    #pragma unroll
    for (int m = 0; m < MMIX; m++) emb_out[m * K + t] = logits[m] * inv;
}

// ---------------- projection: k (padded grid), v[0..3] (padded grid), q ------
// x is channel-last [B,H,W,Cin]. Outputs channel-last. Implicit zero padding.
__global__ void proj_kernel(const float* __restrict__ x,
    const float* __restrict__ qw, const float* __restrict__ kw_,
    const float* __restrict__ vw,
    float* __restrict__ kpad, float* __restrict__ vpad, float* __restrict__ qout,
    int B, int Cin, int H, int W, int Co,
    int Hp, int Wp, int Hout, int Wout, int pt, int pl)
{
    int co = threadIdx.x;
    int g0 = blockIdx.x * PIX;
    int totalPix = B * Hp * Wp;

    int xbase[PIX]; int hh[PIX], ww[PIX], bb[PIX];
    bool valid[PIX], inq[PIX];
    #pragma unroll
    for (int p = 0; p < PIX; p++) {
        int pix = g0 + p;
        valid[p] = false; inq[p] = false;
        xbase[p] = 0; hh[p] = 0; ww[p] = 0; bb[p] = 0;
        if (pix < totalPix) {
            int wp = pix % Wp; int t = pix / Wp;
            int hp = t % Hp;  int b = t / Hp;
            int h = hp - pt, w = wp - pl;
            if (h >= 0 && h < H && w >= 0 && w < W) {
                valid[p] = true;
                xbase[p] = ((b * H + h) * W + w) * Cin;
                inq[p] = (h < Hout) && (w < Wout);
                hh[p] = h; ww[p] = w; bb[p] = b;
            }
        }
    }

    if (co >= Co) return;

    float ak[PIX], aq[PIX], av0[PIX], av1[PIX], av2[PIX], av3[PIX];
    #pragma unroll
    for (int p = 0; p < PIX; p++) { ak[p]=0.f; aq[p]=0.f; av0[p]=0.f; av1[p]=0.f; av2[p]=0.f; av3[p]=0.f; }

    int CinCo = Cin * Co;
    for (int ci = 0; ci < Cin; ci++) {
        float wq  = qw [ci * Co + co];
        float wk  = kw_[ci * Co + co];
        float wv0 = vw [ci * Co + co];
        float wv1 = vw [CinCo     + ci * Co + co];
        float wv2 = vw [2 * CinCo + ci * Co + co];
        float wv3 = vw [3 * CinCo + ci * Co + co];
        #pragma unroll
        for (int p = 0; p < PIX; p++) {
            if (valid[p]) {
                float xv = x[xbase[p] + ci];
                aq[p]  = fmaf(xv, wq,  aq[p]);
                ak[p]  = fmaf(xv, wk,  ak[p]);
                av0[p] = fmaf(xv, wv0, av0[p]);
                av1[p] = fmaf(xv, wv1, av1[p]);
                av2[p] = fmaf(xv, wv2, av2[p]);
                av3[p] = fmaf(xv, wv3, av3[p]);
            }
        }
    }

    int vstride = totalPix * Co;
    #pragma unroll
    for (int p = 0; p < PIX; p++) {
        int pix = g0 + p;
        if (pix < totalPix) {
            int off = pix * Co + co;
            kpad[off] = ak[p];
            vpad[off] = av0[p];
            vpad[vstride + off] = av1[p];
            vpad[2 * vstride + off] = av2[p];
            vpad[3 * vstride + off] = av3[p];
            if (inq[p])
                qout[((bb[p] * Hout + hh[p]) * Wout + ww[p]) * Co + co] = aq[p];
        }
    }
}

// ---------------- attention: one WARP per output pixel -----------------------
// block = 256 threads = 8 warps = 8 consecutive pixels (window overlap -> L1 reuse)
template<int KH, int KW, int CO>
__global__ void att_kernel(const float* __restrict__ q,
    const float* __restrict__ kpad, const float* __restrict__ vpad,
    const float* __restrict__ emb, float* __restrict__ out,
    int Hp, int Wp, int Hout, int Wout, int total, int vstride)
{
    constexpr int K = KH * KW;
    __shared__ float s_emb[MMIX * K];
    for (int e = threadIdx.x; e < MMIX * K; e += blockDim.x) s_emb[e] = emb[e];
    __syncthreads();

    int gw = (blockIdx.x * blockDim.x + threadIdx.x) >> 5;   // global warp = pixel
    int lane = threadIdx.x & 31;
    if (gw >= total) return;

    int wo = gw % Wout; int t = gw / Wout;
    int ho = t % Hout;  int b = t / Hout;

    int kvbase[K];
    #pragma unroll
    for (int k = 0; k < K; k++) {
        int i = k / KW, j = k % KW;
        kvbase[k] = ((b * Hp + ho + i) * Wp + (wo + j)) * CO;
    }

    // ---- scores: q . k per tap, lanes stride over channels
    float partial[K];
    #pragma unroll
    for (int k = 0; k < K; k++) partial[k] = 0.f;
    int qbase = gw * CO;
    #pragma unroll
    for (int co = lane; co < CO; co += 32) {
        float qv = q[qbase + co];
        #pragma unroll
        for (int k = 0; k < K; k++)
            partial[k] = fmaf(qv, kpad[kvbase[k] + co], partial[k]);
    }
    #pragma unroll
    for (int k = 0; k < K; k++) {
        #pragma unroll
        for (int off = 16; off > 0; off >>= 1)
            partial[k] += __shfl_xor_sync(0xffffffffu, partial[k], off);
    }

    // ---- softmax over taps (redundant per lane, all-lane values from butterfly)
    float mx = partial[0];
    #pragma unroll
    for (int k = 1; k < K; k++) mx = fmaxf(mx, partial[k]);
    float sum = 0.f;
    float aw[K];
    #pragma unroll
    for (int k = 0; k < K; k++) { aw[k] = expf(partial[k] - mx); sum += aw[k]; }
    float inv = 1.f / sum;

    // ---- fold attn weight into mixture weights: wkm[m][k] = aw[k]*inv*emb[m,k]
    float wkm[MMIX][K];
    #pragma unroll
    for (int m = 0; m < MMIX; m++)
        #pragma unroll
        for (int k = 0; k < K; k++)
            wkm[m][k] = aw[k] * inv * s_emb[m * K + k];

    // ---- output: pure FMA over coalesced v loads
    #pragma unroll
    for (int co = lane; co < CO; co += 32) {
        float acc = 0.f;
        #pragma unroll
        for (int k = 0; k < K; k++) {
            int off = kvbase[k] + co;
            acc = fmaf(wkm[0][k], vpad[off], acc);
            acc = fmaf(wkm[1][k], vpad[vstride + off], acc);
            acc = fmaf(wkm[2][k], vpad[2 * vstride + off], acc);
            acc = fmaf(wkm[3][k], vpad[3 * vstride + off], acc);
        }
        out[qbase + co] = acc;
    }
}

// ---------------- BN pass 1: per-block partial sums (deterministic) ----------
// blockDim=256, Co divides 256. Channel of a thread is fixed: tid % Co.
__global__ void bn_stats(const float* __restrict__ in, float* __restrict__ part,
                         long total, int Co)
{
    int tid = threadIdx.x;
    float s = 0.f, sq = 0.f;
    for (long i = (long)blockIdx.x * blockDim.x + tid; i < total;
         i += (long)gridDim.x * blockDim.x) {
        float v = in[i];
        s += v; sq += v * v;
    }
    __shared__ float sh[256], sh2[256];
    sh[tid] = s; sh2[tid] = sq;
    __syncthreads();
    for (int off = 128; off >= Co; off >>= 1) {
        if (tid < off) { sh[tid] += sh[tid + off]; sh2[tid] += sh2[tid + off]; }
        __syncthreads();
    }
    if (tid < Co) {
        part[blockIdx.x * 2 * Co + tid]      = sh[tid];
        part[blockIdx.x * 2 * Co + Co + tid] = sh2[tid];
    }
}

// ---------------- BN pass 2: reduce partials -> scale/shift per channel ------
__global__ void bn_finalize(const float* __restrict__ part,
    const float* __restrict__ gamma, const float* __restrict__ beta,
    float* __restrict__ ss, int Co, float invN)
{
    int c = threadIdx.x;
    if (c >= Co) return;
    float s = 0.f, sq = 0.f;
    for (int g = 0; g < BN_BLOCKS; g++) {
        s  += part[g * 2 * Co + c];
        sq += part[g * 2 * Co + Co + c];
    }
    float mean = s * invN;
    float var  = sq * invN - mean * mean;
    float sc = gamma[c] * rsqrtf(var + 1e-5f);
    ss[c]      = sc;
    ss[Co + c] = beta[c] - mean * sc;
}

// ---------------- BN pass 3: elementwise apply + ReLU + stride subsample -----
__global__ void bn_apply(const float* __restrict__ in, const float* __restrict__ ss,
    float* __restrict__ out, int B, int H, int W, int Co, int sh_, int sw_,
    int Hs, int Ws, int totalOut)
{
    int idx = blockIdx.x * blockDim.x + threadIdx.x;
    if (idx >= totalOut) return;
    int c = idx % Co; int pix = idx / Co;
    int ws = pix % Ws; int t = pix / Ws;
    int hs = t % Hs;   int b = t / Hs;
    float v = in[((b * H + hs * sh_) * W + ws * sw_) * Co + c];
    float y = fmaf(v, ss[c], ss[Co + c]);
    out[idx] = y > 0.f ? y : 0.f;
}

// ---------------- final AvgPool2d((1,56)) ------------------------------------
__global__ void avgpool_kernel(const float* __restrict__ in, float* __restrict__ out,
                               int B, int C, int W, int nW)
{
    int idx = blockIdx.x * blockDim.x + threadIdx.x;
    int total = B * C * nW;
    if (idx >= total) return;
    int nw = idx % nW; int t = idx / nW; int c = t % C; int b = t / C;
    float s = 0.f;
    for (int j = 0; j < 56; j++)
        s += in[((long)b * W + nw * 56 + j) * C + c];
    out[(b * C + c) * nW + nw] = s * (1.f / 56.f);
}

// ---------------- launch -----------------------------------------------------
extern "C" void kernel_launch(void* const* d_in, const int* in_sizes, int n_in,
                              void* d_out, int out_size)
{
    const float* x = (const float*)d_in[0];
    const float* p[24];
    for (int i = 0; i < 24; i++) p[i] = (const float*)d_in[1 + i];

    float *kpad0, *vpad0, *q0, *att0, *bn0;
    float *kpad1, *vpad1, *q1, *att1, *bn1;
    float *kpad2, *vpad2, *q2, *att2, *bn2;
    float *emb, *bnpart, *bnss;
    cudaGetSymbolAddress((void**)&kpad0, d_kpad0);
    cudaGetSymbolAddress((void**)&vpad0, d_vpad0);
    cudaGetSymbolAddress((void**)&q0,    d_q0);
    cudaGetSymbolAddress((void**)&att0,  d_att0);
    cudaGetSymbolAddress((void**)&bn0,   d_bn0);
    cudaGetSymbolAddress((void**)&kpad1, d_kpad1);
    cudaGetSymbolAddress((void**)&vpad1, d_vpad1);
    cudaGetSymbolAddress((void**)&q1,    d_q1);
    cudaGetSymbolAddress((void**)&att1,  d_att1);
    cudaGetSymbolAddress((void**)&bn1,   d_bn1);
    cudaGetSymbolAddress((void**)&kpad2, d_kpad2);
    cudaGetSymbolAddress((void**)&vpad2, d_vpad2);
    cudaGetSymbolAddress((void**)&q2,    d_q2);
    cudaGetSymbolAddress((void**)&att2,  d_att2);
    cudaGetSymbolAddress((void**)&bn2,   d_bn2);
    cudaGetSymbolAddress((void**)&emb,   d_emb);
    cudaGetSymbolAddress((void**)&bnpart, d_bnpart);
    cudaGetSymbolAddress((void**)&bnss,   d_bnss);

    // ---- stage 0: Cin=1 -> Co=64, kh=1 kw=5, pad (l,r,t,b)=(2,2,0,0)
    // H=8 W=3000, Hp=8 Wp=3004, Hout=8 Wout=3000
    emb_kernel<<<1, 32>>>(p[3], p[4], p[5], emb + 0, 64, 1, 5);
    {
        int tp = 2 * 8 * 3004;
        proj_kernel<<<(tp + PIX - 1) / PIX, 64>>>(x, p[0], p[1], p[2],
            kpad0, vpad0, q0, 2, 1, 8, 3000, 64, 8, 3004, 8, 3000, 0, 2);
        int total = 2 * 8 * 3000;
        att_kernel<1, 5, 64><<<(total * 32 + 255) / 256, 256>>>(q0, kpad0, vpad0,
            emb + 0, att0, 8, 3004, 8, 3000, total, tp * 64);
        long telems = (long)total * 64;
        bn_stats<<<BN_BLOCKS, 256>>>(att0, bnpart, telems, 64);
        bn_finalize<<<1, 64>>>(bnpart, p[6], p[7], bnss, 64, 1.f / (float)total);
        int outN = 2 * 4 * 1500 * 64;
        bn_apply<<<(outN + 255) / 256, 256>>>(att0, bnss, bn0, 2, 8, 3000, 64, 2, 2, 4, 1500, outN);
    }

    // ---- stage 1: Cin=64 -> Co=128, kh=2 kw=5, pad (2,2,1,1)
    // H=4 W=1500, Hp=6 Wp=1504, Hout=4 Wout=1500
    emb_kernel<<<1, 64>>>(p[11], p[12], p[13], emb + 40, 128, 2, 5);
    {
        int tp = 2 * 6 * 1504;
        proj_kernel<<<(tp + PIX - 1) / PIX, 128>>>(bn0, p[8], p[9], p[10],
            kpad1, vpad1, q1, 2, 64, 4, 1500, 128, 6, 1504, 4, 1500, 1, 2);
        int total = 2 * 4 * 1500;
        att_kernel<2, 5, 128><<<(total * 32 + 255) / 256, 256>>>(q1, kpad1, vpad1,
            emb + 40, att1, 6, 1504, 4, 1500, total, tp * 128);
        long telems = (long)total * 128;
        bn_stats<<<BN_BLOCKS, 256>>>(att1, bnpart, telems, 128);
        bn_finalize<<<1, 128>>>(bnpart, p[14], p[15], bnss, 128, 1.f / (float)total);
        int outN = 2 * 2 * 750 * 128;
        bn_apply<<<(outN + 255) / 256, 256>>>(att1, bnss, bn1, 2, 4, 1500, 128, 2, 2, 2, 750, outN);
    }

    // ---- stage 2: Cin=128 -> Co=16, kh=2 kw=5, pad (2,2,0,0)
    // H=2 W=750, Hp=2 Wp=754, Hout=1 Wout=750
    emb_kernel<<<1, 32>>>(p[19], p[20], p[21], emb + 80, 16, 2, 5);
    {
        int tp = 2 * 2 * 754;
        proj_kernel<<<(tp + PIX - 1) / PIX, 32>>>(bn1, p[16], p[17], p[18],
            kpad2, vpad2, q2, 2, 128, 2, 750, 16, 2, 754, 1, 750, 0, 2);
        int total = 2 * 1 * 750;
        att_kernel<2, 5, 16><<<(total * 32 + 255) / 256, 256>>>(q2, kpad2, vpad2,
            emb + 80, att2, 2, 754, 1, 750, total, tp * 16);
        long telems = (long)total * 16;
        bn_stats<<<BN_BLOCKS, 256>>>(att2, bnpart, telems, 16);
        bn_finalize<<<1, 16>>>(bnpart, p[22], p[23], bnss, 16, 1.f / (float)total);
        int outN = 2 * 1 * 750 * 16;
        bn_apply<<<(outN + 255) / 256, 256>>>(att2, bnss, bn2, 2, 1, 750, 16, 1, 1, 1, 750, outN);
    }

    // ---- AvgPool2d((1,56)): [2,16,1,750] -> [2,16,1,13]
    avgpool_kernel<<<(2 * 16 * 13 + 127) / 128, 128>>>(bn2, (float*)d_out, 2, 16, 750, 13);
}

// round 5
// speedup vs baseline: 1.4916x; 1.0839x over previous
#include <cuda_runtime.h>
#include <math.h>

#define MMIX 4
#define PIX 8
#define BN_BLOCKS 192

// ---------------- scratch (static __device__, no allocation) ----------------
__device__ float d_att0[3072000];
__device__ float d_bn0[768000];

__device__ float d_kpad1[2310144];
__device__ float d_vpad1[9240576];
__device__ float d_q1[1536000];
__device__ float d_att1[1536000];
__device__ float d_bn1[384000];

__device__ float d_kpad2[48256];
__device__ float d_vpad2[193024];
__device__ float d_q2[24000];
__device__ float d_att2[24000];
__device__ float d_bn2[24000];

__device__ float d_emb[120];                 // 3 stages x (M*K <= 40)
__device__ float d_prep0[321];               // [0]=qw.kw ; [1..320]=E[5][64]
__device__ float d_bnpart[BN_BLOCKS * 256];  // per-block partials (2*Co <= 256)
__device__ float d_bnss[256];                // per-channel scale/shift

// ---------------- mixture embedding: emb[m,k] = softmax_m(la[m,i]+lb[m,j]) ----
__global__ void emb_kernel(const float* __restrict__ ea, const float* __restrict__ eb,
                           const float* __restrict__ em, float* __restrict__ emb_out,
                           int Co, int kh, int kw_)
{
    int K = kh * kw_;
    int t = threadIdx.x;
    if (t >= K) return;
    int i = t / kw_, j = t % kw_;
    float logits[MMIX];
    #pragma unroll
    for (int m = 0; m < MMIX; m++) {
        float la = 0.f, lb = 0.f;
        for (int c = 0; c < Co; c++) {
            float e = em[m * Co + c];
            la += e * ea[c * kh + i];
            lb += e * eb[c * kw_ + j];
        }
        logits[m] = la + lb;
    }
    float mx = logits[0];
    #pragma unroll
    for (int m = 1; m < MMIX; m++) mx = fmaxf(mx, logits[m]);
    float sum = 0.f;
    #pragma unroll
    for (int m = 0; m < MMIX; m++) { logits[m] = expf(logits[m] - mx); sum += logits[m]; }
    float inv = 1.f / sum;
    #pragma unroll
    for (int m = 0; m < MMIX; m++) emb_out[m * K + t] = logits[m] * inv;
}

// ---------------- stage-0 prep: c0 = qw.kw ; E[tap][co] = sum_m emb[m,tap]*vw[m,co]
__global__ void prep0_kernel(const float* __restrict__ qw, const float* __restrict__ kw_,
                             const float* __restrict__ vw, const float* __restrict__ emb,
                             float* __restrict__ prep)
{
    int t = threadIdx.x; // 64 threads
    __shared__ float sh[64];
    sh[t] = qw[t] * kw_[t];
    __syncthreads();
    if (t == 0) {
        float s = 0.f;
        for (int i = 0; i < 64; i++) s += sh[i];
        prep[0] = s;
    }
    #pragma unroll
    for (int j = 0; j < 5; j++) {
        float e = 0.f;
        #pragma unroll
        for (int m = 0; m < MMIX; m++) e += emb[m * 5 + j] * vw[m * 64 + t];
        prep[1 + j * 64 + t] = e;
    }
}

// ---------------- stage-0 fused attention (Cin=1 algebraic collapse) ---------
// score[tap] = c0 * x_pix * x_tap ; out[co] = sum_tap softmax(score)[tap]*x_tap*E[tap][co]
__global__ void att0_kernel(const float* __restrict__ x, const float* __restrict__ prep,
                            float* __restrict__ out)
{
    __shared__ float sE[5 * 64];
    for (int e = threadIdx.x; e < 320; e += blockDim.x) sE[e] = prep[1 + e];
    __syncthreads();

    int gw = (blockIdx.x * blockDim.x + threadIdx.x) >> 5;  // warp = pixel
    int lane = threadIdx.x & 31;
    if (gw >= 48000) return;
    int wo = gw % 3000;
    int row = gw / 3000;          // b*8+h, rows contiguous in x [2,8,3000]
    float c0 = prep[0];
    int rowbase = row * 3000;

    float xs[5];
    #pragma unroll
    for (int j = 0; j < 5; j++) {
        int w = wo - 2 + j;
        xs[j] = (w >= 0 && w < 3000) ? x[rowbase + w] : 0.f;
    }
    float cx = c0 * xs[2];        // x_pix = center of window (pad=2)

    float sc[5]; float mx = -1e30f;
    #pragma unroll
    for (int j = 0; j < 5; j++) { sc[j] = cx * xs[j]; mx = fmaxf(mx, sc[j]); }
    float sum = 0.f;
    #pragma unroll
    for (int j = 0; j < 5; j++) { sc[j] = expf(sc[j] - mx); sum += sc[j]; }
    float inv = 1.f / sum;
    float wj[5];
    #pragma unroll
    for (int j = 0; j < 5; j++) wj[j] = sc[j] * inv * xs[j];

    float acc0 = 0.f, acc1 = 0.f;
    #pragma unroll
    for (int j = 0; j < 5; j++) {
        acc0 = fmaf(wj[j], sE[j * 64 + lane], acc0);
        acc1 = fmaf(wj[j], sE[j * 64 + 32 + lane], acc1);
    }
    int ob = gw * 64;
    out[ob + lane] = acc0;
    out[ob + 32 + lane] = acc1;
}

// ---------------- projection: k (padded grid), v[0..3] (padded grid), q ------
__global__ void proj_kernel(const float* __restrict__ x,
    const float* __restrict__ qw, const float* __restrict__ kw_,
    const float* __restrict__ vw,
    float* __restrict__ kpad, float* __restrict__ vpad, float* __restrict__ qout,
    int B, int Cin, int H, int W, int Co,
    int Hp, int Wp, int Hout, int Wout, int pt, int pl)
{
    int co = threadIdx.x;
    int g0 = blockIdx.x * PIX;
    int totalPix = B * Hp * Wp;

    int xbase[PIX]; int hh[PIX], ww[PIX], bb[PIX];
    bool valid[PIX], inq[PIX];
    #pragma unroll
    for (int p = 0; p < PIX; p++) {
        int pix = g0 + p;
        valid[p] = false; inq[p] = false;
        xbase[p] = 0; hh[p] = 0; ww[p] = 0; bb[p] = 0;
        if (pix < totalPix) {
            int wp = pix % Wp; int t = pix / Wp;
            int hp = t % Hp;  int b = t / Hp;
            int h = hp - pt, w = wp - pl;
            if (h >= 0 && h < H && w >= 0 && w < W) {
                valid[p] = true;
                xbase[p] = ((b * H + h) * W + w) * Cin;
                inq[p] = (h < Hout) && (w < Wout);
                hh[p] = h; ww[p] = w; bb[p] = b;
            }
        }
    }

    if (co >= Co) return;

    float ak[PIX], aq[PIX], av0[PIX], av1[PIX], av2[PIX], av3[PIX];
    #pragma unroll
    for (int p = 0; p < PIX; p++) { ak[p]=0.f; aq[p]=0.f; av0[p]=0.f; av1[p]=0.f; av2[p]=0.f; av3[p]=0.f; }

    int CinCo = Cin * Co;
    for (int ci = 0; ci < Cin; ci++) {
        float wq  = qw [ci * Co + co];
        float wk  = kw_[ci * Co + co];
        float wv0 = vw [ci * Co + co];
        float wv1 = vw [CinCo     + ci * Co + co];
        float wv2 = vw [2 * CinCo + ci * Co + co];
        float wv3 = vw [3 * CinCo + ci * Co + co];
        #pragma unroll
        for (int p = 0; p < PIX; p++) {
            if (valid[p]) {
                float xv = x[xbase[p] + ci];
                aq[p]  = fmaf(xv, wq,  aq[p]);
                ak[p]  = fmaf(xv, wk,  ak[p]);
                av0[p] = fmaf(xv, wv0, av0[p]);
                av1[p] = fmaf(xv, wv1, av1[p]);
                av2[p] = fmaf(xv, wv2, av2[p]);
                av3[p] = fmaf(xv, wv3, av3[p]);
            }
        }
    }

    int vstride = totalPix * Co;
    #pragma unroll
    for (int p = 0; p < PIX; p++) {
        int pix = g0 + p;
        if (pix < totalPix) {
            int off = pix * Co + co;
            kpad[off] = ak[p];
            vpad[off] = av0[p];
            vpad[vstride + off] = av1[p];
            vpad[2 * vstride + off] = av2[p];
            vpad[3 * vstride + off] = av3[p];
            if (inq[p])
                qout[((bb[p] * Hout + hh[p]) * Wout + ww[p]) * Co + co] = aq[p];
        }
    }
}

// ---------------- attention: one WARP per output pixel -----------------------
template<int KH, int KW, int CO>
__global__ void att_kernel(const float* __restrict__ q,
    const float* __restrict__ kpad, const float* __restrict__ vpad,
    const float* __restrict__ emb, float* __restrict__ out,
    int Hp, int Wp, int Hout, int Wout, int total, int vstride)
{
    constexpr int K = KH * KW;
    __shared__ float s_emb[MMIX * K];
    for (int e = threadIdx.x; e < MMIX * K; e += blockDim.x) s_emb[e] = emb[e];
    __syncthreads();

    int gw = (blockIdx.x * blockDim.x + threadIdx.x) >> 5;   // global warp = pixel
    int lane = threadIdx.x & 31;
    if (gw >= total) return;

    int wo = gw % Wout; int t = gw / Wout;
    int ho = t % Hout;  int b = t / Hout;

    int kvbase[K];
    #pragma unroll
    for (int k = 0; k < K; k++) {
        int i = k / KW, j = k % KW;
        kvbase[k] = ((b * Hp + ho + i) * Wp + (wo + j)) * CO;
    }

    float partial[K];
    #pragma unroll
    for (int k = 0; k < K; k++) partial[k] = 0.f;
    int qbase = gw * CO;
    #pragma unroll
    for (int co = lane; co < CO; co += 32) {
        float qv = q[qbase + co];
        #pragma unroll
        for (int k = 0; k < K; k++)
            partial[k] = fmaf(qv, kpad[kvbase[k] + co], partial[k]);
    }
    #pragma unroll
    for (int k = 0; k < K; k++) {
        #pragma unroll
        for (int off = 16; off > 0; off >>= 1)
            partial[k] += __shfl_xor_sync(0xffffffffu, partial[k], off);
    }

    float mx = partial[0];
    #pragma unroll
    for (int k = 1; k < K; k++) mx = fmaxf(mx, partial[k]);
    float sum = 0.f;
    float aw[K];
    #pragma unroll
    for (int k = 0; k < K; k++) { aw[k] = expf(partial[k] - mx); sum += aw[k]; }
    float inv = 1.f / sum;

    float wkm[MMIX][K];
    #pragma unroll
    for (int m = 0; m < MMIX; m++)
        #pragma unroll
        for (int k = 0; k < K; k++)
            wkm[m][k] = aw[k] * inv * s_emb[m * K + k];

    #pragma unroll
    for (int co = lane; co < CO; co += 32) {
        float acc = 0.f;
        #pragma unroll
        for (int k = 0; k < K; k++) {
            int off = kvbase[k] + co;
            acc = fmaf(wkm[0][k], vpad[off], acc);
            acc = fmaf(wkm[1][k], vpad[vstride + off], acc);
            acc = fmaf(wkm[2][k], vpad[2 * vstride + off], acc);
            acc = fmaf(wkm[3][k], vpad[3 * vstride + off], acc);
        }
        out[qbase + co] = acc;
    }
}

// ---------------- BN pass 1: vectorized per-block partial sums ---------------
// in treated as float4; nvec = total/4. Channel of element e is e % Co;
// stride (grid*1024) and block offset (1024) are multiples of Co for Co in {16,64,128}.
__global__ void bn_stats(const float4* __restrict__ in, float* __restrict__ part,
                         int nvec, int Co)
{
    int tid = threadIdx.x;
    float s0=0.f,s1=0.f,s2=0.f,s3=0.f,q0=0.f,q1=0.f,q2=0.f,q3=0.f;
    for (int i = blockIdx.x * 256 + tid; i < nvec; i += gridDim.x * 256) {
        float4 v = in[i];
        s0 += v.x; q0 = fmaf(v.x, v.x, q0);
        s1 += v.y; q1 = fmaf(v.y, v.y, q1);
        s2 += v.z; q2 = fmaf(v.z, v.z, q2);
        s3 += v.w; q3 = fmaf(v.w, v.w, q3);
    }
    __shared__ float sh[1024], sh2[1024];
    sh[4*tid]=s0; sh[4*tid+1]=s1; sh[4*tid+2]=s2; sh[4*tid+3]=s3;
    sh2[4*tid]=q0; sh2[4*tid+1]=q1; sh2[4*tid+2]=q2; sh2[4*tid+3]=q3;
    __syncthreads();
    for (int off = 512; off >= Co; off >>= 1) {
        for (int e = tid; e < off; e += 256) { sh[e] += sh[e + off]; sh2[e] += sh2[e + off]; }
        __syncthreads();
    }
    if (tid < Co) {
        part[blockIdx.x * 2 * Co + tid]      = sh[tid];
        part[blockIdx.x * 2 * Co + Co + tid] = sh2[tid];
    }
}

// ---------------- BN pass 2: reduce partials -> scale/shift per channel ------
__global__ void bn_finalize(const float* __restrict__ part,
    const float* __restrict__ gamma, const float* __restrict__ beta,
    float* __restrict__ ss, int Co, float invN)
{
    int c = threadIdx.x;
    if (c >= Co) return;
    float s = 0.f, sq = 0.f;
    for (int g = 0; g < BN_BLOCKS; g++) {
        s  += part[g * 2 * Co + c];
        sq += part[g * 2 * Co + Co + c];
    }
    float mean = s * invN;
    float var  = sq * invN - mean * mean;
    float sc = gamma[c] * rsqrtf(var + 1e-5f);
    ss[c]      = sc;
    ss[Co + c] = beta[c] - mean * sc;
}

// ---------------- BN pass 3: elementwise apply + ReLU + stride subsample -----
__global__ void bn_apply(const float* __restrict__ in, const float* __restrict__ ss,
    float* __restrict__ out, int B, int H, int W, int Co, int sh_, int sw_,
    int Hs, int Ws, int totalOut)
{
    int idx = blockIdx.x * blockDim.x + threadIdx.x;
    if (idx >= totalOut) return;
    int c = idx % Co; int pix = idx / Co;
    int ws = pix % Ws; int t = pix / Ws;
    int hs = t % Hs;   int b = t / Hs;
    float v = in[((b * H + hs * sh_) * W + ws * sw_) * Co + c];
    float y = fmaf(v, ss[c], ss[Co + c]);
    out[idx] = y > 0.f ? y : 0.f;
}

// ---------------- final AvgPool2d((1,56)) ------------------------------------
__global__ void avgpool_kernel(const float* __restrict__ in, float* __restrict__ out,
                               int B, int C, int W, int nW)
{
    int idx = blockIdx.x * blockDim.x + threadIdx.x;
    int total = B * C * nW;
    if (idx >= total) return;
    int nw = idx % nW; int t = idx / nW; int c = t % C; int b = t / C;
    float s = 0.f;
    for (int j = 0; j < 56; j++)
        s += in[((long)b * W + nw * 56 + j) * C + c];
    out[(b * C + c) * nW + nw] = s * (1.f / 56.f);
}

// ---------------- launch -----------------------------------------------------
extern "C" void kernel_launch(void* const* d_in, const int* in_sizes, int n_in,
                              void* d_out, int out_size)
{
    const float* x = (const float*)d_in[0];
    const float* p[24];
    for (int i = 0; i < 24; i++) p[i] = (const float*)d_in[1 + i];

    float *att0, *bn0;
    float *kpad1, *vpad1, *q1, *att1, *bn1;
    float *kpad2, *vpad2, *q2, *att2, *bn2;
    float *emb, *prep0, *bnpart, *bnss;
    cudaGetSymbolAddress((void**)&att0,  d_att0);
    cudaGetSymbolAddress((void**)&bn0,   d_bn0);
    cudaGetSymbolAddress((void**)&kpad1, d_kpad1);
    cudaGetSymbolAddress((void**)&vpad1, d_vpad1);
    cudaGetSymbolAddress((void**)&q1,    d_q1);
    cudaGetSymbolAddress((void**)&att1,  d_att1);
    cudaGetSymbolAddress((void**)&bn1,   d_bn1);
    cudaGetSymbolAddress((void**)&kpad2, d_kpad2);
    cudaGetSymbolAddress((void**)&vpad2, d_vpad2);
    cudaGetSymbolAddress((void**)&q2,    d_q2);
    cudaGetSymbolAddress((void**)&att2,  d_att2);
    cudaGetSymbolAddress((void**)&bn2,   d_bn2);
    cudaGetSymbolAddress((void**)&emb,   d_emb);
    cudaGetSymbolAddress((void**)&prep0, d_prep0);
    cudaGetSymbolAddress((void**)&bnpart, d_bnpart);
    cudaGetSymbolAddress((void**)&bnss,   d_bnss);

    // ---- stage 0 (Cin=1, algebraically collapsed): Co=64, kh=1 kw=5, pad (2,2,0,0)
    emb_kernel<<<1, 32>>>(p[3], p[4], p[5], emb + 0, 64, 1, 5);
    prep0_kernel<<<1, 64>>>(p[0], p[1], p[2], emb + 0, prep0);
    {
        int total = 2 * 8 * 3000;   // 48000 pixels
        att0_kernel<<<(total * 32 + 255) / 256, 256>>>(x, prep0, att0);
        bn_stats<<<BN_BLOCKS, 256>>>((const float4*)att0, bnpart, total * 64 / 4, 64);
        bn_finalize<<<1, 64>>>(bnpart, p[6], p[7], bnss, 64, 1.f / (float)total);
        int outN = 2 * 4 * 1500 * 64;
        bn_apply<<<(outN + 255) / 256, 256>>>(att0, bnss, bn0, 2, 8, 3000, 64, 2, 2, 4, 1500, outN);
    }

    // ---- stage 1: Cin=64 -> Co=128, kh=2 kw=5, pad (2,2,1,1)
    emb_kernel<<<1, 64>>>(p[11], p[12], p[13], emb + 40, 128, 2, 5);
    {
        int tp = 2 * 6 * 1504;
        proj_kernel<<<(tp + PIX - 1) / PIX, 128>>>(bn0, p[8], p[9], p[10],
            kpad1, vpad1, q1, 2, 64, 4, 1500, 128, 6, 1504, 4, 1500, 1, 2);
        int total = 2 * 4 * 1500;
        att_kernel<2, 5, 128><<<(total * 32 + 255) / 256, 256>>>(q1, kpad1, vpad1,
            emb + 40, att1, 6, 1504, 4, 1500, total, tp * 128);
        bn_stats<<<BN_BLOCKS, 256>>>((const float4*)att1, bnpart, total * 128 / 4, 128);
        bn_finalize<<<1, 128>>>(bnpart, p[14], p[15], bnss, 128, 1.f / (float)total);
        int outN = 2 * 2 * 750 * 128;
        bn_apply<<<(outN + 255) / 256, 256>>>(att1, bnss, bn1, 2, 4, 1500, 128, 2, 2, 2, 750, outN);
    }

    // ---- stage 2: Cin=128 -> Co=16, kh=2 kw=5, pad (2,2,0,0)
    emb_kernel<<<1, 32>>>(p[19], p[20], p[21], emb + 80, 16, 2, 5);
    {
        int tp = 2 * 2 * 754;
        proj_kernel<<<(tp + PIX - 1) / PIX, 32>>>(bn1, p[16], p[17], p[18],
            kpad2, vpad2, q2, 2, 128, 2, 750, 16, 2, 754, 1, 750, 0, 2);
        int total = 2 * 1 * 750;
        att_kernel<2, 5, 16><<<(total * 32 + 255) / 256, 256>>>(q2, kpad2, vpad2,
            emb + 80, att2, 2, 754, 1, 750, total, tp * 16);
        bn_stats<<<BN_BLOCKS, 256>>>((const float4*)att2, bnpart, total * 16 / 4, 16);
        bn_finalize<<<1, 16>>>(bnpart, p[22], p[23], bnss, 16, 1.f / (float)total);
        int outN = 2 * 1 * 750 * 16;
        bn_apply<<<(outN + 255) / 256, 256>>>(att2, bnss, bn2, 2, 1, 750, 16, 1, 1, 1, 750, outN);
    }

    // ---- AvgPool2d((1,56)): [2,16,1,750] -> [2,16,1,13]
    avgpool_kernel<<<(2 * 16 * 13 + 127) / 128, 128>>>(bn2, (float*)d_out, 2, 16, 750, 13);
}

// round 6
// speedup vs baseline: 1.6599x; 1.1129x over previous
#include <cuda_runtime.h>
#include <math.h>

#define MMIX 4
#define PIX 8
#define NBLK 296   // fixed grid for att/apply kernels (2 waves on 148 SMs)

// ---------------- scratch (static __device__, no allocation) ----------------
__device__ float d_att0[3072000];
__device__ float d_bn0[768000];

__device__ float d_kpad1[2310144];
__device__ float d_vpad1[9240576];
__device__ float d_q1[1536000];
__device__ float d_att1[1536000];
__device__ float d_bn1[384000];

__device__ float d_kpad2[48256];
__device__ float d_vpad2[193024];
__device__ float d_q2[24000];
__device__ float d_att2[24000];

__device__ float d_emb[120];              // 3 stages x (M*K <= 40)
__device__ float d_prep0[321];            // [0]=qw.kw ; [1..320]=E[5][64]
__device__ float d_bnpart[NBLK * 256];    // per-block partials (2*Co <= 256)

// ---------------- device helper: one mixture-softmax tap ---------------------
__device__ void emb_tap(const float* __restrict__ ea, const float* __restrict__ eb,
                        const float* __restrict__ em, float* __restrict__ emb_out,
                        int Co, int kh, int kw_, int t)
{
    int K = kh * kw_;
    int i = t / kw_, j = t % kw_;
    float logits[MMIX];
    #pragma unroll
    for (int m = 0; m < MMIX; m++) {
        float la = 0.f, lb = 0.f;
        for (int c = 0; c < Co; c++) {
            float e = em[m * Co + c];
            la += e * ea[c * kh + i];
            lb += e * eb[c * kw_ + j];
        }
        logits[m] = la + lb;
    }
    float mx = logits[0];
    #pragma unroll
    for (int m = 1; m < MMIX; m++) mx = fmaxf(mx, logits[m]);
    float sum = 0.f;
    #pragma unroll
    for (int m = 0; m < MMIX; m++) { logits[m] = expf(logits[m] - mx); sum += logits[m]; }
    float inv = 1.f / sum;
    #pragma unroll
    for (int m = 0; m < MMIX; m++) emb_out[m * K + t] = logits[m] * inv;
}

// ---------------- setup: all 3 stage embeddings + stage-0 prep (1 launch) ----
__global__ void setup_kernel(
    const float* __restrict__ ea0, const float* __restrict__ eb0, const float* __restrict__ em0,
    const float* __restrict__ ea1, const float* __restrict__ eb1, const float* __restrict__ em1,
    const float* __restrict__ ea2, const float* __restrict__ eb2, const float* __restrict__ em2,
    const float* __restrict__ qw0, const float* __restrict__ kw0, const float* __restrict__ vw0,
    float* __restrict__ emb, float* __restrict__ prep)
{
    int t = threadIdx.x;  // 128 threads
    if (t < 5)                 emb_tap(ea0, eb0, em0, emb + 0,  64,  1, 5, t);
    else if (t >= 32 && t < 42) emb_tap(ea1, eb1, em1, emb + 40, 128, 2, 5, t - 32);
    else if (t >= 64 && t < 74) emb_tap(ea2, eb2, em2, emb + 80, 16,  2, 5, t - 64);
    __syncthreads();   // emb0 visible (same block, global mem)

    __shared__ float sh[64];
    if (t < 64) sh[t] = qw0[t] * kw0[t];
    __syncthreads();
    if (t == 0) {
        float s = 0.f;
        for (int i = 0; i < 64; i++) s += sh[i];
        prep[0] = s;
    }
    if (t < 64) {
        #pragma unroll
        for (int j = 0; j < 5; j++) {
            float e = 0.f;
            #pragma unroll
            for (int m = 0; m < MMIX; m++) e += emb[m * 5 + j] * vw0[m * 64 + t];
            prep[1 + j * 64 + t] = e;
        }
    }
}

// ---------------- stage-0 fused attention + BN stats (Cin=1 collapse) --------
// warp = pixel (grid-stride); epilogue: deterministic per-block sum/sumsq
__global__ void att0_kernel(const float* __restrict__ x, const float* __restrict__ prep,
                            float* __restrict__ out, float* __restrict__ bnpart)
{
    __shared__ float sE[5 * 64];
    __shared__ float red_s[8][64], red_q[8][64];
    for (int e = threadIdx.x; e < 320; e += blockDim.x) sE[e] = prep[1 + e];
    __syncthreads();

    int wid = threadIdx.x >> 5, lane = threadIdx.x & 31;
    int warp0 = blockIdx.x * 8 + wid, wstride = gridDim.x * 8;
    float c0 = prep[0];

    float s0 = 0.f, s1 = 0.f, q0 = 0.f, q1 = 0.f;
    for (int gw = warp0; gw < 48000; gw += wstride) {
        int wo = gw % 3000;
        int rowbase = (gw / 3000) * 3000;

        float xs[5];
        #pragma unroll
        for (int j = 0; j < 5; j++) {
            int w = wo - 2 + j;
            xs[j] = (w >= 0 && w < 3000) ? x[rowbase + w] : 0.f;
        }
        float cx = c0 * xs[2];
        float sc[5]; float mx = -1e30f;
        #pragma unroll
        for (int j = 0; j < 5; j++) { sc[j] = cx * xs[j]; mx = fmaxf(mx, sc[j]); }
        float sum = 0.f;
        #pragma unroll
        for (int j = 0; j < 5; j++) { sc[j] = expf(sc[j] - mx); sum += sc[j]; }
        float inv = 1.f / sum;
        float wj[5];
        #pragma unroll
        for (int j = 0; j < 5; j++) wj[j] = sc[j] * inv * xs[j];

        float a0 = 0.f, a1 = 0.f;
        #pragma unroll
        for (int j = 0; j < 5; j++) {
            a0 = fmaf(wj[j], sE[j * 64 + lane], a0);
            a1 = fmaf(wj[j], sE[j * 64 + 32 + lane], a1);
        }
        int ob = gw * 64;
        out[ob + lane] = a0;
        out[ob + 32 + lane] = a1;
        s0 += a0; q0 = fmaf(a0, a0, q0);
        s1 += a1; q1 = fmaf(a1, a1, q1);
    }
    red_s[wid][lane] = s0; red_s[wid][32 + lane] = s1;
    red_q[wid][lane] = q0; red_q[wid][32 + lane] = q1;
    __syncthreads();
    for (int c = threadIdx.x; c < 64; c += blockDim.x) {
        float s = 0.f, q = 0.f;
        #pragma unroll
        for (int w = 0; w < 8; w++) { s += red_s[w][c]; q += red_q[w][c]; }
        bnpart[blockIdx.x * 128 + c]      = s;
        bnpart[blockIdx.x * 128 + 64 + c] = q;
    }
}

// ---------------- projection (unchanged; profiled next round at slot #4) -----
__global__ void proj_kernel(const float* __restrict__ x,
    const float* __restrict__ qw, const float* __restrict__ kw_,
    const float* __restrict__ vw,
    float* __restrict__ kpad, float* __restrict__ vpad, float* __restrict__ qout,
    int B, int Cin, int H, int W, int Co,
    int Hp, int Wp, int Hout, int Wout, int pt, int pl)
{
    int co = threadIdx.x;
    int g0 = blockIdx.x * PIX;
    int totalPix = B * Hp * Wp;

    int xbase[PIX]; int hh[PIX], ww[PIX], bb[PIX];
    bool valid[PIX], inq[PIX];
    #pragma unroll
    for (int p = 0; p < PIX; p++) {
        int pix = g0 + p;
        valid[p] = false; inq[p] = false;
        xbase[p] = 0; hh[p] = 0; ww[p] = 0; bb[p] = 0;
        if (pix < totalPix) {
            int wp = pix % Wp; int t = pix / Wp;
            int hp = t % Hp;  int b = t / Hp;
            int h = hp - pt, w = wp - pl;
            if (h >= 0 && h < H && w >= 0 && w < W) {
                valid[p] = true;
                xbase[p] = ((b * H + h) * W + w) * Cin;
                inq[p] = (h < Hout) && (w < Wout);
                hh[p] = h; ww[p] = w; bb[p] = b;
            }
        }
    }
    if (co >= Co) return;

    float ak[PIX], aq[PIX], av0[PIX], av1[PIX], av2[PIX], av3[PIX];
    #pragma unroll
    for (int p = 0; p < PIX; p++) { ak[p]=0.f; aq[p]=0.f; av0[p]=0.f; av1[p]=0.f; av2[p]=0.f; av3[p]=0.f; }

    int CinCo = Cin * Co;
    for (int ci = 0; ci < Cin; ci++) {
        float wq  = qw [ci * Co + co];
        float wk  = kw_[ci * Co + co];
        float wv0 = vw [ci * Co + co];
        float wv1 = vw [CinCo     + ci * Co + co];
        float wv2 = vw [2 * CinCo + ci * Co + co];
        float wv3 = vw [3 * CinCo + ci * Co + co];
        #pragma unroll
        for (int p = 0; p < PIX; p++) {
            if (valid[p]) {
                float xv = x[xbase[p] + ci];
                aq[p]  = fmaf(xv, wq,  aq[p]);
                ak[p]  = fmaf(xv, wk,  ak[p]);
                av0[p] = fmaf(xv, wv0, av0[p]);
                av1[p] = fmaf(xv, wv1, av1[p]);
                av2[p] = fmaf(xv, wv2, av2[p]);
                av3[p] = fmaf(xv, wv3, av3[p]);
            }
        }
    }

    int vstride = totalPix * Co;
    #pragma unroll
    for (int p = 0; p < PIX; p++) {
        int pix = g0 + p;
        if (pix < totalPix) {
            int off = pix * Co + co;
            kpad[off] = ak[p];
            vpad[off] = av0[p];
            vpad[vstride + off] = av1[p];
            vpad[2 * vstride + off] = av2[p];
            vpad[3 * vstride + off] = av3[p];
            if (inq[p])
                qout[((bb[p] * Hout + hh[p]) * Wout + ww[p]) * Co + co] = aq[p];
        }
    }
}

// ---------------- attention + fused BN stats: warp per pixel, grid-stride ----
template<int KH, int KW, int CO>
__global__ void att_stats_kernel(const float* __restrict__ q,
    const float* __restrict__ kpad, const float* __restrict__ vpad,
    const float* __restrict__ emb, float* __restrict__ out,
    int Hp, int Wp, int Hout, int Wout, int total, int vstride,
    float* __restrict__ bnpart)
{
    constexpr int K = KH * KW;
    constexpr int CPL = (CO + 31) / 32;      // channels per lane
    constexpr int CW = (CO > 32) ? CO : 32;
    __shared__ float s_emb[MMIX * K];
    __shared__ float red_s[8][CW], red_q[8][CW];
    for (int e = threadIdx.x; e < MMIX * K; e += blockDim.x) s_emb[e] = emb[e];
    __syncthreads();

    int wid = threadIdx.x >> 5, lane = threadIdx.x & 31;
    int warp0 = blockIdx.x * 8 + wid, wstride = gridDim.x * 8;

    float sacc[CPL], qacc[CPL];
    #pragma unroll
    for (int i = 0; i < CPL; i++) { sacc[i] = 0.f; qacc[i] = 0.f; }

    for (int gw = warp0; gw < total; gw += wstride) {
        int wo = gw % Wout; int t = gw / Wout;
        int ho = t % Hout;  int b = t / Hout;

        int kvbase[K];
        #pragma unroll
        for (int k = 0; k < K; k++) {
            int i = k / KW, j = k % KW;
            kvbase[k] = ((b * Hp + ho + i) * Wp + (wo + j)) * CO;
        }

        float partial[K];
        #pragma unroll
        for (int k = 0; k < K; k++) partial[k] = 0.f;
        int qbase = gw * CO;
        #pragma unroll
        for (int i = 0; i < CPL; i++) {
            int co = lane + 32 * i;
            if (co < CO) {
                float qv = q[qbase + co];
                #pragma unroll
                for (int k = 0; k < K; k++)
                    partial[k] = fmaf(qv, kpad[kvbase[k] + co], partial[k]);
            }
        }
        #pragma unroll
        for (int k = 0; k < K; k++) {
            #pragma unroll
            for (int off = 16; off > 0; off >>= 1)
                partial[k] += __shfl_xor_sync(0xffffffffu, partial[k], off);
        }

        float mx = partial[0];
        #pragma unroll
        for (int k = 1; k < K; k++) mx = fmaxf(mx, partial[k]);
        float sum = 0.f;
        float aw[K];
        #pragma unroll
        for (int k = 0; k < K; k++) { aw[k] = expf(partial[k] - mx); sum += aw[k]; }
        float inv = 1.f / sum;

        float wkm[MMIX][K];
        #pragma unroll
        for (int m = 0; m < MMIX; m++)
            #pragma unroll
            for (int k = 0; k < K; k++)
                wkm[m][k] = aw[k] * inv * s_emb[m * K + k];

        #pragma unroll
        for (int i = 0; i < CPL; i++) {
            int co = lane + 32 * i;
            if (co < CO) {
                float a0 = 0.f, a1 = 0.f, a2 = 0.f, a3 = 0.f;
                #pragma unroll
                for (int k = 0; k < K; k++) {
                    int off = kvbase[k] + co;
                    a0 = fmaf(wkm[0][k], vpad[off], a0);
                    a1 = fmaf(wkm[1][k], vpad[vstride + off], a1);
                    a2 = fmaf(wkm[2][k], vpad[2 * vstride + off], a2);
                    a3 = fmaf(wkm[3][k], vpad[3 * vstride + off], a3);
                }
                float acc = (a0 + a1) + (a2 + a3);
                out[qbase + co] = acc;
                sacc[i] += acc;
                qacc[i] = fmaf(acc, acc, qacc[i]);
            }
        }
    }

    #pragma unroll
    for (int i = 0; i < CPL; i++) {
        int c = lane + 32 * i;
        if (c < CO) { red_s[wid][c] = sacc[i]; red_q[wid][c] = qacc[i]; }
    }
    __syncthreads();
    for (int c = threadIdx.x; c < CO; c += blockDim.x) {
        float s = 0.f, q2 = 0.f;
        #pragma unroll
        for (int w = 0; w < 8; w++) { s += red_s[w][c]; q2 += red_q[w][c]; }
        bnpart[blockIdx.x * 2 * CO + c]      = s;
        bnpart[blockIdx.x * 2 * CO + CO + c] = q2;
    }
}

// ---------------- BN finalize (redundant per block) + apply + subsample ------
template<int CO>
__global__ void bn_apply_fused(const float* __restrict__ in,
    const float* __restrict__ bnpart, int nparts,
    const float* __restrict__ gamma, const float* __restrict__ beta,
    float* __restrict__ out, int H, int W, int Hs, int Ws, int totalOut, float invN)
{
    __shared__ float ssc[CO], ssh[CO];
    for (int c = threadIdx.x; c < CO; c += blockDim.x) {
        float s = 0.f, q = 0.f;
        for (int g = 0; g < nparts; g++) {
            s += bnpart[g * 2 * CO + c];
            q += bnpart[g * 2 * CO + CO + c];
        }
        float mean = s * invN;
        float var  = q * invN - mean * mean;
        float sc = gamma[c] * rsqrtf(var + 1e-5f);
        ssc[c] = sc;
        ssh[c] = beta[c] - mean * sc;
    }
    __syncthreads();
    for (int idx = blockIdx.x * blockDim.x + threadIdx.x; idx < totalOut;
         idx += gridDim.x * blockDim.x) {
        int c = idx & (CO - 1); int pix = idx / CO;
        int ws = pix % Ws; int t = pix / Ws;
        int hs = t % Hs;   int b = t / Hs;
        float v = in[((b * H + hs * 2) * W + ws * 2) * CO + c];
        float y = fmaf(v, ssc[c], ssh[c]);
        out[idx] = y > 0.f ? y : 0.f;
    }
}

// ---------------- stage-2 BN finalize + apply + AvgPool(1,56) -> d_out -------
// warp per output (b,c,nw); 416 outputs total.
__global__ void bn_avg_final(const float* __restrict__ in,
    const float* __restrict__ bnpart, int nparts,
    const float* __restrict__ gamma, const float* __restrict__ beta,
    float* __restrict__ out)
{
    __shared__ float ssc[16], ssh[16];
    for (int c = threadIdx.x; c < 16; c += blockDim.x) {
        float s = 0.f, q = 0.f;
        for (int g = 0; g < nparts; g++) {
            s += bnpart[g * 32 + c];
            q += bnpart[g * 32 + 16 + c];
        }
        float mean = s * (1.f / 1500.f);
        float var  = q * (1.f / 1500.f) - mean * mean;
        float sc = gamma[c] * rsqrtf(var + 1e-5f);
        ssc[c] = sc;
        ssh[c] = beta[c] - mean * sc;
    }
    __syncthreads();
    int gw = (blockIdx.x * blockDim.x + threadIdx.x) >> 5;
    int lane = threadIdx.x & 31;
    if (gw >= 416) return;
    int nw = gw % 13; int t = gw / 13;
    int c = t % 16;   int b = t / 16;
    float sc = ssc[c], sh_ = ssh[c];
    float s = 0.f;
    int base = b * 750 + nw * 56;
    #pragma unroll
    for (int j0 = 0; j0 < 56; j0 += 32) {
        int j = j0 + lane;
        if (j < 56) {
            float v = in[(base + j) * 16 + c];
            float y = fmaf(v, sc, sh_);
            s += (y > 0.f ? y : 0.f);
        }
    }
    #pragma unroll
    for (int off = 16; off > 0; off >>= 1)
        s += __shfl_xor_sync(0xffffffffu, s, off);
    if (lane == 0) out[(b * 16 + c) * 13 + nw] = s * (1.f / 56.f);
}

// ---------------- launch (9 nodes) -------------------------------------------
extern "C" void kernel_launch(void* const* d_in, const int* in_sizes, int n_in,
                              void* d_out, int out_size)
{
    const float* x = (const float*)d_in[0];
    const float* p[24];
    for (int i = 0; i < 24; i++) p[i] = (const float*)d_in[1 + i];

    float *att0, *bn0, *kpad1, *vpad1, *q1, *att1, *bn1;
    float *kpad2, *vpad2, *q2, *att2;
    float *emb, *prep0, *bnpart;
    cudaGetSymbolAddress((void**)&att0,  d_att0);
    cudaGetSymbolAddress((void**)&bn0,   d_bn0);
    cudaGetSymbolAddress((void**)&kpad1, d_kpad1);
    cudaGetSymbolAddress((void**)&vpad1, d_vpad1);
    cudaGetSymbolAddress((void**)&q1,    d_q1);
    cudaGetSymbolAddress((void**)&att1,  d_att1);
    cudaGetSymbolAddress((void**)&bn1,   d_bn1);
    cudaGetSymbolAddress((void**)&kpad2, d_kpad2);
    cudaGetSymbolAddress((void**)&vpad2, d_vpad2);
    cudaGetSymbolAddress((void**)&q2,    d_q2);
    cudaGetSymbolAddress((void**)&att2,  d_att2);
    cudaGetSymbolAddress((void**)&emb,   d_emb);
    cudaGetSymbolAddress((void**)&prep0, d_prep0);
    cudaGetSymbolAddress((void**)&bnpart, d_bnpart);

    // 1) setup: all embeddings + stage-0 prep
    setup_kernel<<<1, 128>>>(p[3], p[4], p[5], p[11], p[12], p[13],
                             p[19], p[20], p[21], p[0], p[1], p[2], emb, prep0);

    // 2) stage-0 fused attention + stats   3) BN apply + subsample
    att0_kernel<<<NBLK, 256>>>(x, prep0, att0, bnpart);
    bn_apply_fused<64><<<NBLK, 256>>>(att0, bnpart, NBLK, p[6], p[7], bn0,
                                      8, 3000, 4, 1500, 2 * 4 * 1500 * 64,
                                      1.f / 48000.f);

    // 4) stage-1 projection (profiled slot)
    {
        int tp = 2 * 6 * 1504;
        proj_kernel<<<(tp + PIX - 1) / PIX, 128>>>(bn0, p[8], p[9], p[10],
            kpad1, vpad1, q1, 2, 64, 4, 1500, 128, 6, 1504, 4, 1500, 1, 2);
        // 5) stage-1 attention + stats   6) BN apply + subsample
        att_stats_kernel<2, 5, 128><<<NBLK, 256>>>(q1, kpad1, vpad1, emb + 40,
            att1, 6, 1504, 4, 1500, 2 * 4 * 1500, tp * 128, bnpart);
        bn_apply_fused<128><<<NBLK, 256>>>(att1, bnpart, NBLK, p[14], p[15], bn1,
                                           4, 1500, 2, 750, 2 * 2 * 750 * 128,
                                           1.f / 12000.f);
    }

    // 7) stage-2 projection  8) attention + stats  9) BN + avgpool -> out
    {
        int tp = 2 * 2 * 754;
        proj_kernel<<<(tp + PIX - 1) / PIX, 32>>>(bn1, p[16], p[17], p[18],
            kpad2, vpad2, q2, 2, 128, 2, 750, 16, 2, 754, 1, 750, 0, 2);
        att_stats_kernel<2, 5, 16><<<NBLK, 256>>>(q2, kpad2, vpad2, emb + 80,
            att2, 2, 754, 1, 750, 2 * 1 * 750, tp * 16, bnpart);
        bn_avg_final<<<52, 256>>>(att2, bnpart, NBLK, p[22], p[23], (float*)d_out);
    }
}

// round 7
// speedup vs baseline: 2.1740x; 1.3097x over previous
#include <cuda_runtime.h>
#include <math.h>

#define MMIX 4
#define PIX 8
#define NBLK 296   // fixed grid for att/apply kernels (2 waves on 148 SMs)

// ---------------- scratch (static __device__, no allocation) ----------------
__device__ float d_att0[3072000];
__device__ float d_bn0[768000];

__device__ float d_kpad1[2310144];
__device__ float d_vpad1[9240576];
__device__ float d_q1[1536000];
__device__ float d_att1[1536000];
__device__ float d_bn1[384000];

__device__ float d_kpad2[48256];
__device__ float d_vpad2[193024];
__device__ float d_q2[24000];
__device__ float d_att2[24000];

__device__ float d_emb[120];              // 3 stages x (M*K <= 40)
__device__ float d_prep0[321];            // [0]=qw.kw ; [1..320]=E[5][64]
__device__ float d_bnpart[NBLK * 256];    // per-block partials (2*Co <= 256)

// ---------------- device helper: one mixture-softmax tap ---------------------
__device__ void emb_tap(const float* __restrict__ ea, const float* __restrict__ eb,
                        const float* __restrict__ em, float* __restrict__ emb_out,
                        int Co, int kh, int kw_, int t)
{
    int K = kh * kw_;
    int i = t / kw_, j = t % kw_;
    float logits[MMIX];
    #pragma unroll
    for (int m = 0; m < MMIX; m++) {
        float la = 0.f, lb = 0.f;
        for (int c = 0; c < Co; c++) {
            float e = em[m * Co + c];
            la += e * ea[c * kh + i];
            lb += e * eb[c * kw_ + j];
        }
        logits[m] = la + lb;
    }
    float mx = logits[0];
    #pragma unroll
    for (int m = 1; m < MMIX; m++) mx = fmaxf(mx, logits[m]);
    float sum = 0.f;
    #pragma unroll
    for (int m = 0; m < MMIX; m++) { logits[m] = expf(logits[m] - mx); sum += logits[m]; }
    float inv = 1.f / sum;
    #pragma unroll
    for (int m = 0; m < MMIX; m++) emb_out[m * K + t] = logits[m] * inv;
}

// ---------------- setup: all 3 stage embeddings + stage-0 prep (1 launch) ----
__global__ void setup_kernel(
    const float* __restrict__ ea0, const float* __restrict__ eb0, const float* __restrict__ em0,
    const float* __restrict__ ea1, const float* __restrict__ eb1, const float* __restrict__ em1,
    const float* __restrict__ ea2, const float* __restrict__ eb2, const float* __restrict__ em2,
    const float* __restrict__ qw0, const float* __restrict__ kw0, const float* __restrict__ vw0,
    float* __restrict__ emb, float* __restrict__ prep)
{
    int t = threadIdx.x;  // 128 threads
    if (t < 5)                 emb_tap(ea0, eb0, em0, emb + 0,  64,  1, 5, t);
    else if (t >= 32 && t < 42) emb_tap(ea1, eb1, em1, emb + 40, 128, 2, 5, t - 32);
    else if (t >= 64 && t < 74) emb_tap(ea2, eb2, em2, emb + 80, 16,  2, 5, t - 64);
    __syncthreads();   // emb0 visible (same block, global mem)

    __shared__ float sh[64];
    if (t < 64) sh[t] = qw0[t] * kw0[t];
    __syncthreads();
    if (t == 0) {
        float s = 0.f;
        for (int i = 0; i < 64; i++) s += sh[i];
        prep[0] = s;
    }
    if (t < 64) {
        #pragma unroll
        for (int j = 0; j < 5; j++) {
            float e = 0.f;
            #pragma unroll
            for (int m = 0; m < MMIX; m++) e += emb[m * 5 + j] * vw0[m * 64 + t];
            prep[1 + j * 64 + t] = e;
        }
    }
}

// ---------------- stage-0 fused attention + BN stats (Cin=1 collapse) --------
__global__ void att0_kernel(const float* __restrict__ x, const float* __restrict__ prep,
                            float* __restrict__ out, float* __restrict__ bnpart)
{
    __shared__ float sE[5 * 64];
    __shared__ float red_s[8][64], red_q[8][64];
    for (int e = threadIdx.x; e < 320; e += blockDim.x) sE[e] = prep[1 + e];
    __syncthreads();

    int wid = threadIdx.x >> 5, lane = threadIdx.x & 31;
    int warp0 = blockIdx.x * 8 + wid, wstride = gridDim.x * 8;
    float c0 = prep[0];

    float s0 = 0.f, s1 = 0.f, q0 = 0.f, q1 = 0.f;
    for (int gw = warp0; gw < 48000; gw += wstride) {
        int wo = gw % 3000;
        int rowbase = (gw / 3000) * 3000;

        float xs[5];
        #pragma unroll
        for (int j = 0; j < 5; j++) {
            int w = wo - 2 + j;
            xs[j] = (w >= 0 && w < 3000) ? x[rowbase + w] : 0.f;
        }
        float cx = c0 * xs[2];
        float sc[5]; float mx = -1e30f;
        #pragma unroll
        for (int j = 0; j < 5; j++) { sc[j] = cx * xs[j]; mx = fmaxf(mx, sc[j]); }
        float sum = 0.f;
        #pragma unroll
        for (int j = 0; j < 5; j++) { sc[j] = expf(sc[j] - mx); sum += sc[j]; }
        float inv = 1.f / sum;
        float wj[5];
        #pragma unroll
        for (int j = 0; j < 5; j++) wj[j] = sc[j] * inv * xs[j];

        float a0 = 0.f, a1 = 0.f;
        #pragma unroll
        for (int j = 0; j < 5; j++) {
            a0 = fmaf(wj[j], sE[j * 64 + lane], a0);
            a1 = fmaf(wj[j], sE[j * 64 + 32 + lane], a1);
        }
        int ob = gw * 64;
        out[ob + lane] = a0;
        out[ob + 32 + lane] = a1;
        s0 += a0; q0 = fmaf(a0, a0, q0);
        s1 += a1; q1 = fmaf(a1, a1, q1);
    }
    red_s[wid][lane] = s0; red_s[wid][32 + lane] = s1;
    red_q[wid][lane] = q0; red_q[wid][32 + lane] = q1;
    __syncthreads();
    for (int c = threadIdx.x; c < 64; c += blockDim.x) {
        float s = 0.f, q = 0.f;
        #pragma unroll
        for (int w = 0; w < 8; w++) { s += red_s[w][c]; q += red_q[w][c]; }
        bnpart[blockIdx.x * 128 + c]      = s;
        bnpart[blockIdx.x * 128 + 64 + c] = q;
    }
}

// ---------------- stage-1 projection as smem-tiled GEMM ----------------------
// C[12000x768] = X[12000x64] * W[64x768]; grid.y selects stream (0:q 1:k 2..5:v)
// Mtile=64, Ntile=128, thread = 4x8 register tile. Valid pixels only; padded
// borders of kpad/vpad stay zero (never written; __device__ zero-init).
__global__ void gemm_proj1(const float* __restrict__ xin,
    const float* __restrict__ qw, const float* __restrict__ kw_,
    const float* __restrict__ vw,
    float* __restrict__ qout, float* __restrict__ kpad, float* __restrict__ vpad,
    int vstride)
{
    __shared__ float xs[64][64];     // [pix][ci]  16KB
    __shared__ float ws[64][128];    // [ci][co]   32KB

    int s = blockIdx.y;
    const float* wsrc = (s == 0) ? qw : (s == 1) ? kw_ : vw + (s - 2) * 64 * 128;
    int tid = threadIdx.x;           // 256
    int m0 = blockIdx.x * 64;

    // weights: 2048 float4, direct copy
    {
        const float4* src = (const float4*)wsrc;
        float4* dst = (float4*)&ws[0][0];
        #pragma unroll
        for (int i = 0; i < 8; i++) dst[tid + 256 * i] = src[tid + 256 * i];
    }
    // x tile: 1024 float4, row = idx/16
    {
        float4* dst = (float4*)&xs[0][0];
        #pragma unroll
        for (int i = 0; i < 4; i++) {
            int idx = tid + 256 * i;
            int pix = m0 + (idx >> 4);
            dst[idx] = (pix < 12000) ? ((const float4*)xin)[pix * 16 + (idx & 15)]
                                     : make_float4(0.f, 0.f, 0.f, 0.f);
        }
    }
    __syncthreads();

    int ty = tid >> 4, tx = tid & 15;
    int mr = ty * 4, nc = tx * 8;

    float acc[4][8];
    #pragma unroll
    for (int i = 0; i < 4; i++)
        #pragma unroll
        for (int j = 0; j < 8; j++) acc[i][j] = 0.f;

    #pragma unroll 16
    for (int k = 0; k < 64; k++) {
        float av0 = xs[mr + 0][k], av1 = xs[mr + 1][k];
        float av2 = xs[mr + 2][k], av3 = xs[mr + 3][k];
        float4 b0 = *(const float4*)&ws[k][nc];
        float4 b1 = *(const float4*)&ws[k][nc + 4];
        float bv[8] = {b0.x, b0.y, b0.z, b0.w, b1.x, b1.y, b1.z, b1.w};
        #pragma unroll
        for (int j = 0; j < 8; j++) {
            acc[0][j] = fmaf(av0, bv[j], acc[0][j]);
            acc[1][j] = fmaf(av1, bv[j], acc[1][j]);
            acc[2][j] = fmaf(av2, bv[j], acc[2][j]);
            acc[3][j] = fmaf(av3, bv[j], acc[3][j]);
        }
    }

    #pragma unroll
    for (int i = 0; i < 4; i++) {
        int pix = m0 + mr + i;
        if (pix >= 12000) continue;
        float* dst; int base;
        if (s == 0) {
            dst = qout; base = pix * 128 + nc;
        } else {
            int b = pix / 6000, rem = pix % 6000;
            int h = rem / 1500, w = rem % 1500;
            int padpix = (b * 6 + h + 1) * 1504 + (w + 2);   // pt=1, pl=2
            base = padpix * 128 + nc;
            dst = (s == 1) ? kpad : vpad + (s - 2) * vstride;
        }
        *(float4*)&dst[base]     = make_float4(acc[i][0], acc[i][1], acc[i][2], acc[i][3]);
        *(float4*)&dst[base + 4] = make_float4(acc[i][4], acc[i][5], acc[i][6], acc[i][7]);
    }
}

// ---------------- stage-2 projection (small; SIMT per-pixel) -----------------
__global__ void proj_kernel(const float* __restrict__ x,
    const float* __restrict__ qw, const float* __restrict__ kw_,
    const float* __restrict__ vw,
    float* __restrict__ kpad, float* __restrict__ vpad, float* __restrict__ qout,
    int B, int Cin, int H, int W, int Co,
    int Hp, int Wp, int Hout, int Wout, int pt, int pl)
{
    int co = threadIdx.x;
    int g0 = blockIdx.x * PIX;
    int totalPix = B * Hp * Wp;

    int xbase[PIX]; int hh[PIX], ww[PIX], bb[PIX];
    bool valid[PIX], inq[PIX];
    #pragma unroll
    for (int p = 0; p < PIX; p++) {
        int pix = g0 + p;
        valid[p] = false; inq[p] = false;
        xbase[p] = 0; hh[p] = 0; ww[p] = 0; bb[p] = 0;
        if (pix < totalPix) {
            int wp = pix % Wp; int t = pix / Wp;
            int hp = t % Hp;  int b = t / Hp;
            int h = hp - pt, w = wp - pl;
            if (h >= 0 && h < H && w >= 0 && w < W) {
                valid[p] = true;
                xbase[p] = ((b * H + h) * W + w) * Cin;
                inq[p] = (h < Hout) && (w < Wout);
                hh[p] = h; ww[p] = w; bb[p] = b;
            }
        }
    }
    if (co >= Co) return;

    float ak[PIX], aq[PIX], av0[PIX], av1[PIX], av2[PIX], av3[PIX];
    #pragma unroll
    for (int p = 0; p < PIX; p++) { ak[p]=0.f; aq[p]=0.f; av0[p]=0.f; av1[p]=0.f; av2[p]=0.f; av3[p]=0.f; }

    int CinCo = Cin * Co;
    for (int ci = 0; ci < Cin; ci++) {
        float wq  = qw [ci * Co + co];
        float wk  = kw_[ci * Co + co];
        float wv0 = vw [ci * Co + co];
        float wv1 = vw [CinCo     + ci * Co + co];
        float wv2 = vw [2 * CinCo + ci * Co + co];
        float wv3 = vw [3 * CinCo + ci * Co + co];
        #pragma unroll
        for (int p = 0; p < PIX; p++) {
            if (valid[p]) {
                float xv = x[xbase[p] + ci];
                aq[p]  = fmaf(xv, wq,  aq[p]);
                ak[p]  = fmaf(xv, wk,  ak[p]);
                av0[p] = fmaf(xv, wv0, av0[p]);
                av1[p] = fmaf(xv, wv1, av1[p]);
                av2[p] = fmaf(xv, wv2, av2[p]);
                av3[p] = fmaf(xv, wv3, av3[p]);
            }
        }
    }

    int vstride = totalPix * Co;
    #pragma unroll
    for (int p = 0; p < PIX; p++) {
        int pix = g0 + p;
        if (pix < totalPix) {
            int off = pix * Co + co;
            kpad[off] = ak[p];
            vpad[off] = av0[p];
            vpad[vstride + off] = av1[p];
            vpad[2 * vstride + off] = av2[p];
            vpad[3 * vstride + off] = av3[p];
            if (inq[p])
                qout[((bb[p] * Hout + hh[p]) * Wout + ww[p]) * Co + co] = aq[p];
        }
    }
}

// ---------------- attention + fused BN stats: warp per pixel, grid-stride ----
template<int KH, int KW, int CO>
__global__ void att_stats_kernel(const float* __restrict__ q,
    const float* __restrict__ kpad, const float* __restrict__ vpad,
    const float* __restrict__ emb, float* __restrict__ out,
    int Hp, int Wp, int Hout, int Wout, int total, int vstride,
    float* __restrict__ bnpart)
{
    constexpr int K = KH * KW;
    constexpr int CPL = (CO + 31) / 32;
    constexpr int CW = (CO > 32) ? CO : 32;
    __shared__ float s_emb[MMIX * K];
    __shared__ float red_s[8][CW], red_q[8][CW];
    for (int e = threadIdx.x; e < MMIX * K; e += blockDim.x) s_emb[e] = emb[e];
    __syncthreads();

    int wid = threadIdx.x >> 5, lane = threadIdx.x & 31;
    int warp0 = blockIdx.x * 8 + wid, wstride = gridDim.x * 8;

    float sacc[CPL], qacc[CPL];
    #pragma unroll
    for (int i = 0; i < CPL; i++) { sacc[i] = 0.f; qacc[i] = 0.f; }

    for (int gw = warp0; gw < total; gw += wstride) {
        int wo = gw % Wout; int t = gw / Wout;
        int ho = t % Hout;  int b = t / Hout;

        int kvbase[K];
        #pragma unroll
        for (int k = 0; k < K; k++) {
            int i = k / KW, j = k % KW;
            kvbase[k] = ((b * Hp + ho + i) * Wp + (wo + j)) * CO;
        }

        float partial[K];
        #pragma unroll
        for (int k = 0; k < K; k++) partial[k] = 0.f;
        int qbase = gw * CO;
        #pragma unroll
        for (int i = 0; i < CPL; i++) {
            int co = lane + 32 * i;
            if (co < CO) {
                float qv = q[qbase + co];
                #pragma unroll
                for (int k = 0; k < K; k++)
                    partial[k] = fmaf(qv, kpad[kvbase[k] + co], partial[k]);
            }
        }
        #pragma unroll
        for (int k = 0; k < K; k++) {
            #pragma unroll
            for (int off = 16; off > 0; off >>= 1)
                partial[k] += __shfl_xor_sync(0xffffffffu, partial[k], off);
        }

        float mx = partial[0];
        #pragma unroll
        for (int k = 1; k < K; k++) mx = fmaxf(mx, partial[k]);
        float sum = 0.f;
        float aw[K];
        #pragma unroll
        for (int k = 0; k < K; k++) { aw[k] = expf(partial[k] - mx); sum += aw[k]; }
        float inv = 1.f / sum;

        float wkm[MMIX][K];
        #pragma unroll
        for (int m = 0; m < MMIX; m++)
            #pragma unroll
            for (int k = 0; k < K; k++)
                wkm[m][k] = aw[k] * inv * s_emb[m * K + k];

        #pragma unroll
        for (int i = 0; i < CPL; i++) {
            int co = lane + 32 * i;
            if (co < CO) {
                float a0 = 0.f, a1 = 0.f, a2 = 0.f, a3 = 0.f;
                #pragma unroll
                for (int k = 0; k < K; k++) {
                    int off = kvbase[k] + co;
                    a0 = fmaf(wkm[0][k], vpad[off], a0);
                    a1 = fmaf(wkm[1][k], vpad[vstride + off], a1);
                    a2 = fmaf(wkm[2][k], vpad[2 * vstride + off], a2);
                    a3 = fmaf(wkm[3][k], vpad[3 * vstride + off], a3);
                }
                float acc = (a0 + a1) + (a2 + a3);
                out[qbase + co] = acc;
                sacc[i] += acc;
                qacc[i] = fmaf(acc, acc, qacc[i]);
            }
        }
    }

    #pragma unroll
    for (int i = 0; i < CPL; i++) {
        int c = lane + 32 * i;
        if (c < CO) { red_s[wid][c] = sacc[i]; red_q[wid][c] = qacc[i]; }
    }
    __syncthreads();
    for (int c = threadIdx.x; c < CO; c += blockDim.x) {
        float s = 0.f, q2 = 0.f;
        #pragma unroll
        for (int w = 0; w < 8; w++) { s += red_s[w][c]; q2 += red_q[w][c]; }
        bnpart[blockIdx.x * 2 * CO + c]      = s;
        bnpart[blockIdx.x * 2 * CO + CO + c] = q2;
    }
}

// ---------------- BN finalize (redundant per block) + apply + subsample ------
template<int CO>
__global__ void bn_apply_fused(const float* __restrict__ in,
    const float* __restrict__ bnpart, int nparts,
    const float* __restrict__ gamma, const float* __restrict__ beta,
    float* __restrict__ out, int H, int W, int Hs, int Ws, int totalOut, float invN)
{
    __shared__ float ssc[CO], ssh[CO];
    for (int c = threadIdx.x; c < CO; c += blockDim.x) {
        float s = 0.f, q = 0.f;
        for (int g = 0; g < nparts; g++) {
            s += bnpart[g * 2 * CO + c];
            q += bnpart[g * 2 * CO + CO + c];
        }
        float mean = s * invN;
        float var  = q * invN - mean * mean;
        float sc = gamma[c] * rsqrtf(var + 1e-5f);
        ssc[c] = sc;
        ssh[c] = beta[c] - mean * sc;
    }
    __syncthreads();
    for (int idx = blockIdx.x * blockDim.x + threadIdx.x; idx < totalOut;
         idx += gridDim.x * blockDim.x) {
        int c = idx & (CO - 1); int pix = idx / CO;
        int ws = pix % Ws; int t = pix / Ws;
        int hs = t % Hs;   int b = t / Hs;
        float v = in[((b * H + hs * 2) * W + ws * 2) * CO + c];
        float y = fmaf(v, ssc[c], ssh[c]);
        out[idx] = y > 0.f ? y : 0.f;
    }
}

// ---------------- stage-2 BN finalize + apply + AvgPool(1,56) -> d_out -------
__global__ void bn_avg_final(const float* __restrict__ in,
    const float* __restrict__ bnpart, int nparts,
    const float* __restrict__ gamma, const float* __restrict__ beta,
    float* __restrict__ out)
{
    __shared__ float ssc[16], ssh[16];
    for (int c = threadIdx.x; c < 16; c += blockDim.x) {
        float s = 0.f, q = 0.f;
        for (int g = 0; g < nparts; g++) {
            s += bnpart[g * 32 + c];
            q += bnpart[g * 32 + 16 + c];
        }
        float mean = s * (1.f / 1500.f);
        float var  = q * (1.f / 1500.f) - mean * mean;
        float sc = gamma[c] * rsqrtf(var + 1e-5f);
        ssc[c] = sc;
        ssh[c] = beta[c] - mean * sc;
    }
    __syncthreads();
    int gw = (blockIdx.x * blockDim.x + threadIdx.x) >> 5;
    int lane = threadIdx.x & 31;
    if (gw >= 416) return;
    int nw = gw % 13; int t = gw / 13;
    int c = t % 16;   int b = t / 16;
    float sc = ssc[c], sh_ = ssh[c];
    float s = 0.f;
    int base = b * 750 + nw * 56;
    #pragma unroll
    for (int j0 = 0; j0 < 56; j0 += 32) {
        int j = j0 + lane;
        if (j < 56) {
            float v = in[(base + j) * 16 + c];
            float y = fmaf(v, sc, sh_);
            s += (y > 0.f ? y : 0.f);
        }
    }
    #pragma unroll
    for (int off = 16; off > 0; off >>= 1)
        s += __shfl_xor_sync(0xffffffffu, s, off);
    if (lane == 0) out[(b * 16 + c) * 13 + nw] = s * (1.f / 56.f);
}

// ---------------- launch (9 nodes) -------------------------------------------
extern "C" void kernel_launch(void* const* d_in, const int* in_sizes, int n_in,
                              void* d_out, int out_size)
{
    const float* x = (const float*)d_in[0];
    const float* p[24];
    for (int i = 0; i < 24; i++) p[i] = (const float*)d_in[1 + i];

    float *att0, *bn0, *kpad1, *vpad1, *q1, *att1, *bn1;
    float *kpad2, *vpad2, *q2, *att2;
    float *emb, *prep0, *bnpart;
    cudaGetSymbolAddress((void**)&att0,  d_att0);
    cudaGetSymbolAddress((void**)&bn0,   d_bn0);
    cudaGetSymbolAddress((void**)&kpad1, d_kpad1);
    cudaGetSymbolAddress((void**)&vpad1, d_vpad1);
    cudaGetSymbolAddress((void**)&q1,    d_q1);
    cudaGetSymbolAddress((void**)&att1,  d_att1);
    cudaGetSymbolAddress((void**)&bn1,   d_bn1);
    cudaGetSymbolAddress((void**)&kpad2, d_kpad2);
    cudaGetSymbolAddress((void**)&vpad2, d_vpad2);
    cudaGetSymbolAddress((void**)&q2,    d_q2);
    cudaGetSymbolAddress((void**)&att2,  d_att2);
    cudaGetSymbolAddress((void**)&emb,   d_emb);
    cudaGetSymbolAddress((void**)&prep0, d_prep0);
    cudaGetSymbolAddress((void**)&bnpart, d_bnpart);

    // 1) setup: all embeddings + stage-0 prep
    setup_kernel<<<1, 128>>>(p[3], p[4], p[5], p[11], p[12], p[13],
                             p[19], p[20], p[21], p[0], p[1], p[2], emb, prep0);

    // 2) stage-0 fused attention + stats   3) BN apply + subsample
    att0_kernel<<<NBLK, 256>>>(x, prep0, att0, bnpart);
    bn_apply_fused<64><<<NBLK, 256>>>(att0, bnpart, NBLK, p[6], p[7], bn0,
                                      8, 3000, 4, 1500, 2 * 4 * 1500 * 64,
                                      1.f / 48000.f);

    // 4) stage-1 projection as GEMM (profiled slot)
    {
        dim3 g1(188, 6);
        gemm_proj1<<<g1, 256>>>(bn0, p[8], p[9], p[10], q1, kpad1, vpad1,
                                18048 * 128);
        // 5) stage-1 attention + stats   6) BN apply + subsample
        att_stats_kernel<2, 5, 128><<<NBLK, 256>>>(q1, kpad1, vpad1, emb + 40,
            att1, 6, 1504, 4, 1500, 2 * 4 * 1500, 18048 * 128, bnpart);
        bn_apply_fused<128><<<NBLK, 256>>>(att1, bnpart, NBLK, p[14], p[15], bn1,
                                           4, 1500, 2, 750, 2 * 2 * 750 * 128,
                                           1.f / 12000.f);
    }

    // 7) stage-2 projection  8) attention + stats  9) BN + avgpool -> out
    {
        int tp = 2 * 2 * 754;
        proj_kernel<<<(tp + PIX - 1) / PIX, 32>>>(bn1, p[16], p[17], p[18],
            kpad2, vpad2, q2, 2, 128, 2, 750, 16, 2, 754, 1, 750, 0, 2);
        att_stats_kernel<2, 5, 16><<<NBLK, 256>>>(q2, kpad2, vpad2, emb + 80,
            att2, 2, 754, 1, 750, 2 * 1 * 750, tp * 16, bnpart);
        bn_avg_final<<<52, 256>>>(att2, bnpart, NBLK, p[22], p[23], (float*)d_out);
    }
}

// round 8
// speedup vs baseline: 2.3234x; 1.0687x over previous
#include <cuda_runtime.h>
#include <math.h>

#define MMIX 4
#define PIX 8
#define NBLK 296   // fixed grid for att/apply kernels (2 waves on 148 SMs)

// ---------------- scratch (static __device__, no allocation) ----------------
__device__ float d_att0[3072000];
__device__ float d_bn0[768000];

__device__ float d_kpad1[2310144];
__device__ float d_vpad1[9240576];
__device__ float d_q1[1536000];
__device__ float d_att1[1536000];
__device__ float d_bn1[384000];

__device__ float d_kpad2[48256];
__device__ float d_vpad2[193024];
__device__ float d_q2[24000];
__device__ float d_att2[24000];

__device__ float d_emb[120];              // 3 stages x (M*K <= 40)
__device__ float d_prep0[321];            // [0]=qw.kw ; [1..320]=E[5][64]
__device__ float d_bnpart[NBLK * 256];    // per-block partials (2*Co <= 256)

// ---------------- device helper: one mixture-softmax tap ---------------------
__device__ void emb_tap(const float* __restrict__ ea, const float* __restrict__ eb,
                        const float* __restrict__ em, float* __restrict__ emb_out,
                        int Co, int kh, int kw_, int t)
{
    int K = kh * kw_;
    int i = t / kw_, j = t % kw_;
    float logits[MMIX];
    #pragma unroll
    for (int m = 0; m < MMIX; m++) {
        float la = 0.f, lb = 0.f;
        for (int c = 0; c < Co; c++) {
            float e = em[m * Co + c];
            la += e * ea[c * kh + i];
            lb += e * eb[c * kw_ + j];
        }
        logits[m] = la + lb;
    }
    float mx = logits[0];
    #pragma unroll
    for (int m = 1; m < MMIX; m++) mx = fmaxf(mx, logits[m]);
    float sum = 0.f;
    #pragma unroll
    for (int m = 0; m < MMIX; m++) { logits[m] = expf(logits[m] - mx); sum += logits[m]; }
    float inv = 1.f / sum;
    #pragma unroll
    for (int m = 0; m < MMIX; m++) emb_out[m * K + t] = logits[m] * inv;
}

// ---------------- setup: all 3 stage embeddings + stage-0 prep (1 launch) ----
__global__ void setup_kernel(
    const float* __restrict__ ea0, const float* __restrict__ eb0, const float* __restrict__ em0,
    const float* __restrict__ ea1, const float* __restrict__ eb1, const float* __restrict__ em1,
    const float* __restrict__ ea2, const float* __restrict__ eb2, const float* __restrict__ em2,
    const float* __restrict__ qw0, const float* __restrict__ kw0, const float* __restrict__ vw0,
    float* __restrict__ emb, float* __restrict__ prep)
{
    int t = threadIdx.x;  // 128 threads
    if (t < 5)                 emb_tap(ea0, eb0, em0, emb + 0,  64,  1, 5, t);
    else if (t >= 32 && t < 42) emb_tap(ea1, eb1, em1, emb + 40, 128, 2, 5, t - 32);
    else if (t >= 64 && t < 74) emb_tap(ea2, eb2, em2, emb + 80, 16,  2, 5, t - 64);
    __syncthreads();   // emb0 visible (same block, global mem)

    __shared__ float sh[64];
    if (t < 64) sh[t] = qw0[t] * kw0[t];
    __syncthreads();
    if (t == 0) {
        float s = 0.f;
        for (int i = 0; i < 64; i++) s += sh[i];
        prep[0] = s;
    }
    if (t < 64) {
        #pragma unroll
        for (int j = 0; j < 5; j++) {
            float e = 0.f;
            #pragma unroll
            for (int m = 0; m < MMIX; m++) e += emb[m * 5 + j] * vw0[m * 64 + t];
            prep[1 + j * 64 + t] = e;
        }
    }
}

// ---------------- stage-0 fused attention + BN stats (Cin=1 collapse) --------
__global__ void att0_kernel(const float* __restrict__ x, const float* __restrict__ prep,
                            float* __restrict__ out, float* __restrict__ bnpart)
{
    __shared__ float sE[5 * 64];
    __shared__ float red_s[8][64], red_q[8][64];
    for (int e = threadIdx.x; e < 320; e += blockDim.x) sE[e] = prep[1 + e];
    __syncthreads();

    int wid = threadIdx.x >> 5, lane = threadIdx.x & 31;
    int warp0 = blockIdx.x * 8 + wid, wstride = gridDim.x * 8;
    float c0 = prep[0];

    float s0 = 0.f, s1 = 0.f, q0 = 0.f, q1 = 0.f;
    for (int gw = warp0; gw < 48000; gw += wstride) {
        int wo = gw % 3000;
        int rowbase = (gw / 3000) * 3000;

        float xs[5];
        #pragma unroll
        for (int j = 0; j < 5; j++) {
            int w = wo - 2 + j;
            xs[j] = (w >= 0 && w < 3000) ? x[rowbase + w] : 0.f;
        }
        float cx = c0 * xs[2];
        float sc[5]; float mx = -1e30f;
        #pragma unroll
        for (int j = 0; j < 5; j++) { sc[j] = cx * xs[j]; mx = fmaxf(mx, sc[j]); }
        float sum = 0.f;
        #pragma unroll
        for (int j = 0; j < 5; j++) { sc[j] = expf(sc[j] - mx); sum += sc[j]; }
        float inv = 1.f / sum;
        float wj[5];
        #pragma unroll
        for (int j = 0; j < 5; j++) wj[j] = sc[j] * inv * xs[j];

        float a0 = 0.f, a1 = 0.f;
        #pragma unroll
        for (int j = 0; j < 5; j++) {
            a0 = fmaf(wj[j], sE[j * 64 + lane], a0);
            a1 = fmaf(wj[j], sE[j * 64 + 32 + lane], a1);
        }
        int ob = gw * 64;
        out[ob + lane] = a0;
        out[ob + 32 + lane] = a1;
        s0 += a0; q0 = fmaf(a0, a0, q0);
        s1 += a1; q1 = fmaf(a1, a1, q1);
    }
    red_s[wid][lane] = s0; red_s[wid][32 + lane] = s1;
    red_q[wid][lane] = q0; red_q[wid][32 + lane] = q1;
    __syncthreads();
    for (int c = threadIdx.x; c < 64; c += blockDim.x) {
        float s = 0.f, q = 0.f;
        #pragma unroll
        for (int w = 0; w < 8; w++) { s += red_s[w][c]; q += red_q[w][c]; }
        bnpart[blockIdx.x * 128 + c]      = s;
        bnpart[blockIdx.x * 128 + 64 + c] = q;
    }
}

// ---------------- stage-1 projection as smem-tiled GEMM ----------------------
// C[12000x768] = X[12000x64] * W[64x768]; grid.y selects stream (0:q 1:k 2..5:v)
// Mtile=64, Ntile=128, 128 threads, thread = 8x8 register tile.
// Per k-step: 8 broadcast scalar LDS + 2 LDS.128 per 64 FFMA.
__global__ void gemm_proj1(const float* __restrict__ xin,
    const float* __restrict__ qw, const float* __restrict__ kw_,
    const float* __restrict__ vw,
    float* __restrict__ qout, float* __restrict__ kpad, float* __restrict__ vpad,
    int vstride)
{
    __shared__ float xs[64][64];     // [pix][ci]  16KB
    __shared__ float ws[64][128];    // [ci][co]   32KB

    int s = blockIdx.y;
    const float* wsrc = (s == 0) ? qw : (s == 1) ? kw_ : vw + (s - 2) * 64 * 128;
    int tid = threadIdx.x;           // 128
    int m0 = blockIdx.x * 64;

    // weights: 2048 float4, direct copy (16 per thread)
    {
        const float4* src = (const float4*)wsrc;
        float4* dst = (float4*)&ws[0][0];
        #pragma unroll
        for (int i = 0; i < 16; i++) dst[tid + 128 * i] = src[tid + 128 * i];
    }
    // x tile: 1024 float4 (8 per thread), row = idx/16
    {
        float4* dst = (float4*)&xs[0][0];
        #pragma unroll
        for (int i = 0; i < 8; i++) {
            int idx = tid + 128 * i;
            int pix = m0 + (idx >> 4);
            dst[idx] = (pix < 12000) ? ((const float4*)xin)[pix * 16 + (idx & 15)]
                                     : make_float4(0.f, 0.f, 0.f, 0.f);
        }
    }
    __syncthreads();

    int ty = tid >> 4, tx = tid & 15;   // ty 0..7, tx 0..15
    int mr = ty * 8, nc = tx * 8;

    float acc[8][8];
    #pragma unroll
    for (int i = 0; i < 8; i++)
        #pragma unroll
        for (int j = 0; j < 8; j++) acc[i][j] = 0.f;

    #pragma unroll 8
    for (int k = 0; k < 64; k++) {
        float av[8];
        #pragma unroll
        for (int i = 0; i < 8; i++) av[i] = xs[mr + i][k];
        float4 b0 = *(const float4*)&ws[k][nc];
        float4 b1 = *(const float4*)&ws[k][nc + 4];
        float bv[8] = {b0.x, b0.y, b0.z, b0.w, b1.x, b1.y, b1.z, b1.w};
        #pragma unroll
        for (int i = 0; i < 8; i++)
            #pragma unroll
            for (int j = 0; j < 8; j++)
                acc[i][j] = fmaf(av[i], bv[j], acc[i][j]);
    }

    #pragma unroll
    for (int i = 0; i < 8; i++) {
        int pix = m0 + mr + i;
        if (pix >= 12000) continue;
        float* dst; int base;
        if (s == 0) {
            dst = qout; base = pix * 128 + nc;
        } else {
            int b = pix / 6000, rem = pix % 6000;
            int h = rem / 1500, w = rem % 1500;
            int padpix = (b * 6 + h + 1) * 1504 + (w + 2);   // pt=1, pl=2
            base = padpix * 128 + nc;
            dst = (s == 1) ? kpad : vpad + (s - 2) * vstride;
        }
        *(float4*)&dst[base]     = make_float4(acc[i][0], acc[i][1], acc[i][2], acc[i][3]);
        *(float4*)&dst[base + 4] = make_float4(acc[i][4], acc[i][5], acc[i][6], acc[i][7]);
    }
}

// ---------------- stage-2 projection (small; SIMT per-pixel) -----------------
__global__ void proj_kernel(const float* __restrict__ x,
    const float* __restrict__ qw, const float* __restrict__ kw_,
    const float* __restrict__ vw,
    float* __restrict__ kpad, float* __restrict__ vpad, float* __restrict__ qout,
    int B, int Cin, int H, int W, int Co,
    int Hp, int Wp, int Hout, int Wout, int pt, int pl)
{
    int co = threadIdx.x;
    int g0 = blockIdx.x * PIX;
    int totalPix = B * Hp * Wp;

    int xbase[PIX]; int hh[PIX], ww[PIX], bb[PIX];
    bool valid[PIX], inq[PIX];
    #pragma unroll
    for (int p = 0; p < PIX; p++) {
        int pix = g0 + p;
        valid[p] = false; inq[p] = false;
        xbase[p] = 0; hh[p] = 0; ww[p] = 0; bb[p] = 0;
        if (pix < totalPix) {
            int wp = pix % Wp; int t = pix / Wp;
            int hp = t % Hp;  int b = t / Hp;
            int h = hp - pt, w = wp - pl;
            if (h >= 0 && h < H && w >= 0 && w < W) {
                valid[p] = true;
                xbase[p] = ((b * H + h) * W + w) * Cin;
                inq[p] = (h < Hout) && (w < Wout);
                hh[p] = h; ww[p] = w; bb[p] = b;
            }
        }
    }
    if (co >= Co) return;

    float ak[PIX], aq[PIX], av0[PIX], av1[PIX], av2[PIX], av3[PIX];
    #pragma unroll
    for (int p = 0; p < PIX; p++) { ak[p]=0.f; aq[p]=0.f; av0[p]=0.f; av1[p]=0.f; av2[p]=0.f; av3[p]=0.f; }

    int CinCo = Cin * Co;
    for (int ci = 0; ci < Cin; ci++) {
        float wq  = qw [ci * Co + co];
        float wk  = kw_[ci * Co + co];
        float wv0 = vw [ci * Co + co];
        float wv1 = vw [CinCo     + ci * Co + co];
        float wv2 = vw [2 * CinCo + ci * Co + co];
        float wv3 = vw [3 * CinCo + ci * Co + co];
        #pragma unroll
        for (int p = 0; p < PIX; p++) {
            if (valid[p]) {
                float xv = x[xbase[p] + ci];
                aq[p]  = fmaf(xv, wq,  aq[p]);
                ak[p]  = fmaf(xv, wk,  ak[p]);
                av0[p] = fmaf(xv, wv0, av0[p]);
                av1[p] = fmaf(xv, wv1, av1[p]);
                av2[p] = fmaf(xv, wv2, av2[p]);
                av3[p] = fmaf(xv, wv3, av3[p]);
            }
        }
    }

    int vstride = totalPix * Co;
    #pragma unroll
    for (int p = 0; p < PIX; p++) {
        int pix = g0 + p;
        if (pix < totalPix) {
            int off = pix * Co + co;
            kpad[off] = ak[p];
            vpad[off] = av0[p];
            vpad[vstride + off] = av1[p];
            vpad[2 * vstride + off] = av2[p];
            vpad[3 * vstride + off] = av3[p];
            if (inq[p])
                qout[((bb[p] * Hout + hh[p]) * Wout + ww[p]) * Co + co] = aq[p];
        }
    }
}

// ---------------- attention + fused BN stats: warp per pixel, grid-stride ----
template<int KH, int KW, int CO>
__global__ void att_stats_kernel(const float* __restrict__ q,
    const float* __restrict__ kpad, const float* __restrict__ vpad,
    const float* __restrict__ emb, float* __restrict__ out,
    int Hp, int Wp, int Hout, int Wout, int total, int vstride,
    float* __restrict__ bnpart)
{
    constexpr int K = KH * KW;
    constexpr int CPL = (CO + 31) / 32;
    constexpr int CW = (CO > 32) ? CO : 32;
    __shared__ float s_emb[MMIX * K];
    __shared__ float red_s[8][CW], red_q[8][CW];
    for (int e = threadIdx.x; e < MMIX * K; e += blockDim.x) s_emb[e] = emb[e];
    __syncthreads();

    int wid = threadIdx.x >> 5, lane = threadIdx.x & 31;
    int warp0 = blockIdx.x * 8 + wid, wstride = gridDim.x * 8;

    float sacc[CPL], qacc[CPL];
    #pragma unroll
    for (int i = 0; i < CPL; i++) { sacc[i] = 0.f; qacc[i] = 0.f; }

    for (int gw = warp0; gw < total; gw += wstride) {
        int wo = gw % Wout; int t = gw / Wout;
        int ho = t % Hout;  int b = t / Hout;

        int kvbase[K];
        #pragma unroll
        for (int k = 0; k < K; k++) {
            int i = k / KW, j = k % KW;
            kvbase[k] = ((b * Hp + ho + i) * Wp + (wo + j)) * CO;
        }

        float partial[K];
        #pragma unroll
        for (int k = 0; k < K; k++) partial[k] = 0.f;
        int qbase = gw * CO;
        #pragma unroll
        for (int i = 0; i < CPL; i++) {
            int co = lane + 32 * i;
            if (co < CO) {
                float qv = q[qbase + co];
                #pragma unroll
                for (int k = 0; k < K; k++)
                    partial[k] = fmaf(qv, kpad[kvbase[k] + co], partial[k]);
            }
        }
        #pragma unroll
        for (int k = 0; k < K; k++) {
            #pragma unroll
            for (int off = 16; off > 0; off >>= 1)
                partial[k] += __shfl_xor_sync(0xffffffffu, partial[k], off);
        }

        float mx = partial[0];
        #pragma unroll
        for (int k = 1; k < K; k++) mx = fmaxf(mx, partial[k]);
        float sum = 0.f;
        float aw[K];
        #pragma unroll
        for (int k = 0; k < K; k++) { aw[k] = expf(partial[k] - mx); sum += aw[k]; }
        float inv = 1.f / sum;

        float wkm[MMIX][K];
        #pragma unroll
        for (int m = 0; m < MMIX; m++)
            #pragma unroll
            for (int k = 0; k < K; k++)
                wkm[m][k] = aw[k] * inv * s_emb[m * K + k];

        #pragma unroll
        for (int i = 0; i < CPL; i++) {
            int co = lane + 32 * i;
            if (co < CO) {
                float a0 = 0.f, a1 = 0.f, a2 = 0.f, a3 = 0.f;
                #pragma unroll
                for (int k = 0; k < K; k++) {
                    int off = kvbase[k] + co;
                    a0 = fmaf(wkm[0][k], vpad[off], a0);
                    a1 = fmaf(wkm[1][k], vpad[vstride + off], a1);
                    a2 = fmaf(wkm[2][k], vpad[2 * vstride + off], a2);
                    a3 = fmaf(wkm[3][k], vpad[3 * vstride + off], a3);
                }
                float acc = (a0 + a1) + (a2 + a3);
                out[qbase + co] = acc;
                sacc[i] += acc;
                qacc[i] = fmaf(acc, acc, qacc[i]);
            }
        }
    }

    #pragma unroll
    for (int i = 0; i < CPL; i++) {
        int c = lane + 32 * i;
        if (c < CO) { red_s[wid][c] = sacc[i]; red_q[wid][c] = qacc[i]; }
    }
    __syncthreads();
    for (int c = threadIdx.x; c < CO; c += blockDim.x) {
        float s = 0.f, q2 = 0.f;
        #pragma unroll
        for (int w = 0; w < 8; w++) { s += red_s[w][c]; q2 += red_q[w][c]; }
        bnpart[blockIdx.x * 2 * CO + c]      = s;
        bnpart[blockIdx.x * 2 * CO + CO + c] = q2;
    }
}

// ---------------- BN finalize (redundant per block) + apply + subsample ------
template<int CO>
__global__ void bn_apply_fused(const float* __restrict__ in,
    const float* __restrict__ bnpart, int nparts,
    const float* __restrict__ gamma, const float* __restrict__ beta,
    float* __restrict__ out, int H, int W, int Hs, int Ws, int totalOut, float invN)
{
    __shared__ float ssc[CO], ssh[CO];
    for (int c = threadIdx.x; c < CO; c += blockDim.x) {
        float s = 0.f, q = 0.f;
        for (int g = 0; g < nparts; g++) {
            s += bnpart[g * 2 * CO + c];
            q += bnpart[g * 2 * CO + CO + c];
        }
        float mean = s * invN;
        float var  = q * invN - mean * mean;
        float sc = gamma[c] * rsqrtf(var + 1e-5f);
        ssc[c] = sc;
        ssh[c] = beta[c] - mean * sc;
    }
    __syncthreads();
    for (int idx = blockIdx.x * blockDim.x + threadIdx.x; idx < totalOut;
         idx += gridDim.x * blockDim.x) {
        int c = idx & (CO - 1); int pix = idx / CO;
        int ws = pix % Ws; int t = pix / Ws;
        int hs = t % Hs;   int b = t / Hs;
        float v = in[((b * H + hs * 2) * W + ws * 2) * CO + c];
        float y = fmaf(v, ssc[c], ssh[c]);
        out[idx] = y > 0.f ? y : 0.f;
    }
}

// ---------------- stage-2 BN finalize + apply + AvgPool(1,56) -> d_out -------
__global__ void bn_avg_final(const float* __restrict__ in,
    const float* __restrict__ bnpart, int nparts,
    const float* __restrict__ gamma, const float* __restrict__ beta,
    float* __restrict__ out)
{
    __shared__ float ssc[16], ssh[16];
    for (int c = threadIdx.x; c < 16; c += blockDim.x) {
        float s = 0.f, q = 0.f;
        for (int g = 0; g < nparts; g++) {
            s += bnpart[g * 32 + c];
            q += bnpart[g * 32 + 16 + c];
        }
        float mean = s * (1.f / 1500.f);
        float var  = q * (1.f / 1500.f) - mean * mean;
        float sc = gamma[c] * rsqrtf(var + 1e-5f);
        ssc[c] = sc;
        ssh[c] = beta[c] - mean * sc;
    }
    __syncthreads();
    int gw = (blockIdx.x * blockDim.x + threadIdx.x) >> 5;
    int lane = threadIdx.x & 31;
    if (gw >= 416) return;
    int nw = gw % 13; int t = gw / 13;
    int c = t % 16;   int b = t / 16;
    float sc = ssc[c], sh_ = ssh[c];
    float s = 0.f;
    int base = b * 750 + nw * 56;
    #pragma unroll
    for (int j0 = 0; j0 < 56; j0 += 32) {
        int j = j0 + lane;
        if (j < 56) {
            float v = in[(base + j) * 16 + c];
            float y = fmaf(v, sc, sh_);
            s += (y > 0.f ? y : 0.f);
        }
    }
    #pragma unroll
    for (int off = 16; off > 0; off >>= 1)
        s += __shfl_xor_sync(0xffffffffu, s, off);
    if (lane == 0) out[(b * 16 + c) * 13 + nw] = s * (1.f / 56.f);
}

// ---------------- launch (9 nodes) -------------------------------------------
extern "C" void kernel_launch(void* const* d_in, const int* in_sizes, int n_in,
                              void* d_out, int out_size)
{
    const float* x = (const float*)d_in[0];
    const float* p[24];
    for (int i = 0; i < 24; i++) p[i] = (const float*)d_in[1 + i];

    float *att0, *bn0, *kpad1, *vpad1, *q1, *att1, *bn1;
    float *kpad2, *vpad2, *q2, *att2;
    float *emb, *prep0, *bnpart;
    cudaGetSymbolAddress((void**)&att0,  d_att0);
    cudaGetSymbolAddress((void**)&bn0,   d_bn0);
    cudaGetSymbolAddress((void**)&kpad1, d_kpad1);
    cudaGetSymbolAddress((void**)&vpad1, d_vpad1);
    cudaGetSymbolAddress((void**)&q1,    d_q1);
    cudaGetSymbolAddress((void**)&att1,  d_att1);
    cudaGetSymbolAddress((void**)&bn1,   d_bn1);
    cudaGetSymbolAddress((void**)&kpad2, d_kpad2);
    cudaGetSymbolAddress((void**)&vpad2, d_vpad2);
    cudaGetSymbolAddress((void**)&q2,    d_q2);
    cudaGetSymbolAddress((void**)&att2,  d_att2);
    cudaGetSymbolAddress((void**)&emb,   d_emb);
    cudaGetSymbolAddress((void**)&prep0, d_prep0);
    cudaGetSymbolAddress((void**)&bnpart, d_bnpart);

    // 1) setup: all embeddings + stage-0 prep
    setup_kernel<<<1, 128>>>(p[3], p[4], p[5], p[11], p[12], p[13],
                             p[19], p[20], p[21], p[0], p[1], p[2], emb, prep0);

    // 2) stage-0 fused attention + stats   3) BN apply + subsample
    att0_kernel<<<NBLK, 256>>>(x, prep0, att0, bnpart);
    bn_apply_fused<64><<<NBLK, 256>>>(att0, bnpart, NBLK, p[6], p[7], bn0,
                                      8, 3000, 4, 1500, 2 * 4 * 1500 * 64,
                                      1.f / 48000.f);

    // 4) stage-1 projection as GEMM (profiled slot)
    {
        dim3 g1(188, 6);
        gemm_proj1<<<g1, 128>>>(bn0, p[8], p[9], p[10], q1, kpad1, vpad1,
                                18048 * 128);
        // 5) stage-1 attention + stats   6) BN apply + subsample
        att_stats_kernel<2, 5, 128><<<NBLK, 256>>>(q1, kpad1, vpad1, emb + 40,
            att1, 6, 1504, 4, 1500, 2 * 4 * 1500, 18048 * 128, bnpart);
        bn_apply_fused<128><<<NBLK, 256>>>(att1, bnpart, NBLK, p[14], p[15], bn1,
                                           4, 1500, 2, 750, 2 * 2 * 750 * 128,
                                           1.f / 12000.f);
    }

    // 7) stage-2 projection  8) attention + stats  9) BN + avgpool -> out
    {
        int tp = 2 * 2 * 754;
        proj_kernel<<<(tp + PIX - 1) / PIX, 32>>>(bn1, p[16], p[17], p[18],
            kpad2, vpad2, q2, 2, 128, 2, 750, 16, 2, 754, 1, 750, 0, 2);
        att_stats_kernel<2, 5, 16><<<NBLK, 256>>>(q2, kpad2, vpad2, emb + 80,
            att2, 2, 754, 1, 750, 2 * 1 * 750, tp * 16, bnpart);
        bn_avg_final<<<52, 256>>>(att2, bnpart, NBLK, p[22], p[23], (float*)d_out);
    }
}

// round 10
// speedup vs baseline: 3.2434x; 1.3960x over previous
#include <cuda_runtime.h>
#include <math.h>

#define MMIX 4
#define NBLK 296   // fixed grid for att/apply kernels (2 waves on 148 SMs)

// ---------------- scratch (static __device__, no allocation) ----------------
__device__ float d_att0[3072000];
__device__ float d_bn0[768000];

__device__ float d_kpad1[2310144];
__device__ float d_vpad1[9240576];
__device__ float d_q1[1536000];
__device__ float d_att1[1536000];
__device__ float d_bn1[384000];

__device__ float d_kpad2[48256];
__device__ float d_vpad2[193024];
__device__ float d_q2[24000];
__device__ float d_att2[24000];

__device__ float d_emb[120];              // 3 stages x (M*K <= 40)
__device__ float d_prep0[321];            // [0]=qw.kw ; [1..320]=E[5][64]
__device__ float d_bnpart[NBLK * 256];    // per-block partials (2*Co <= 256)

// ---------------- device helper: one mixture-softmax tap ---------------------
__device__ void emb_tap(const float* __restrict__ ea, const float* __restrict__ eb,
                        const float* __restrict__ em, float* __restrict__ emb_out,
                        int Co, int kh, int kw_, int t)
{
    int K = kh * kw_;
    int i = t / kw_, j = t % kw_;
    float logits[MMIX];
    #pragma unroll
    for (int m = 0; m < MMIX; m++) {
        float la = 0.f, lb = 0.f;
        for (int c = 0; c < Co; c++) {
            float e = em[m * Co + c];
            la += e * ea[c * kh + i];
            lb += e * eb[c * kw_ + j];
        }
        logits[m] = la + lb;
    }
    float mx = logits[0];
    #pragma unroll
    for (int m = 1; m < MMIX; m++) mx = fmaxf(mx, logits[m]);
    float sum = 0.f;
    #pragma unroll
    for (int m = 0; m < MMIX; m++) { logits[m] = expf(logits[m] - mx); sum += logits[m]; }
    float inv = 1.f / sum;
    #pragma unroll
    for (int m = 0; m < MMIX; m++) emb_out[m * K + t] = logits[m] * inv;
}

// ---------------- setup: all 3 stage embeddings + stage-0 prep (1 launch) ----
__global__ void setup_kernel(
    const float* __restrict__ ea0, const float* __restrict__ eb0, const float* __restrict__ em0,
    const float* __restrict__ ea1, const float* __restrict__ eb1, const float* __restrict__ em1,
    const float* __restrict__ ea2, const float* __restrict__ eb2, const float* __restrict__ em2,
    const float* __restrict__ qw0, const float* __restrict__ kw0, const float* __restrict__ vw0,
    float* __restrict__ emb, float* __restrict__ prep)
{
    int t = threadIdx.x;  // 128 threads
    if (t < 5)                 emb_tap(ea0, eb0, em0, emb + 0,  64,  1, 5, t);
    else if (t >= 32 && t < 42) emb_tap(ea1, eb1, em1, emb + 40, 128, 2, 5, t - 32);
    else if (t >= 64 && t < 74) emb_tap(ea2, eb2, em2, emb + 80, 16,  2, 5, t - 64);
    __syncthreads();   // emb0 visible (same block, global mem)

    __shared__ float sh[64];
    if (t < 64) sh[t] = qw0[t] * kw0[t];
    __syncthreads();
    if (t == 0) {
        float s = 0.f;
        for (int i = 0; i < 64; i++) s += sh[i];
        prep[0] = s;
    }
    if (t < 64) {
        #pragma unroll
        for (int j = 0; j < 5; j++) {
            float e = 0.f;
            #pragma unroll
            for (int m = 0; m < MMIX; m++) e += emb[m * 5 + j] * vw0[m * 64 + t];
            prep[1 + j * 64 + t] = e;
        }
    }
}

// ---------------- stage-0 fused attention + BN stats (Cin=1 collapse) --------
__global__ void att0_kernel(const float* __restrict__ x, const float* __restrict__ prep,
                            float* __restrict__ out, float* __restrict__ bnpart)
{
    __shared__ float sE[5 * 64];
    __shared__ float red_s[8][64], red_q[8][64];
    for (int e = threadIdx.x; e < 320; e += blockDim.x) sE[e] = prep[1 + e];
    __syncthreads();

    int wid = threadIdx.x >> 5, lane = threadIdx.x & 31;
    int warp0 = blockIdx.x * 8 + wid, wstride = gridDim.x * 8;
    float c0 = prep[0];

    float s0 = 0.f, s1 = 0.f, q0 = 0.f, q1 = 0.f;
    for (int gw = warp0; gw < 48000; gw += wstride) {
        int wo = gw % 3000;
        int rowbase = (gw / 3000) * 3000;

        float xs[5];
        #pragma unroll
        for (int j = 0; j < 5; j++) {
            int w = wo - 2 + j;
            xs[j] = (w >= 0 && w < 3000) ? x[rowbase + w] : 0.f;
        }
        float cx = c0 * xs[2];
        float sc[5]; float mx = -1e30f;
        #pragma unroll
        for (int j = 0; j < 5; j++) { sc[j] = cx * xs[j]; mx = fmaxf(mx, sc[j]); }
        float sum = 0.f;
        #pragma unroll
        for (int j = 0; j < 5; j++) { sc[j] = expf(sc[j] - mx); sum += sc[j]; }
        float inv = 1.f / sum;
        float wj[5];
        #pragma unroll
        for (int j = 0; j < 5; j++) wj[j] = sc[j] * inv * xs[j];

        float a0 = 0.f, a1 = 0.f;
        #pragma unroll
        for (int j = 0; j < 5; j++) {
            a0 = fmaf(wj[j], sE[j * 64 + lane], a0);
            a1 = fmaf(wj[j], sE[j * 64 + 32 + lane], a1);
        }
        int ob = gw * 64;
        out[ob + lane] = a0;
        out[ob + 32 + lane] = a1;
        s0 += a0; q0 = fmaf(a0, a0, q0);
        s1 += a1; q1 = fmaf(a1, a1, q1);
    }
    red_s[wid][lane] = s0; red_s[wid][32 + lane] = s1;
    red_q[wid][lane] = q0; red_q[wid][32 + lane] = q1;
    __syncthreads();
    for (int c = threadIdx.x; c < 64; c += blockDim.x) {
        float s = 0.f, q = 0.f;
        #pragma unroll
        for (int w = 0; w < 8; w++) { s += red_s[w][c]; q += red_q[w][c]; }
        bnpart[blockIdx.x * 128 + c]      = s;
        bnpart[blockIdx.x * 128 + 64 + c] = q;
    }
}

// ---------------- stage-1 projection as smem-tiled GEMM ----------------------
// C[12000x768] = X[12000x64] * W[64x768]; grid.y selects stream (0:q 1:k 2..5:v)
// Mtile=64, Ntile=128, 128 threads, 8x8 register tile, k processed in pairs:
// per 2 k-steps: 8 LDS.64 (a) + 4 LDS.128 (b) per 128 FFMA.
__global__ void __launch_bounds__(128) gemm_proj1(const float* __restrict__ xin,
    const float* __restrict__ qw, const float* __restrict__ kw_,
    const float* __restrict__ vw,
    float* __restrict__ qout, float* __restrict__ kpad, float* __restrict__ vpad,
    int vstride)
{
    __shared__ float xs[64][64];     // [pix][ci]  16KB
    __shared__ float ws[64][128];    // [ci][co]   32KB

    int s = blockIdx.y;
    const float* wsrc = (s == 0) ? qw : (s == 1) ? kw_ : vw + (s - 2) * 64 * 128;
    int tid = threadIdx.x;           // 128
    int m0 = blockIdx.x * 64;

    // weights: 2048 float4, direct copy (16 per thread)
    {
        const float4* src = (const float4*)wsrc;
        float4* dst = (float4*)&ws[0][0];
        #pragma unroll
        for (int i = 0; i < 16; i++) dst[tid + 128 * i] = src[tid + 128 * i];
    }
    // x tile: 1024 float4 (8 per thread), row = idx/16
    {
        float4* dst = (float4*)&xs[0][0];
        #pragma unroll
        for (int i = 0; i < 8; i++) {
            int idx = tid + 128 * i;
            int pix = m0 + (idx >> 4);
            dst[idx] = (pix < 12000) ? ((const float4*)xin)[pix * 16 + (idx & 15)]
                                     : make_float4(0.f, 0.f, 0.f, 0.f);
        }
    }
    __syncthreads();

    int ty = tid >> 4, tx = tid & 15;   // ty 0..7, tx 0..15
    int mr = ty * 8, nc = tx * 8;

    float acc[8][8];
    #pragma unroll
    for (int i = 0; i < 8; i++)
        #pragma unroll
        for (int j = 0; j < 8; j++) acc[i][j] = 0.f;

    #pragma unroll 4
    for (int k = 0; k < 64; k += 2) {
        float2 ax[8];
        #pragma unroll
        for (int i = 0; i < 8; i++) ax[i] = *(const float2*)&xs[mr + i][k];
        float4 b00 = *(const float4*)&ws[k][nc];
        float4 b01 = *(const float4*)&ws[k][nc + 4];
        float4 b10 = *(const float4*)&ws[k + 1][nc];
        float4 b11 = *(const float4*)&ws[k + 1][nc + 4];
        float bv0[8] = {b00.x, b00.y, b00.z, b00.w, b01.x, b01.y, b01.z, b01.w};
        float bv1[8] = {b10.x, b10.y, b10.z, b10.w, b11.x, b11.y, b11.z, b11.w};
        #pragma unroll
        for (int i = 0; i < 8; i++) {
            #pragma unroll
            for (int j = 0; j < 8; j++) {
                acc[i][j] = fmaf(ax[i].x, bv0[j], acc[i][j]);
                acc[i][j] = fmaf(ax[i].y, bv1[j], acc[i][j]);
            }
        }
    }

    #pragma unroll
    for (int i = 0; i < 8; i++) {
        int pix = m0 + mr + i;
        if (pix >= 12000) continue;
        float* dst; int base;
        if (s == 0) {
            dst = qout; base = pix * 128 + nc;
        } else {
            int b = pix / 6000, rem = pix % 6000;
            int h = rem / 1500, w = rem % 1500;
            int padpix = (b * 6 + h + 1) * 1504 + (w + 2);   // pt=1, pl=2
            base = padpix * 128 + nc;
            dst = (s == 1) ? kpad : vpad + (s - 2) * vstride;
        }
        *(float4*)&dst[base]     = make_float4(acc[i][0], acc[i][1], acc[i][2], acc[i][3]);
        *(float4*)&dst[base + 4] = make_float4(acc[i][4], acc[i][5], acc[i][6], acc[i][7]);
    }
}

// ---------------- stage-2 projection as mini-GEMM ----------------------------
// C[3000x96] = X[3000x128] * W[128x96]; cols 0..15 q, 16..31 k, 32..95 v[m]
// Mtile=32, Ntile=48 (grid.y in {0,1}), 128 threads, thread = 4x3 tile.
// Valid pixels only; padded borders of kpad2/vpad2 stay zero (never written).
__global__ void proj2_gemm(const float* __restrict__ xin,
    const float* __restrict__ qw, const float* __restrict__ kw_,
    const float* __restrict__ vw,
    float* __restrict__ qout, float* __restrict__ kpad, float* __restrict__ vpad)
{
    __shared__ float xs[32][128];   // 16KB
    __shared__ float ws[128][48];   // 24KB
    int tid = threadIdx.x;
    int m0 = blockIdx.x * 32;
    int c0 = blockIdx.y * 48;

    // weights: 1536 float4 (12 per thread); float4 never straddles a stream
    {
        float4* dst = (float4*)&ws[0][0];
        #pragma unroll
        for (int i = 0; i < 12; i++) {
            int idx = tid + 128 * i;
            int ci = idx / 12;
            int c = c0 + (idx % 12) * 4;
            const float* src;
            if (c < 16)      src = qw  + ci * 16 + c;
            else if (c < 32) src = kw_ + ci * 16 + (c - 16);
            else             src = vw + ((c - 32) >> 4) * 2048 + ci * 16 + ((c - 32) & 15);
            dst[idx] = *(const float4*)src;
        }
    }
    // x tile: 1024 float4 (8 per thread)
    {
        float4* dst = (float4*)&xs[0][0];
        #pragma unroll
        for (int i = 0; i < 8; i++) {
            int idx = tid + 128 * i;
            int pix = m0 + (idx >> 5);
            dst[idx] = (pix < 3000) ? ((const float4*)xin)[pix * 32 + (idx & 31)]
                                    : make_float4(0.f, 0.f, 0.f, 0.f);
        }
    }
    __syncthreads();

    int ty = tid >> 4, tx = tid & 15;   // ty 0..7 -> 4 pixels, tx 0..15 -> 3 cols
    int mr = ty * 4, nc = tx * 3;

    float acc[4][3];
    #pragma unroll
    for (int i = 0; i < 4; i++)
        #pragma unroll
        for (int j = 0; j < 3; j++) acc[i][j] = 0.f;

    #pragma unroll 4
    for (int k = 0; k < 128; k += 2) {
        float2 ax[4];
        #pragma unroll
        for (int i = 0; i < 4; i++) ax[i] = *(const float2*)&xs[mr + i][k];
        float bv0[3], bv1[3];
        #pragma unroll
        for (int j = 0; j < 3; j++) { bv0[j] = ws[k][nc + j]; bv1[j] = ws[k + 1][nc + j]; }
        #pragma unroll
        for (int i = 0; i < 4; i++)
            #pragma unroll
            for (int j = 0; j < 3; j++) {
                acc[i][j] = fmaf(ax[i].x, bv0[j], acc[i][j]);
                acc[i][j] = fmaf(ax[i].y, bv1[j], acc[i][j]);
            }
    }

    #pragma unroll
    for (int i = 0; i < 4; i++) {
        int pix = m0 + mr + i;
        if (pix >= 3000) continue;
        int b_ = pix / 1500, rem = pix % 1500;
        int h = rem / 750, w = rem % 750;
        int padbase = ((b_ * 2 + h) * 754 + w + 2) * 16;     // pt=0, pl=2
        #pragma unroll
        for (int j = 0; j < 3; j++) {
            int c = c0 + nc + j;
            float v = acc[i][j];
            if (c < 16) {
                if (h == 0) qout[(b_ * 750 + w) * 16 + c] = v;   // Hout=1
            } else if (c < 32) {
                kpad[padbase + (c - 16)] = v;
            } else {
                vpad[((c - 32) >> 4) * 48256 + padbase + ((c - 32) & 15)] = v;
            }
        }
    }
}

// ---------------- attention + fused BN stats: warp per pixel, grid-stride ----
template<int KH, int KW, int CO>
__global__ void att_stats_kernel(const float* __restrict__ q,
    const float* __restrict__ kpad, const float* __restrict__ vpad,
    const float* __restrict__ emb, float* __restrict__ out,
    int Hp, int Wp, int Hout, int Wout, int total, int vstride,
    float* __restrict__ bnpart)
{
    constexpr int K = KH * KW;
    constexpr int CPL = (CO + 31) / 32;
    constexpr int CW = (CO > 32) ? CO : 32;
    __shared__ float s_emb[MMIX * K];
    __shared__ float red_s[8][CW], red_q[8][CW];
    for (int e = threadIdx.x; e < MMIX * K; e += blockDim.x) s_emb[e] = emb[e];
    __syncthreads();

    int wid = threadIdx.x >> 5, lane = threadIdx.x & 31;
    int warp0 = blockIdx.x * 8 + wid, wstride = gridDim.x * 8;

    float sacc[CPL], qacc[CPL];
    #pragma unroll
    for (int i = 0; i < CPL; i++) { sacc[i] = 0.f; qacc[i] = 0.f; }

    for (int gw = warp0; gw < total; gw += wstride) {
        int wo = gw % Wout; int t = gw / Wout;
        int ho = t % Hout;  int b = t / Hout;

        int kvbase[K];
        #pragma unroll
        for (int k = 0; k < K; k++) {
            int i = k / KW, j = k % KW;
            kvbase[k] = ((b * Hp + ho + i) * Wp + (wo + j)) * CO;
        }

        float partial[K];
        #pragma unroll
        for (int k = 0; k < K; k++) partial[k] = 0.f;
        int qbase = gw * CO;
        #pragma unroll
        for (int i = 0; i < CPL; i++) {
            int co = lane + 32 * i;
            if (co < CO) {
                float qv = q[qbase + co];
                #pragma unroll
                for (int k = 0; k < K; k++)
                    partial[k] = fmaf(qv, kpad[kvbase[k] + co], partial[k]);
            }
        }
        #pragma unroll
        for (int k = 0; k < K; k++) {
            #pragma unroll
            for (int off = 16; off > 0; off >>= 1)
                partial[k] += __shfl_xor_sync(0xffffffffu, partial[k], off);
        }

        float mx = partial[0];
        #pragma unroll
        for (int k = 1; k < K; k++) mx = fmaxf(mx, partial[k]);
        float sum = 0.f;
        float aw[K];
        #pragma unroll
        for (int k = 0; k < K; k++) { aw[k] = expf(partial[k] - mx); sum += aw[k]; }
        float inv = 1.f / sum;

        float wkm[MMIX][K];
        #pragma unroll
        for (int m = 0; m < MMIX; m++)
            #pragma unroll
            for (int k = 0; k < K; k++)
                wkm[m][k] = aw[k] * inv * s_emb[m * K + k];

        #pragma unroll
        for (int i = 0; i < CPL; i++) {
            int co = lane + 32 * i;
            if (co < CO) {
                float a0 = 0.f, a1 = 0.f, a2 = 0.f, a3 = 0.f;
                #pragma unroll
                for (int k = 0; k < K; k++) {
                    int off = kvbase[k] + co;
                    a0 = fmaf(wkm[0][k], vpad[off], a0);
                    a1 = fmaf(wkm[1][k], vpad[vstride + off], a1);
                    a2 = fmaf(wkm[2][k], vpad[2 * vstride + off], a2);
                    a3 = fmaf(wkm[3][k], vpad[3 * vstride + off], a3);
                }
                float acc = (a0 + a1) + (a2 + a3);
                out[qbase + co] = acc;
                sacc[i] += acc;
                qacc[i] = fmaf(acc, acc, qacc[i]);
            }
        }
    }

    #pragma unroll
    for (int i = 0; i < CPL; i++) {
        int c = lane + 32 * i;
        if (c < CO) { red_s[wid][c] = sacc[i]; red_q[wid][c] = qacc[i]; }
    }
    __syncthreads();
    for (int c = threadIdx.x; c < CO; c += blockDim.x) {
        float s = 0.f, q2 = 0.f;
        #pragma unroll
        for (int w = 0; w < 8; w++) { s += red_s[w][c]; q2 += red_q[w][c]; }
        bnpart[blockIdx.x * 2 * CO + c]      = s;
        bnpart[blockIdx.x * 2 * CO + CO + c] = q2;
    }
}

// ---------------- BN finalize (redundant per block) + apply + subsample ------
template<int CO>
__global__ void bn_apply_fused(const float* __restrict__ in,
    const float* __restrict__ bnpart, int nparts,
    const float* __restrict__ gamma, const float* __restrict__ beta,
    float* __restrict__ out, int H, int W, int Hs, int Ws, int totalOut, float invN)
{
    __shared__ float ssc[CO], ssh[CO];
    for (int c = threadIdx.x; c < CO; c += blockDim.x) {
        float s = 0.f, q = 0.f;
        for (int g = 0; g < nparts; g++) {
            s += bnpart[g * 2 * CO + c];
            q += bnpart[g * 2 * CO + CO + c];
        }
        float mean = s * invN;
        float var  = q * invN - mean * mean;
        float sc = gamma[c] * rsqrtf(var + 1e-5f);
        ssc[c] = sc;
        ssh[c] = beta[c] - mean * sc;
    }
    __syncthreads();
    for (int idx = blockIdx.x * blockDim.x + threadIdx.x; idx < totalOut;
         idx += gridDim.x * blockDim.x) {
        int c = idx & (CO - 1); int pix = idx / CO;
        int ws = pix % Ws; int t = pix / Ws;
        int hs = t % Hs;   int b = t / Hs;
        float v = in[((b * H + hs * 2) * W + ws * 2) * CO + c];
        float y = fmaf(v, ssc[c], ssh[c]);
        out[idx] = y > 0.f ? y : 0.f;
    }
}

// ---------------- stage-2 BN finalize + apply + AvgPool(1,56) -> d_out -------
__global__ void bn_avg_final(const float* __restrict__ in,
    const float* __restrict__ bnpart, int nparts,
    const float* __restrict__ gamma, const float* __restrict__ beta,
    float* __restrict__ out)
{
    __shared__ float ssc[16], ssh[16];
    for (int c = threadIdx.x; c < 16; c += blockDim.x) {
        float s = 0.f, q = 0.f;
        for (int g = 0; g < nparts; g++) {
            s += bnpart[g * 32 + c];
            q += bnpart[g * 32 + 16 + c];
        }
        float mean = s * (1.f / 1500.f);
        float var  = q * (1.f / 1500.f) - mean * mean;
        float sc = gamma[c] * rsqrtf(var + 1e-5f);
        ssc[c] = sc;
        ssh[c] = beta[c] - mean * sc;
    }
    __syncthreads();
    int gw = (blockIdx.x * blockDim.x + threadIdx.x) >> 5;
    int lane = threadIdx.x & 31;
    if (gw >= 416) return;
    int nw = gw % 13; int t = gw / 13;
    int c = t % 16;   int b = t / 16;
    float sc = ssc[c], sh_ = ssh[c];
    float s = 0.f;
    int base = b * 750 + nw * 56;
    #pragma unroll
    for (int j0 = 0; j0 < 56; j0 += 32) {
        int j = j0 + lane;
        if (j < 56) {
            float v = in[(base + j) * 16 + c];
            float y = fmaf(v, sc, sh_);
            s += (y > 0.f ? y : 0.f);
        }
    }
    #pragma unroll
    for (int off = 16; off > 0; off >>= 1)
        s += __shfl_xor_sync(0xffffffffu, s, off);
    if (lane == 0) out[(b * 16 + c) * 13 + nw] = s * (1.f / 56.f);
}

// ---------------- launch (9 nodes) -------------------------------------------
extern "C" void kernel_launch(void* const* d_in, const int* in_sizes, int n_in,
                              void* d_out, int out_size)
{
    const float* x = (const float*)d_in[0];
    const float* p[24];
    for (int i = 0; i < 24; i++) p[i] = (const float*)d_in[1 + i];

    float *att0, *bn0, *kpad1, *vpad1, *q1, *att1, *bn1;
    float *kpad2, *vpad2, *q2, *att2;
    float *emb, *prep0, *bnpart;
    cudaGetSymbolAddress((void**)&att0,  d_att0);
    cudaGetSymbolAddress((void**)&bn0,   d_bn0);
    cudaGetSymbolAddress((void**)&kpad1, d_kpad1);
    cudaGetSymbolAddress((void**)&vpad1, d_vpad1);
    cudaGetSymbolAddress((void**)&q1,    d_q1);
    cudaGetSymbolAddress((void**)&att1,  d_att1);
    cudaGetSymbolAddress((void**)&bn1,   d_bn1);
    cudaGetSymbolAddress((void**)&kpad2, d_kpad2);
    cudaGetSymbolAddress((void**)&vpad2, d_vpad2);
    cudaGetSymbolAddress((void**)&q2,    d_q2);
    cudaGetSymbolAddress((void**)&att2,  d_att2);
    cudaGetSymbolAddress((void**)&emb,   d_emb);
    cudaGetSymbolAddress((void**)&prep0, d_prep0);
    cudaGetSymbolAddress((void**)&bnpart, d_bnpart);

    // 1) setup: all embeddings + stage-0 prep
    setup_kernel<<<1, 128>>>(p[3], p[4], p[5], p[11], p[12], p[13],
                             p[19], p[20], p[21], p[0], p[1], p[2], emb, prep0);

    // 2) stage-0 fused attention + stats   3) BN apply + subsample
    att0_kernel<<<NBLK, 256>>>(x, prep0, att0, bnpart);
    bn_apply_fused<64><<<NBLK, 256>>>(att0, bnpart, NBLK, p[6], p[7], bn0,
                                      8, 3000, 4, 1500, 2 * 4 * 1500 * 64,
                                      1.f / 48000.f);

    // 4) stage-1 projection as GEMM (profiled slot)
    {
        dim3 g1(188, 6);
        gemm_proj1<<<g1, 128>>>(bn0, p[8], p[9], p[10], q1, kpad1, vpad1,
                                18048 * 128);
        // 5) stage-1 attention + stats   6) BN apply + subsample
        att_stats_kernel<2, 5, 128><<<NBLK, 256>>>(q1, kpad1, vpad1, emb + 40,
            att1, 6, 1504, 4, 1500, 2 * 4 * 1500, 18048 * 128, bnpart);
        bn_apply_fused<128><<<NBLK, 256>>>(att1, bnpart, NBLK, p[14], p[15], bn1,
                                           4, 1500, 2, 750, 2 * 2 * 750 * 128,
                                           1.f / 12000.f);
    }

    // 7) stage-2 projection as mini-GEMM  8) attention + stats  9) BN+avgpool
    {
        dim3 g2(94, 2);
        proj2_gemm<<<g2, 128>>>(bn1, p[16], p[17], p[18], q2, kpad2, vpad2);
        att_stats_kernel<2, 5, 16><<<NBLK, 256>>>(q2, kpad2, vpad2, emb + 80,
            att2, 2, 754, 1, 750, 2 * 1 * 750, 48256, bnpart);
        bn_avg_final<<<52, 256>>>(att2, bnpart, NBLK, p[22], p[23], (float*)d_out);
    }
}

// round 14
// speedup vs baseline: 3.5164x; 1.0842x over previous
#include <cuda_runtime.h>
#include <math.h>

#define MMIX 4
#define NBLK 296   // fixed grid for att kernels (2 waves on 148 SMs)

// ---------------- scratch (static __device__, no allocation) ----------------
__device__ float d_att0[768000];          // stage-0 raw att, subsampled compact [12000][64]
__device__ float d_kpad1[2310144];
__device__ float d_vpad1[9240576];
__device__ float d_q1[1536000];
__device__ float d_att1[384000];          // stage-1 raw att, subsampled compact [3000][128]
__device__ float d_kpad2[48256];
__device__ float d_vpad2[193024];
__device__ float d_q2[24000];
__device__ float d_att2[24000];

__device__ float d_emb[120];              // 3 stages x (M*K <= 40)
__device__ float d_prep0[321];            // [0]=qw.kw ; [1..320]=E[5][64]
__device__ float d_bnpart[NBLK * 256];    // per-block partials (2*Co <= 256)
__device__ float d_bnss[384];             // stage0: sc[64],sh[64] @0 ; stage1: sc[128]@128, sh[128]@256

// ---------------- device helper: one mixture-softmax tap ---------------------
__device__ void emb_tap(const float* __restrict__ ea, const float* __restrict__ eb,
                        const float* __restrict__ em, float* __restrict__ emb_out,
                        int Co, int kh, int kw_, int t)
{
    int K = kh * kw_;
    int i = t / kw_, j = t % kw_;
    float logits[MMIX];
    #pragma unroll
    for (int m = 0; m < MMIX; m++) {
        float la = 0.f, lb = 0.f;
        for (int c = 0; c < Co; c++) {
            float e = em[m * Co + c];
            la += e * ea[c * kh + i];
            lb += e * eb[c * kw_ + j];
        }
        logits[m] = la + lb;
    }
    float mx = logits[0];
    #pragma unroll
    for (int m = 1; m < MMIX; m++) mx = fmaxf(mx, logits[m]);
    float sum = 0.f;
    #pragma unroll
    for (int m = 0; m < MMIX; m++) { logits[m] = expf(logits[m] - mx); sum += logits[m]; }
    float inv = 1.f / sum;
    #pragma unroll
    for (int m = 0; m < MMIX; m++) emb_out[m * K + t] = logits[m] * inv;
}

// ---------------- setup: all 3 stage embeddings + stage-0 prep (1 launch) ----
__global__ void setup_kernel(
    const float* __restrict__ ea0, const float* __restrict__ eb0, const float* __restrict__ em0,
    const float* __restrict__ ea1, const float* __restrict__ eb1, const float* __restrict__ em1,
    const float* __restrict__ ea2, const float* __restrict__ eb2, const float* __restrict__ em2,
    const float* __restrict__ qw0, const float* __restrict__ kw0, const float* __restrict__ vw0,
    float* __restrict__ emb, float* __restrict__ prep)
{
    int t = threadIdx.x;  // 128 threads
    if (t < 5)                 emb_tap(ea0, eb0, em0, emb + 0,  64,  1, 5, t);
    else if (t >= 32 && t < 42) emb_tap(ea1, eb1, em1, emb + 40, 128, 2, 5, t - 32);
    else if (t >= 64 && t < 74) emb_tap(ea2, eb2, em2, emb + 80, 16,  2, 5, t - 64);
    __syncthreads();   // emb0 visible (same block, global mem)

    __shared__ float sh[64];
    if (t < 64) sh[t] = qw0[t] * kw0[t];
    __syncthreads();
    if (t == 0) {
        float s = 0.f;
        for (int i = 0; i < 64; i++) s += sh[i];
        prep[0] = s;
    }
    if (t < 64) {
        #pragma unroll
        for (int j = 0; j < 5; j++) {
            float e = 0.f;
            #pragma unroll
            for (int m = 0; m < MMIX; m++) e += emb[m * 5 + j] * vw0[m * 64 + t];
            prep[1 + j * 64 + t] = e;
        }
    }
}

// ---------------- stage-0 fused attention + BN stats (Cin=1 collapse) --------
// Stats over ALL pixels; writes RAW values only at subsampled positions (compact).
__global__ void att0_kernel(const float* __restrict__ x, const float* __restrict__ prep,
                            float* __restrict__ out, float* __restrict__ bnpart)
{
    __shared__ float sE[5 * 64];
    __shared__ float red_s[8][64], red_q[8][64];
    for (int e = threadIdx.x; e < 320; e += blockDim.x) sE[e] = prep[1 + e];
    __syncthreads();

    int wid = threadIdx.x >> 5, lane = threadIdx.x & 31;
    int warp0 = blockIdx.x * 8 + wid, wstride = gridDim.x * 8;
    float c0 = prep[0];

    float s0 = 0.f, s1 = 0.f, q0 = 0.f, q1 = 0.f;
    for (int gw = warp0; gw < 48000; gw += wstride) {
        int wo = gw % 3000;
        int row = gw / 3000;          // b*8+h
        int rowbase = row * 3000;

        float xs[5];
        #pragma unroll
        for (int j = 0; j < 5; j++) {
            int w = wo - 2 + j;
            xs[j] = (w >= 0 && w < 3000) ? x[rowbase + w] : 0.f;
        }
        float cx = c0 * xs[2];
        float sc[5]; float mx = -1e30f;
        #pragma unroll
        for (int j = 0; j < 5; j++) { sc[j] = cx * xs[j]; mx = fmaxf(mx, sc[j]); }
        float sum = 0.f;
        #pragma unroll
        for (int j = 0; j < 5; j++) { sc[j] = expf(sc[j] - mx); sum += sc[j]; }
        float inv = 1.f / sum;
        float wj[5];
        #pragma unroll
        for (int j = 0; j < 5; j++) wj[j] = sc[j] * inv * xs[j];

        float a0 = 0.f, a1 = 0.f;
        #pragma unroll
        for (int j = 0; j < 5; j++) {
            a0 = fmaf(wj[j], sE[j * 64 + lane], a0);
            a1 = fmaf(wj[j], sE[j * 64 + 32 + lane], a1);
        }
        s0 += a0; q0 = fmaf(a0, a0, q0);
        s1 += a1; q1 = fmaf(a1, a1, q1);
        // subsample write: h even (row&1==0 since row=b*8+h) and wo even
        if (((row & 1) | (wo & 1)) == 0) {
            int b = row >> 3;
            int hs = (row >> 1) & 3;
            int cp = (b * 4 + hs) * 1500 + (wo >> 1);    // [12000] compact pixels
            out[cp * 64 + lane] = a0;
            out[cp * 64 + 32 + lane] = a1;
        }
    }
    red_s[wid][lane] = s0; red_s[wid][32 + lane] = s1;
    red_q[wid][lane] = q0; red_q[wid][32 + lane] = q1;
    __syncthreads();
    for (int c = threadIdx.x; c < 64; c += blockDim.x) {
        float s = 0.f, q = 0.f;
        #pragma unroll
        for (int w = 0; w < 8; w++) { s += red_s[w][c]; q += red_q[w][c]; }
        bnpart[blockIdx.x * 128 + c]      = s;
        bnpart[blockIdx.x * 128 + 64 + c] = q;
    }
}

// ---------------- BN finalize: partials -> per-channel scale/shift -----------
__global__ void bn_finalize_k(const float* __restrict__ bnpart,
    const float* __restrict__ gamma, const float* __restrict__ beta,
    float* __restrict__ ss, int Co, float invN)
{
    int c = threadIdx.x;
    if (c >= Co) return;
    float s = 0.f, q = 0.f;
    for (int g = 0; g < NBLK; g++) {
        s += bnpart[g * 2 * Co + c];
        q += bnpart[g * 2 * Co + Co + c];
    }
    float mean = s * invN;
    float var  = q * invN - mean * mean;
    float sc = gamma[c] * rsqrtf(var + 1e-5f);
    ss[c]      = sc;
    ss[Co + c] = beta[c] - mean * sc;
}

// ---------------- stage-1 projection as smem-tiled GEMM, BN fused on load ----
// grid (47, 6): each block loads its 32KB weight slab ONCE, then loops 4 M-tiles.
// x-load applies BN scale/shift + ReLU to the raw subsampled att0 values.
__global__ void __launch_bounds__(128) gemm_proj1(const float* __restrict__ att0c,
    const float* __restrict__ bnss,
    const float* __restrict__ qw, const float* __restrict__ kw_,
    const float* __restrict__ vw,
    float* __restrict__ qout, float* __restrict__ kpad, float* __restrict__ vpad,
    int vstride)
{
    __shared__ float ws[64][128];    // [ci][co]   32KB
    __shared__ float xs[64][64];     // [pix][ci]  16KB
    __shared__ float sxc[64], sxh[64];

    int s = blockIdx.y;
    const float* wsrc = (s == 0) ? qw : (s == 1) ? kw_ : vw + (s - 2) * 64 * 128;
    int tid = threadIdx.x;           // 128

    // weights: 2048 float4, direct copy (16 per thread)
    {
        const float4* src = (const float4*)wsrc;
        float4* dst = (float4*)&ws[0][0];
        #pragma unroll
        for (int i = 0; i < 16; i++) dst[tid + 128 * i] = src[tid + 128 * i];
    }
    if (tid < 64) { sxc[tid] = bnss[tid]; sxh[tid] = bnss[64 + tid]; }
    __syncthreads();

    int ty = tid >> 4, tx = tid & 15;   // ty 0..7, tx 0..15
    int mr = ty * 8, nc = tx * 8;

    for (int t = 0; t < 4; t++) {
        int m0 = (blockIdx.x * 4 + t) * 64;

        // x tile: 1024 float4 (8 per thread); BN + ReLU applied at load
        #pragma unroll
        for (int i = 0; i < 8; i++) {
            int idx = tid + 128 * i;
            int pix = m0 + (idx >> 4);
            int c4 = (idx & 15) * 4;
            float4 v = (pix < 12000) ? ((const float4*)att0c)[pix * 16 + (idx & 15)]
                                     : make_float4(0.f, 0.f, 0.f, 0.f);
            v.x = fmaxf(fmaf(v.x, sxc[c4],     sxh[c4]),     0.f);
            v.y = fmaxf(fmaf(v.y, sxc[c4 + 1], sxh[c4 + 1]), 0.f);
            v.z = fmaxf(fmaf(v.z, sxc[c4 + 2], sxh[c4 + 2]), 0.f);
            v.w = fmaxf(fmaf(v.w, sxc[c4 + 3], sxh[c4 + 3]), 0.f);
            *(float4*)&xs[idx >> 4][c4] = v;
        }
        __syncthreads();

        float acc[8][8];
        #pragma unroll
        for (int i = 0; i < 8; i++)
            #pragma unroll
            for (int j = 0; j < 8; j++) acc[i][j] = 0.f;

        #pragma unroll 4
        for (int k = 0; k < 64; k += 2) {
            float2 ax[8];
            #pragma unroll
            for (int i = 0; i < 8; i++) ax[i] = *(const float2*)&xs[mr + i][k];
            float4 b00 = *(const float4*)&ws[k][nc];
            float4 b01 = *(const float4*)&ws[k][nc + 4];
            float4 b10 = *(const float4*)&ws[k + 1][nc];
            float4 b11 = *(const float4*)&ws[k + 1][nc + 4];
            float bv0[8] = {b00.x, b00.y, b00.z, b00.w, b01.x, b01.y, b01.z, b01.w};
            float bv1[8] = {b10.x, b10.y, b10.z, b10.w, b11.x, b11.y, b11.z, b11.w};
            #pragma unroll
            for (int i = 0; i < 8; i++) {
                #pragma unroll
                for (int j = 0; j < 8; j++) {
                    acc[i][j] = fmaf(ax[i].x, bv0[j], acc[i][j]);
                    acc[i][j] = fmaf(ax[i].y, bv1[j], acc[i][j]);
                }
            }
        }
        __syncthreads();   // all reads of xs done before next tile overwrites

        #pragma unroll
        for (int i = 0; i < 8; i++) {
            int pix = m0 + mr + i;
            if (pix >= 12000) continue;
            float* dst; int base;
            if (s == 0) {
                dst = qout; base = pix * 128 + nc;
            } else {
                int b = pix / 6000, rem = pix % 6000;
                int h = rem / 1500, w = rem % 1500;
                int padpix = (b * 6 + h + 1) * 1504 + (w + 2);   // pt=1, pl=2
                base = padpix * 128 + nc;
                dst = (s == 1) ? kpad : vpad + (s - 2) * vstride;
            }
            *(float4*)&dst[base]     = make_float4(acc[i][0], acc[i][1], acc[i][2], acc[i][3]);
            *(float4*)&dst[base + 4] = make_float4(acc[i][4], acc[i][5], acc[i][6], acc[i][7]);
        }
    }
}

// ---------------- stage-2 projection as mini-GEMM, BN fused on load ----------
// C[3000x96] = X[3000x128] * W[128x96]; cols 0..15 q, 16..31 k, 32..95 v[m]
__global__ void proj2_gemm(const float* __restrict__ att1c,
    const float* __restrict__ bnss,   // sc at [0..127], sh at [128..255] (caller offsets)
    const float* __restrict__ qw, const float* __restrict__ kw_,
    const float* __restrict__ vw,
    float* __restrict__ qout, float* __restrict__ kpad, float* __restrict__ vpad)
{
    __shared__ float xs[32][128];   // 16KB
    __shared__ float ws[128][48];   // 24KB
    __shared__ float sxc[128], sxh[128];
    int tid = threadIdx.x;
    int m0 = blockIdx.x * 32;
    int c0 = blockIdx.y * 48;

    if (tid < 128) { sxc[tid] = bnss[tid]; sxh[tid] = bnss[128 + tid]; }

    // weights: 1536 float4 (12 per thread); float4 never straddles a stream
    {
        float4* dst = (float4*)&ws[0][0];
        #pragma unroll
        for (int i = 0; i < 12; i++) {
            int idx = tid + 128 * i;
            int ci = idx / 12;
            int c = c0 + (idx % 12) * 4;
            const float* src;
            if (c < 16)      src = qw  + ci * 16 + c;
            else if (c < 32) src = kw_ + ci * 16 + (c - 16);
            else             src = vw + ((c - 32) >> 4) * 2048 + ci * 16 + ((c - 32) & 15);
            dst[idx] = *(const float4*)src;
        }
    }
    __syncthreads();  // sxc ready before x-load uses it
    // x tile: 1024 float4 (8 per thread), BN + ReLU on load
    {
        float4* dst = (float4*)&xs[0][0];
        #pragma unroll
        for (int i = 0; i < 8; i++) {
            int idx = tid + 128 * i;
            int pix = m0 + (idx >> 5);
            int c4 = (idx & 31) * 4;
            float4 v = (pix < 3000) ? ((const float4*)att1c)[pix * 32 + (idx & 31)]
                                    : make_float4(0.f, 0.f, 0.f, 0.f);
            v.x = fmaxf(fmaf(v.x, sxc[c4],     sxh[c4]),     0.f);
            v.y = fmaxf(fmaf(v.y, sxc[c4 + 1], sxh[c4 + 1]), 0.f);
            v.z = fmaxf(fmaf(v.z, sxc[c4 + 2], sxh[c4 + 2]), 0.f);
            v.w = fmaxf(fmaf(v.w, sxc[c4 + 3], sxh[c4 + 3]), 0.f);
            dst[idx] = v;
        }
    }
    __syncthreads();

    int ty = tid >> 4, tx = tid & 15;   // ty 0..7 -> 4 pixels, tx 0..15 -> 3 cols
    int mr = ty * 4, nc = tx * 3;

    float acc[4][3];
    #pragma unroll
    for (int i = 0; i < 4; i++)
        #pragma unroll
        for (int j = 0; j < 3; j++) acc[i][j] = 0.f;

    #pragma unroll 4
    for (int k = 0; k < 128; k += 2) {
        float2 ax[4];
        #pragma unroll
        for (int i = 0; i < 4; i++) ax[i] = *(const float2*)&xs[mr + i][k];
        float bv0[3], bv1[3];
        #pragma unroll
        for (int j = 0; j < 3; j++) { bv0[j] = ws[k][nc + j]; bv1[j] = ws[k + 1][nc + j]; }
        #pragma unroll
        for (int i = 0; i < 4; i++)
            #pragma unroll
            for (int j = 0; j < 3; j++) {
                acc[i][j] = fmaf(ax[i].x, bv0[j], acc[i][j]);
                acc[i][j] = fmaf(ax[i].y, bv1[j], acc[i][j]);
            }
    }

    #pragma unroll
    for (int i = 0; i < 4; i++) {
        int pix = m0 + mr + i;
        if (pix >= 3000) continue;
        int b_ = pix / 1500, rem = pix % 1500;
        int h = rem / 750, w = rem % 750;
        int padbase = ((b_ * 2 + h) * 754 + w + 2) * 16;     // pt=0, pl=2
        #pragma unroll
        for (int j = 0; j < 3; j++) {
            int c = c0 + nc + j;
            float v = acc[i][j];
            if (c < 16) {
                if (h == 0) qout[(b_ * 750 + w) * 16 + c] = v;   // Hout=1
            } else if (c < 32) {
                kpad[padbase + (c - 16)] = v;
            } else {
                vpad[((c - 32) >> 4) * 48256 + padbase + ((c - 32) & 15)] = v;
            }
        }
    }
}

// ---------------- attention + fused BN stats: warp per pixel, grid-stride ----
// SUB: write RAW values only at subsampled positions (compact layout).
template<int KH, int KW, int CO, bool SUB>
__global__ void att_stats_kernel(const float* __restrict__ q,
    const float* __restrict__ kpad, const float* __restrict__ vpad,
    const float* __restrict__ emb, float* __restrict__ out,
    int Hp, int Wp, int Hout, int Wout, int total, int vstride,
    float* __restrict__ bnpart)
{
    constexpr int K = KH * KW;
    constexpr int CPL = (CO + 31) / 32;
    constexpr int CW = (CO > 32) ? CO : 32;
    __shared__ float s_emb[MMIX * K];
    __shared__ float red_s[8][CW], red_q[8][CW];
    for (int e = threadIdx.x; e < MMIX * K; e += blockDim.x) s_emb[e] = emb[e];
    __syncthreads();

    int wid = threadIdx.x >> 5, lane = threadIdx.x & 31;
    int warp0 = blockIdx.x * 8 + wid, wstride = gridDim.x * 8;

    float sacc[CPL], qacc[CPL];
    #pragma unroll
    for (int i = 0; i < CPL; i++) { sacc[i] = 0.f; qacc[i] = 0.f; }

    for (int gw = warp0; gw < total; gw += wstride) {
        int wo = gw % Wout; int t = gw / Wout;
        int ho = t % Hout;  int b = t / Hout;

        int kvbase[K];
        #pragma unroll
        for (int k = 0; k < K; k++) {
            int i = k / KW, j = k % KW;
            kvbase[k] = ((b * Hp + ho + i) * Wp + (wo + j)) * CO;
        }

        float partial[K];
        #pragma unroll
        for (int k = 0; k < K; k++) partial[k] = 0.f;
        int qbase = gw * CO;
        #pragma unroll
        for (int i = 0; i < CPL; i++) {
            int co = lane + 32 * i;
            if (co < CO) {
                float qv = q[qbase + co];
                #pragma unroll
                for (int k = 0; k < K; k++)
                    partial[k] = fmaf(qv, kpad[kvbase[k] + co], partial[k]);
            }
        }
        #pragma unroll
        for (int k = 0; k < K; k++) {
            #pragma unroll
            for (int off = 16; off > 0; off >>= 1)
                partial[k] += __shfl_xor_sync(0xffffffffu, partial[k], off);
        }

        float mx = partial[0];
        #pragma unroll
        for (int k = 1; k < K; k++) mx = fmaxf(mx, partial[k]);
        float sum = 0.f;
        float aw[K];
        #pragma unroll
        for (int k = 0; k < K; k++) { aw[k] = expf(partial[k] - mx); sum += aw[k]; }
        float inv = 1.f / sum;

        float wkm[MMIX][K];
        #pragma unroll
        for (int m = 0; m < MMIX; m++)
            #pragma unroll
            for (int k = 0; k < K; k++)
                wkm[m][k] = aw[k] * inv * s_emb[m * K + k];

        bool wr = true;
        int obase = qbase;
        if (SUB) {
            wr = (((ho & 1) | (wo & 1)) == 0);
            obase = ((b * (Hout >> 1) + (ho >> 1)) * (Wout >> 1) + (wo >> 1)) * CO;
        }

        #pragma unroll
        for (int i = 0; i < CPL; i++) {
            int co = lane + 32 * i;
            if (co < CO) {
                float a0 = 0.f, a1 = 0.f, a2 = 0.f, a3 = 0.f;
                #pragma unroll
                for (int k = 0; k < K; k++) {
                    int off = kvbase[k] + co;
                    a0 = fmaf(wkm[0][k], vpad[off], a0);
                    a1 = fmaf(wkm[1][k], vpad[vstride + off], a1);
                    a2 = fmaf(wkm[2][k], vpad[2 * vstride + off], a2);
                    a3 = fmaf(wkm[3][k], vpad[3 * vstride + off], a3);
                }
                float acc = (a0 + a1) + (a2 + a3);
                if (wr) out[obase + co] = acc;
                sacc[i] += acc;
                qacc[i] = fmaf(acc, acc, qacc[i]);
            }
        }
    }

    #pragma unroll
    for (int i = 0; i < CPL; i++) {
        int c = lane + 32 * i;
        if (c < CO) { red_s[wid][c] = sacc[i]; red_q[wid][c] = qacc[i]; }
    }
    __syncthreads();
    for (int c = threadIdx.x; c < CO; c += blockDim.x) {
        float s = 0.f, q2 = 0.f;
        #pragma unroll
        for (int w = 0; w < 8; w++) { s += red_s[w][c]; q2 += red_q[w][c]; }
        bnpart[blockIdx.x * 2 * CO + c]      = s;
        bnpart[blockIdx.x * 2 * CO + CO + c] = q2;
    }
}

// ---------------- stage-2 BN finalize + apply + AvgPool(1,56) -> d_out -------
__global__ void bn_avg_final(const float* __restrict__ in,
    const float* __restrict__ bnpart, int nparts,
    const float* __restrict__ gamma, const float* __restrict__ beta,
    float* __restrict__ out)
{
    __shared__ float ssc[16], ssh[16];
    for (int c = threadIdx.x; c < 16; c += blockDim.x) {
        float s = 0.f, q = 0.f;
        for (int g = 0; g < nparts; g++) {
            s += bnpart[g * 32 + c];
            q += bnpart[g * 32 + 16 + c];
        }
        float mean = s * (1.f / 1500.f);
        float var  = q * (1.f / 1500.f) - mean * mean;
        float sc = gamma[c] * rsqrtf(var + 1e-5f);
        ssc[c] = sc;
        ssh[c] = beta[c] - mean * sc;
    }
    __syncthreads();
    int gw = (blockIdx.x * blockDim.x + threadIdx.x) >> 5;
    int lane = threadIdx.x & 31;
    if (gw >= 416) return;
    int nw = gw % 13; int t = gw / 13;
    int c = t % 16;   int b = t / 16;
    float sc = ssc[c], sh_ = ssh[c];
    float s = 0.f;
    int base = b * 750 + nw * 56;
    #pragma unroll
    for (int j0 = 0; j0 < 56; j0 += 32) {
        int j = j0 + lane;
        if (j < 56) {
            float v = in[(base + j) * 16 + c];
            float y = fmaf(v, sc, sh_);
            s += (y > 0.f ? y : 0.f);
        }
    }
    #pragma unroll
    for (int off = 16; off > 0; off >>= 1)
        s += __shfl_xor_sync(0xffffffffu, s, off);
    if (lane == 0) out[(b * 16 + c) * 13 + nw] = s * (1.f / 56.f);
}

// ---------------- launch (9 nodes) -------------------------------------------
extern "C" void kernel_launch(void* const* d_in, const int* in_sizes, int n_in,
                              void* d_out, int out_size)
{
    const float* x = (const float*)d_in[0];
    const float* p[24];
    for (int i = 0; i < 24; i++) p[i] = (const float*)d_in[1 + i];

    float *att0, *kpad1, *vpad1, *q1, *att1;
    float *kpad2, *vpad2, *q2, *att2;
    float *emb, *prep0, *bnpart, *bnss;
    cudaGetSymbolAddress((void**)&att0,  d_att0);
    cudaGetSymbolAddress((void**)&kpad1, d_kpad1);
    cudaGetSymbolAddress((void**)&vpad1, d_vpad1);
    cudaGetSymbolAddress((void**)&q1,    d_q1);
    cudaGetSymbolAddress((void**)&att1,  d_att1);
    cudaGetSymbolAddress((void**)&kpad2, d_kpad2);
    cudaGetSymbolAddress((void**)&vpad2, d_vpad2);
    cudaGetSymbolAddress((void**)&q2,    d_q2);
    cudaGetSymbolAddress((void**)&att2,  d_att2);
    cudaGetSymbolAddress((void**)&emb,   d_emb);
    cudaGetSymbolAddress((void**)&prep0, d_prep0);
    cudaGetSymbolAddress((void**)&bnpart, d_bnpart);
    cudaGetSymbolAddress((void**)&bnss,   d_bnss);

    // 1) setup: all embeddings + stage-0 prep
    setup_kernel<<<1, 128>>>(p[3], p[4], p[5], p[11], p[12], p[13],
                             p[19], p[20], p[21], p[0], p[1], p[2], emb, prep0);

    // 2) stage-0 fused attention + stats (compact raw subsampled write)
    att0_kernel<<<NBLK, 256>>>(x, prep0, att0, bnpart);
    // 3) finalize stage-0 BN -> scale/shift
    bn_finalize_k<<<1, 64>>>(bnpart, p[6], p[7], bnss, 64, 1.f / 48000.f);

    // 4) stage-1 projection GEMM, BN+ReLU fused on x-load (profiled slot)
    {
        dim3 g1(47, 6);
        gemm_proj1<<<g1, 128>>>(att0, bnss, p[8], p[9], p[10], q1, kpad1, vpad1,
                                18048 * 128);
        // 5) stage-1 attention + stats (compact raw subsampled write)
        att_stats_kernel<2, 5, 128, true><<<NBLK, 256>>>(q1, kpad1, vpad1, emb + 40,
            att1, 6, 1504, 4, 1500, 2 * 4 * 1500, 18048 * 128, bnpart);
        // 6) finalize stage-1 BN
        bn_finalize_k<<<1, 128>>>(bnpart, p[14], p[15], bnss + 128, 128, 1.f / 12000.f);
    }

    // 7) stage-2 projection mini-GEMM, BN+ReLU fused on x-load
    {
        dim3 g2(94, 2);
        proj2_gemm<<<g2, 128>>>(att1, bnss + 128, p[16], p[17], p[18], q2, kpad2, vpad2);
        // 8) stage-2 attention + stats (full write)
        att_stats_kernel<2, 5, 16, false><<<NBLK, 256>>>(q2, kpad2, vpad2, emb + 80,
            att2, 2, 754, 1, 750, 2 * 1 * 750, 48256, bnpart);
        // 9) BN + avgpool -> out
        bn_avg_final<<<52, 256>>>(att2, bnpart, NBLK, p[22], p[23], (float*)d_out);
    }
}

// round 15
// speedup vs baseline: 3.7333x; 1.0617x over previous
#include <cuda_runtime.h>
#include <math.h>

#define MMIX 4
#define NBLK 296   // fixed grid for att kernels (2 waves on 148 SMs)

// ---------------- scratch (static __device__, no allocation) ----------------
__device__ float d_att0[768000];          // stage-0 raw att, subsampled compact [12000][64]
__device__ float d_kpad1[2310144];
__device__ float d_vpad1[9240576];
__device__ float d_q1[1536000];
__device__ float d_att1[384000];          // stage-1 raw att, subsampled compact [3000][128]
__device__ float d_kpad2[48256];
__device__ float d_vpad2[193024];
__device__ float d_q2[24000];
__device__ float d_att2[24000];

__device__ float d_emb[120];              // 3 stages x (M*K <= 40)
__device__ float d_prep0[321];            // [0]=qw.kw ; [1..320]=E[5][64]
__device__ float d_bnpart[NBLK * 256];    // per-block partials (2*Co <= 256)
__device__ float d_bnss[384];             // stage0: sc[64],sh[64] @0 ; stage1: sc[128]@128, sh[128]@256

// ---------------- device helper: one mixture-softmax tap ---------------------
__device__ void emb_tap(const float* __restrict__ ea, const float* __restrict__ eb,
                        const float* __restrict__ em, float* __restrict__ emb_out,
                        int Co, int kh, int kw_, int t)
{
    int K = kh * kw_;
    int i = t / kw_, j = t % kw_;
    float logits[MMIX];
    #pragma unroll
    for (int m = 0; m < MMIX; m++) {
        float la = 0.f, lb = 0.f;
        for (int c = 0; c < Co; c++) {
            float e = em[m * Co + c];
            la += e * ea[c * kh + i];
            lb += e * eb[c * kw_ + j];
        }
        logits[m] = la + lb;
    }
    float mx = logits[0];
    #pragma unroll
    for (int m = 1; m < MMIX; m++) mx = fmaxf(mx, logits[m]);
    float sum = 0.f;
    #pragma unroll
    for (int m = 0; m < MMIX; m++) { logits[m] = expf(logits[m] - mx); sum += logits[m]; }
    float inv = 1.f / sum;
    #pragma unroll
    for (int m = 0; m < MMIX; m++) emb_out[m * K + t] = logits[m] * inv;
}

// ---------------- setup: all 3 stage embeddings + stage-0 prep (1 launch) ----
__global__ void setup_kernel(
    const float* __restrict__ ea0, const float* __restrict__ eb0, const float* __restrict__ em0,
    const float* __restrict__ ea1, const float* __restrict__ eb1, const float* __restrict__ em1,
    const float* __restrict__ ea2, const float* __restrict__ eb2, const float* __restrict__ em2,
    const float* __restrict__ qw0, const float* __restrict__ kw0, const float* __restrict__ vw0,
    float* __restrict__ emb, float* __restrict__ prep)
{
    int t = threadIdx.x;  // 128 threads
    if (t < 5)                 emb_tap(ea0, eb0, em0, emb + 0,  64,  1, 5, t);
    else if (t >= 32 && t < 42) emb_tap(ea1, eb1, em1, emb + 40, 128, 2, 5, t - 32);
    else if (t >= 64 && t < 74) emb_tap(ea2, eb2, em2, emb + 80, 16,  2, 5, t - 64);
    __syncthreads();   // emb0 visible (same block, global mem)

    __shared__ float sh[64];
    if (t < 64) sh[t] = qw0[t] * kw0[t];
    __syncthreads();
    if (t == 0) {
        float s = 0.f;
        for (int i = 0; i < 64; i++) s += sh[i];
        prep[0] = s;
    }
    if (t < 64) {
        #pragma unroll
        for (int j = 0; j < 5; j++) {
            float e = 0.f;
            #pragma unroll
            for (int m = 0; m < MMIX; m++) e += emb[m * 5 + j] * vw0[m * 64 + t];
            prep[1 + j * 64 + t] = e;
        }
    }
}

// ---------------- stage-0 fused attention + BN stats (Cin=1 collapse) --------
// Stats over ALL pixels; writes RAW values only at subsampled positions (compact).
__global__ void att0_kernel(const float* __restrict__ x, const float* __restrict__ prep,
                            float* __restrict__ out, float* __restrict__ bnpart)
{
    __shared__ float sE[5 * 64];
    __shared__ float red_s[8][64], red_q[8][64];
    for (int e = threadIdx.x; e < 320; e += blockDim.x) sE[e] = prep[1 + e];
    __syncthreads();

    int wid = threadIdx.x >> 5, lane = threadIdx.x & 31;
    int warp0 = blockIdx.x * 8 + wid, wstride = gridDim.x * 8;
    float c0 = prep[0];

    float s0 = 0.f, s1 = 0.f, q0 = 0.f, q1 = 0.f;
    for (int gw = warp0; gw < 48000; gw += wstride) {
        int wo = gw % 3000;
        int row = gw / 3000;          // b*8+h
        int rowbase = row * 3000;

        float xs[5];
        #pragma unroll
        for (int j = 0; j < 5; j++) {
            int w = wo - 2 + j;
            xs[j] = (w >= 0 && w < 3000) ? x[rowbase + w] : 0.f;
        }
        float cx = c0 * xs[2];
        float sc[5]; float mx = -1e30f;
        #pragma unroll
        for (int j = 0; j < 5; j++) { sc[j] = cx * xs[j]; mx = fmaxf(mx, sc[j]); }
        float sum = 0.f;
        #pragma unroll
        for (int j = 0; j < 5; j++) { sc[j] = expf(sc[j] - mx); sum += sc[j]; }
        float inv = 1.f / sum;
        float wj[5];
        #pragma unroll
        for (int j = 0; j < 5; j++) wj[j] = sc[j] * inv * xs[j];

        float a0 = 0.f, a1 = 0.f;
        #pragma unroll
        for (int j = 0; j < 5; j++) {
            a0 = fmaf(wj[j], sE[j * 64 + lane], a0);
            a1 = fmaf(wj[j], sE[j * 64 + 32 + lane], a1);
        }
        s0 += a0; q0 = fmaf(a0, a0, q0);
        s1 += a1; q1 = fmaf(a1, a1, q1);
        // subsample write: h even (row&1==0 since row=b*8+h) and wo even
        if (((row & 1) | (wo & 1)) == 0) {
            int b = row >> 3;
            int hs = (row >> 1) & 3;
            int cp = (b * 4 + hs) * 1500 + (wo >> 1);    // [12000] compact pixels
            out[cp * 64 + lane] = a0;
            out[cp * 64 + 32 + lane] = a1;
        }
    }
    red_s[wid][lane] = s0; red_s[wid][32 + lane] = s1;
    red_q[wid][lane] = q0; red_q[wid][32 + lane] = q1;
    __syncthreads();
    for (int c = threadIdx.x; c < 64; c += blockDim.x) {
        float s = 0.f, q = 0.f;
        #pragma unroll
        for (int w = 0; w < 8; w++) { s += red_s[w][c]; q += red_q[w][c]; }
        bnpart[blockIdx.x * 128 + c]      = s;
        bnpart[blockIdx.x * 128 + 64 + c] = q;
    }
}

// ---------------- BN finalize: partials -> per-channel scale/shift -----------
__global__ void bn_finalize_k(const float* __restrict__ bnpart,
    const float* __restrict__ gamma, const float* __restrict__ beta,
    float* __restrict__ ss, int Co, float invN)
{
    int c = threadIdx.x;
    if (c >= Co) return;
    float s = 0.f, q = 0.f;
    for (int g = 0; g < NBLK; g++) {
        s += bnpart[g * 2 * Co + c];
        q += bnpart[g * 2 * Co + Co + c];
    }
    float mean = s * invN;
    float var  = q * invN - mean * mean;
    float sc = gamma[c] * rsqrtf(var + 1e-5f);
    ss[c]      = sc;
    ss[Co + c] = beta[c] - mean * sc;
}

// ---------------- stage-1 projection as smem-tiled GEMM, BN fused on load ----
// grid (94, 6): Mtile=128, Ntile=128, 256 threads, 8x8 register tile.
// Same warps-in-flight as the best R10 config (4512) with 2x prologue amortization.
__global__ void __launch_bounds__(256, 2) gemm_proj1(const float* __restrict__ att0c,
    const float* __restrict__ bnss,
    const float* __restrict__ qw, const float* __restrict__ kw_,
    const float* __restrict__ vw,
    float* __restrict__ qout, float* __restrict__ kpad, float* __restrict__ vpad,
    int vstride)
{
    __shared__ float ws[64][128];     // [ci][co]   32KB
    __shared__ float xs[128][64];     // [pix][ci]  32KB
    __shared__ float sxc[64], sxh[64];

    int s = blockIdx.y;
    const float* wsrc = (s == 0) ? qw : (s == 1) ? kw_ : vw + (s - 2) * 64 * 128;
    int tid = threadIdx.x;            // 256
    int m0 = blockIdx.x * 128;

    // weights: 2048 float4 (8 per thread)
    {
        const float4* src = (const float4*)wsrc;
        float4* dst = (float4*)&ws[0][0];
        #pragma unroll
        for (int i = 0; i < 8; i++) dst[tid + 256 * i] = src[tid + 256 * i];
    }
    if (tid < 64) { sxc[tid] = bnss[tid]; sxh[tid] = bnss[64 + tid]; }
    // x tile: 2048 float4 (8 per thread); BN + ReLU applied at load.
    // sxc/sxh written by warps 0-1 and only read by the same block after
    // __syncthreads below.
    __syncthreads();
    {
        #pragma unroll
        for (int i = 0; i < 8; i++) {
            int idx = tid + 256 * i;
            int pix = m0 + (idx >> 4);
            int c4 = (idx & 15) * 4;
            float4 v = (pix < 12000) ? ((const float4*)att0c)[pix * 16 + (idx & 15)]
                                     : make_float4(0.f, 0.f, 0.f, 0.f);
            v.x = fmaxf(fmaf(v.x, sxc[c4],     sxh[c4]),     0.f);
            v.y = fmaxf(fmaf(v.y, sxc[c4 + 1], sxh[c4 + 1]), 0.f);
            v.z = fmaxf(fmaf(v.z, sxc[c4 + 2], sxh[c4 + 2]), 0.f);
            v.w = fmaxf(fmaf(v.w, sxc[c4 + 3], sxh[c4 + 3]), 0.f);
            *(float4*)&xs[idx >> 4][c4] = v;
        }
    }
    __syncthreads();

    int ty = tid >> 4, tx = tid & 15;   // ty 0..15, tx 0..15
    int mr = ty * 8, nc = tx * 8;

    float acc[8][8];
    #pragma unroll
    for (int i = 0; i < 8; i++)
        #pragma unroll
        for (int j = 0; j < 8; j++) acc[i][j] = 0.f;

    #pragma unroll 4
    for (int k = 0; k < 64; k += 2) {
        float2 ax[8];
        #pragma unroll
        for (int i = 0; i < 8; i++) ax[i] = *(const float2*)&xs[mr + i][k];
        float4 b00 = *(const float4*)&ws[k][nc];
        float4 b01 = *(const float4*)&ws[k][nc + 4];
        float4 b10 = *(const float4*)&ws[k + 1][nc];
        float4 b11 = *(const float4*)&ws[k + 1][nc + 4];
        float bv0[8] = {b00.x, b00.y, b00.z, b00.w, b01.x, b01.y, b01.z, b01.w};
        float bv1[8] = {b10.x, b10.y, b10.z, b10.w, b11.x, b11.y, b11.z, b11.w};
        #pragma unroll
        for (int i = 0; i < 8; i++) {
            #pragma unroll
            for (int j = 0; j < 8; j++) {
                acc[i][j] = fmaf(ax[i].x, bv0[j], acc[i][j]);
                acc[i][j] = fmaf(ax[i].y, bv1[j], acc[i][j]);
            }
        }
    }

    #pragma unroll
    for (int i = 0; i < 8; i++) {
        int pix = m0 + mr + i;
        if (pix >= 12000) continue;
        float* dst; int base;
        if (s == 0) {
            dst = qout; base = pix * 128 + nc;
        } else {
            int b = pix / 6000, rem = pix % 6000;
            int h = rem / 1500, w = rem % 1500;
            int padpix = (b * 6 + h + 1) * 1504 + (w + 2);   // pt=1, pl=2
            base = padpix * 128 + nc;
            dst = (s == 1) ? kpad : vpad + (s - 2) * vstride;
        }
        *(float4*)&dst[base]     = make_float4(acc[i][0], acc[i][1], acc[i][2], acc[i][3]);
        *(float4*)&dst[base + 4] = make_float4(acc[i][4], acc[i][5], acc[i][6], acc[i][7]);
    }
}

// ---------------- stage-2 projection as mini-GEMM, BN fused on load ----------
// C[3000x96] = X[3000x128] * W[128x96]; cols 0..15 q, 16..31 k, 32..95 v[m]
__global__ void proj2_gemm(const float* __restrict__ att1c,
    const float* __restrict__ bnss,   // sc at [0..127], sh at [128..255] (caller offsets)
    const float* __restrict__ qw, const float* __restrict__ kw_,
    const float* __restrict__ vw,
    float* __restrict__ qout, float* __restrict__ kpad, float* __restrict__ vpad)
{
    __shared__ float xs[32][128];   // 16KB
    __shared__ float ws[128][48];   // 24KB
    __shared__ float sxc[128], sxh[128];
    int tid = threadIdx.x;
    int m0 = blockIdx.x * 32;
    int c0 = blockIdx.y * 48;

    if (tid < 128) { sxc[tid] = bnss[tid]; sxh[tid] = bnss[128 + tid]; }

    // weights: 1536 float4 (12 per thread); float4 never straddles a stream
    {
        float4* dst = (float4*)&ws[0][0];
        #pragma unroll
        for (int i = 0; i < 12; i++) {
            int idx = tid + 128 * i;
            int ci = idx / 12;
            int c = c0 + (idx % 12) * 4;
            const float* src;
            if (c < 16)      src = qw  + ci * 16 + c;
            else if (c < 32) src = kw_ + ci * 16 + (c - 16);
            else             src = vw + ((c - 32) >> 4) * 2048 + ci * 16 + ((c - 32) & 15);
            dst[idx] = *(const float4*)src;
        }
    }
    __syncthreads();  // sxc ready before x-load uses it
    // x tile: 1024 float4 (8 per thread), BN + ReLU on load
    {
        float4* dst = (float4*)&xs[0][0];
        #pragma unroll
        for (int i = 0; i < 8; i++) {
            int idx = tid + 128 * i;
            int pix = m0 + (idx >> 5);
            int c4 = (idx & 31) * 4;
            float4 v = (pix < 3000) ? ((const float4*)att1c)[pix * 32 + (idx & 31)]
                                    : make_float4(0.f, 0.f, 0.f, 0.f);
            v.x = fmaxf(fmaf(v.x, sxc[c4],     sxh[c4]),     0.f);
            v.y = fmaxf(fmaf(v.y, sxc[c4 + 1], sxh[c4 + 1]), 0.f);
            v.z = fmaxf(fmaf(v.z, sxc[c4 + 2], sxh[c4 + 2]), 0.f);
            v.w = fmaxf(fmaf(v.w, sxc[c4 + 3], sxh[c4 + 3]), 0.f);
            dst[idx] = v;
        }
    }
    __syncthreads();

    int ty = tid >> 4, tx = tid & 15;   // ty 0..7 -> 4 pixels, tx 0..15 -> 3 cols
    int mr = ty * 4, nc = tx * 3;

    float acc[4][3];
    #pragma unroll
    for (int i = 0; i < 4; i++)
        #pragma unroll
        for (int j = 0; j < 3; j++) acc[i][j] = 0.f;

    #pragma unroll 4
    for (int k = 0; k < 128; k += 2) {
        float2 ax[4];
        #pragma unroll
        for (int i = 0; i < 4; i++) ax[i] = *(const float2*)&xs[mr + i][k];
        float bv0[3], bv1[3];
        #pragma unroll
        for (int j = 0; j < 3; j++) { bv0[j] = ws[k][nc + j]; bv1[j] = ws[k + 1][nc + j]; }
        #pragma unroll
        for (int i = 0; i < 4; i++)
            #pragma unroll
            for (int j = 0; j < 3; j++) {
                acc[i][j] = fmaf(ax[i].x, bv0[j], acc[i][j]);
                acc[i][j] = fmaf(ax[i].y, bv1[j], acc[i][j]);
            }
    }

    #pragma unroll
    for (int i = 0; i < 4; i++) {
        int pix = m0 + mr + i;
        if (pix >= 3000) continue;
        int b_ = pix / 1500, rem = pix % 1500;
        int h = rem / 750, w = rem % 750;
        int padbase = ((b_ * 2 + h) * 754 + w + 2) * 16;     // pt=0, pl=2
        #pragma unroll
        for (int j = 0; j < 3; j++) {
            int c = c0 + nc + j;
            float v = acc[i][j];
            if (c < 16) {
                if (h == 0) qout[(b_ * 750 + w) * 16 + c] = v;   // Hout=1
            } else if (c < 32) {
                kpad[padbase + (c - 16)] = v;
            } else {
                vpad[((c - 32) >> 4) * 48256 + padbase + ((c - 32) & 15)] = v;
            }
        }
    }
}

// ---------------- attention + fused BN stats: warp per pixel, grid-stride ----
// SUB: write RAW values only at subsampled positions (compact layout).
template<int KH, int KW, int CO, bool SUB>
__global__ void att_stats_kernel(const float* __restrict__ q,
    const float* __restrict__ kpad, const float* __restrict__ vpad,
    const float* __restrict__ emb, float* __restrict__ out,
    int Hp, int Wp, int Hout, int Wout, int total, int vstride,
    float* __restrict__ bnpart)
{
    constexpr int K = KH * KW;
    constexpr int CPL = (CO + 31) / 32;
    constexpr int CW = (CO > 32) ? CO : 32;
    __shared__ float s_emb[MMIX * K];
    __shared__ float red_s[8][CW], red_q[8][CW];
    for (int e = threadIdx.x; e < MMIX * K; e += blockDim.x) s_emb[e] = emb[e];
    __syncthreads();

    int wid = threadIdx.x >> 5, lane = threadIdx.x & 31;
    int warp0 = blockIdx.x * 8 + wid, wstride = gridDim.x * 8;

    float sacc[CPL], qacc[CPL];
    #pragma unroll
    for (int i = 0; i < CPL; i++) { sacc[i] = 0.f; qacc[i] = 0.f; }

    for (int gw = warp0; gw < total; gw += wstride) {
        int wo = gw % Wout; int t = gw / Wout;
        int ho = t % Hout;  int b = t / Hout;

        int kvbase[K];
        #pragma unroll
        for (int k = 0; k < K; k++) {
            int i = k / KW, j = k % KW;
            kvbase[k] = ((b * Hp + ho + i) * Wp + (wo + j)) * CO;
        }

        float partial[K];
        #pragma unroll
        for (int k = 0; k < K; k++) partial[k] = 0.f;
        int qbase = gw * CO;
        #pragma unroll
        for (int i = 0; i < CPL; i++) {
            int co = lane + 32 * i;
            if (co < CO) {
                float qv = q[qbase + co];
                #pragma unroll
                for (int k = 0; k < K; k++)
                    partial[k] = fmaf(qv, kpad[kvbase[k] + co], partial[k]);
            }
        }
        #pragma unroll
        for (int k = 0; k < K; k++) {
            #pragma unroll
            for (int off = 16; off > 0; off >>= 1)
                partial[k] += __shfl_xor_sync(0xffffffffu, partial[k], off);
        }

        float mx = partial[0];
        #pragma unroll
        for (int k = 1; k < K; k++) mx = fmaxf(mx, partial[k]);
        float sum = 0.f;
        float aw[K];
        #pragma unroll
        for (int k = 0; k < K; k++) { aw[k] = expf(partial[k] - mx); sum += aw[k]; }
        float inv = 1.f / sum;

        float wkm[MMIX][K];
        #pragma unroll
        for (int m = 0; m < MMIX; m++)
            #pragma unroll
            for (int k = 0; k < K; k++)
                wkm[m][k] = aw[k] * inv * s_emb[m * K + k];

        bool wr = true;
        int obase = qbase;
        if (SUB) {
            wr = (((ho & 1) | (wo & 1)) == 0);
            obase = ((b * (Hout >> 1) + (ho >> 1)) * (Wout >> 1) + (wo >> 1)) * CO;
        }

        #pragma unroll
        for (int i = 0; i < CPL; i++) {
            int co = lane + 32 * i;
            if (co < CO) {
                float a0 = 0.f, a1 = 0.f, a2 = 0.f, a3 = 0.f;
                #pragma unroll
                for (int k = 0; k < K; k++) {
                    int off = kvbase[k] + co;
                    a0 = fmaf(wkm[0][k], vpad[off], a0);
                    a1 = fmaf(wkm[1][k], vpad[vstride + off], a1);
                    a2 = fmaf(wkm[2][k], vpad[2 * vstride + off], a2);
                    a3 = fmaf(wkm[3][k], vpad[3 * vstride + off], a3);
                }
                float acc = (a0 + a1) + (a2 + a3);
                if (wr) out[obase + co] = acc;
                sacc[i] += acc;
                qacc[i] = fmaf(acc, acc, qacc[i]);
            }
        }
    }

    #pragma unroll
    for (int i = 0; i < CPL; i++) {
        int c = lane + 32 * i;
        if (c < CO) { red_s[wid][c] = sacc[i]; red_q[wid][c] = qacc[i]; }
    }
    __syncthreads();
    for (int c = threadIdx.x; c < CO; c += blockDim.x) {
        float s = 0.f, q2 = 0.f;
        #pragma unroll
        for (int w = 0; w < 8; w++) { s += red_s[w][c]; q2 += red_q[w][c]; }
        bnpart[blockIdx.x * 2 * CO + c]      = s;
        bnpart[blockIdx.x * 2 * CO + CO + c] = q2;
    }
}

// ---------------- stage-2 BN finalize + apply + AvgPool(1,56) -> d_out -------
__global__ void bn_avg_final(const float* __restrict__ in,
    const float* __restrict__ bnpart, int nparts,
    const float* __restrict__ gamma, const float* __restrict__ beta,
    float* __restrict__ out)
{
    __shared__ float ssc[16], ssh[16];
    for (int c = threadIdx.x; c < 16; c += blockDim.x) {
        float s = 0.f, q = 0.f;
        for (int g = 0; g < nparts; g++) {
            s += bnpart[g * 32 + c];
            q += bnpart[g * 32 + 16 + c];
        }
        float mean = s * (1.f / 1500.f);
        float var  = q * (1.f / 1500.f) - mean * mean;
        float sc = gamma[c] * rsqrtf(var + 1e-5f);
        ssc[c] = sc;
        ssh[c] = beta[c] - mean * sc;
    }
    __syncthreads();
    int gw = (blockIdx.x * blockDim.x + threadIdx.x) >> 5;
    int lane = threadIdx.x & 31;
    if (gw >= 416) return;
    int nw = gw % 13; int t = gw / 13;
    int c = t % 16;   int b = t / 16;
    float sc = ssc[c], sh_ = ssh[c];
    float s = 0.f;
    int base = b * 750 + nw * 56;
    #pragma unroll
    for (int j0 = 0; j0 < 56; j0 += 32) {
        int j = j0 + lane;
        if (j < 56) {
            float v = in[(base + j) * 16 + c];
            float y = fmaf(v, sc, sh_);
            s += (y > 0.f ? y : 0.f);
        }
    }
    #pragma unroll
    for (int off = 16; off > 0; off >>= 1)
        s += __shfl_xor_sync(0xffffffffu, s, off);
    if (lane == 0) out[(b * 16 + c) * 13 + nw] = s * (1.f / 56.f);
}

// ---------------- launch (9 nodes) -------------------------------------------
extern "C" void kernel_launch(void* const* d_in, const int* in_sizes, int n_in,
                              void* d_out, int out_size)
{
    const float* x = (const float*)d_in[0];
    const float* p[24];
    for (int i = 0; i < 24; i++) p[i] = (const float*)d_in[1 + i];

    float *att0, *kpad1, *vpad1, *q1, *att1;
    float *kpad2, *vpad2, *q2, *att2;
    float *emb, *prep0, *bnpart, *bnss;
    cudaGetSymbolAddress((void**)&att0,  d_att0);
    cudaGetSymbolAddress((void**)&kpad1, d_kpad1);
    cudaGetSymbolAddress((void**)&vpad1, d_vpad1);
    cudaGetSymbolAddress((void**)&q1,    d_q1);
    cudaGetSymbolAddress((void**)&att1,  d_att1);
    cudaGetSymbolAddress((void**)&kpad2, d_kpad2);
    cudaGetSymbolAddress((void**)&vpad2, d_vpad2);
    cudaGetSymbolAddress((void**)&q2,    d_q2);
    cudaGetSymbolAddress((void**)&att2,  d_att2);
    cudaGetSymbolAddress((void**)&emb,   d_emb);
    cudaGetSymbolAddress((void**)&prep0, d_prep0);
    cudaGetSymbolAddress((void**)&bnpart, d_bnpart);
    cudaGetSymbolAddress((void**)&bnss,   d_bnss);

    // 1) setup: all embeddings + stage-0 prep
    setup_kernel<<<1, 128>>>(p[3], p[4], p[5], p[11], p[12], p[13],
                             p[19], p[20], p[21], p[0], p[1], p[2], emb, prep0);

    // 2) stage-0 fused attention + stats (compact raw subsampled write)
    att0_kernel<<<NBLK, 256>>>(x, prep0, att0, bnpart);
    // 3) finalize stage-0 BN -> scale/shift
    bn_finalize_k<<<1, 64>>>(bnpart, p[6], p[7], bnss, 64, 1.f / 48000.f);

    // 4) stage-1 projection GEMM, BN+ReLU fused on x-load (profiled slot)
    {
        dim3 g1(94, 6);
        gemm_proj1<<<g1, 256>>>(att0, bnss, p[8], p[9], p[10], q1, kpad1, vpad1,
                                18048 * 128);
        // 5) stage-1 attention + stats (compact raw subsampled write)
        att_stats_kernel<2, 5, 128, true><<<NBLK, 256>>>(q1, kpad1, vpad1, emb + 40,
            att1, 6, 1504, 4, 1500, 2 * 4 * 1500, 18048 * 128, bnpart);
        // 6) finalize stage-1 BN
        bn_finalize_k<<<1, 128>>>(bnpart, p[14], p[15], bnss + 128, 128, 1.f / 12000.f);
    }

    // 7) stage-2 projection mini-GEMM, BN+ReLU fused on x-load
    {
        dim3 g2(94, 2);
        proj2_gemm<<<g2, 128>>>(att1, bnss + 128, p[16], p[17], p[18], q2, kpad2, vpad2);
        // 8) stage-2 attention + stats (full write)
        att_stats_kernel<2, 5, 16, false><<<NBLK, 256>>>(q2, kpad2, vpad2, emb + 80,
            att2, 2, 754, 1, 750, 2 * 1 * 750, 48256, bnpart);
        // 9) BN + avgpool -> out
        bn_avg_final<<<52, 256>>>(att2, bnpart, NBLK, p[22], p[23], (float*)d_out);
    }
}